// round 3
// baseline (speedup 1.0000x reference)
#include <cuda_runtime.h>

#define BN_EPS 1e-5f

// ---------------- scratch (device globals; no allocation allowed) -------------
__device__ float g_yqk[2 * 512 * 4096];        // qk conv output  (B, 2C, N)
__device__ float g_yv [2 * 256 * 4096];        // v  conv output  (B, C, N)
__device__ float g_pp [2 * 256 * 4096];        // depthwise+BN    (B, C, N)
__device__ float g_o  [2 * 256 * 4096];        // attention output (B, C, N)

// ---------------- conv1x1 + BN:  Y[b][m][n] = BN( sum_c A[m][c] X[b][c][n] ) --
// in_mode:  0 -> X = xp               1 -> X = g_o + g_pp (fused add)
// out_mode: 0 -> g_yqk   1 -> g_yv    2 -> dout
__global__ __launch_bounds__(256) void conv1x1_bn(
    const float* __restrict__ A, const float* __restrict__ xp,
    float* __restrict__ dout,
    const float* __restrict__ gg, const float* __restrict__ bb,
    const float* __restrict__ mm, const float* __restrict__ vv,
    int M, int in_mode, int out_mode)
{
    const int K = 256, N = 4096;
    const int b  = blockIdx.z;
    const int m0 = blockIdx.y * 128, n0 = blockIdx.x * 128;

    const float* X  = (in_mode == 0 ? xp : g_o) + b * K * N;
    const float* X2 = (in_mode == 1 ? g_pp + b * K * N : nullptr);
    float* Y = (out_mode == 0 ? g_yqk : (out_mode == 1 ? g_yv : dout)) + b * M * N;

    __shared__ float As[16][132];
    __shared__ float Bs[16][128];

    const int t  = threadIdx.x;
    const int ty = t >> 4, tx = t & 15;
    const int ra = t >> 2, ca = (t & 3) * 4;     // A load mapping
    const int rb = t >> 5, cb = (t & 31) * 4;    // B load mapping

    float acc[8][8];
#pragma unroll
    for (int i = 0; i < 8; i++)
#pragma unroll
        for (int j = 0; j < 8; j++) acc[i][j] = 0.f;

    for (int k0 = 0; k0 < K; k0 += 16) {
#pragma unroll
        for (int rr = 0; rr < 2; rr++) {
            int row = ra + rr * 64;
            float4 av = *reinterpret_cast<const float4*>(&A[(m0 + row) * K + k0 + ca]);
            As[ca + 0][row] = av.x; As[ca + 1][row] = av.y;
            As[ca + 2][row] = av.z; As[ca + 3][row] = av.w;
        }
#pragma unroll
        for (int rr = 0; rr < 2; rr++) {
            int row = rb + rr * 8;
            float4 bv = *reinterpret_cast<const float4*>(&X[(k0 + row) * N + n0 + cb]);
            if (X2) {
                float4 b2 = *reinterpret_cast<const float4*>(&X2[(k0 + row) * N + n0 + cb]);
                bv.x += b2.x; bv.y += b2.y; bv.z += b2.z; bv.w += b2.w;
            }
            *reinterpret_cast<float4*>(&Bs[row][cb]) = bv;
        }
        __syncthreads();
#pragma unroll
        for (int k = 0; k < 16; k++) {
            float a[8], bf[8];
            float4 a0 = *reinterpret_cast<const float4*>(&As[k][ty * 8]);
            float4 a1 = *reinterpret_cast<const float4*>(&As[k][ty * 8 + 4]);
            a[0]=a0.x; a[1]=a0.y; a[2]=a0.z; a[3]=a0.w;
            a[4]=a1.x; a[5]=a1.y; a[6]=a1.z; a[7]=a1.w;
            float4 u0 = *reinterpret_cast<const float4*>(&Bs[k][tx * 8]);
            float4 u1 = *reinterpret_cast<const float4*>(&Bs[k][tx * 8 + 4]);
            bf[0]=u0.x; bf[1]=u0.y; bf[2]=u0.z; bf[3]=u0.w;
            bf[4]=u1.x; bf[5]=u1.y; bf[6]=u1.z; bf[7]=u1.w;
#pragma unroll
            for (int i = 0; i < 8; i++)
#pragma unroll
                for (int j = 0; j < 8; j++)
                    acc[i][j] = fmaf(a[i], bf[j], acc[i][j]);
        }
        __syncthreads();
    }

#pragma unroll
    for (int i = 0; i < 8; i++) {
        int row = m0 + ty * 8 + i;
        float s  = gg[row] * rsqrtf(vv[row] + BN_EPS);
        float bi = bb[row] - mm[row] * s;
        float4 o0 = make_float4(acc[i][0]*s+bi, acc[i][1]*s+bi, acc[i][2]*s+bi, acc[i][3]*s+bi);
        float4 o1 = make_float4(acc[i][4]*s+bi, acc[i][5]*s+bi, acc[i][6]*s+bi, acc[i][7]*s+bi);
        *reinterpret_cast<float4*>(&Y[row * N + n0 + tx * 8])     = o0;
        *reinterpret_cast<float4*>(&Y[row * N + n0 + tx * 8 + 4]) = o1;
    }
}

// ---------------- depthwise 5x5 (pad 2) + BN on g_yv -> g_pp ------------------
__global__ __launch_bounds__(256) void dw5_bn(
    const float* __restrict__ w_pe,
    const float* __restrict__ gg, const float* __restrict__ bb,
    const float* __restrict__ mm, const float* __restrict__ vv)
{
    const int bc = blockIdx.x;                  // 0..511 = b*256 + c
    const int c  = bc & 255;
    const float* src = g_yv + bc * 4096;
    float* dst = g_pp + bc * 4096;

    __shared__ float tile[68][68];
    __shared__ float wk[25];
    const int t = threadIdx.x;

    for (int i = t; i < 68 * 68; i += 256) ((float*)tile)[i] = 0.f;
    if (t < 25) wk[t] = w_pe[c * 25 + t];
    __syncthreads();
    for (int i = t; i < 4096; i += 256) tile[(i >> 6) + 2][(i & 63) + 2] = src[i];
    __syncthreads();

    float s  = gg[c] * rsqrtf(vv[c] + BN_EPS);
    float bi = bb[c] - mm[c] * s;

    for (int i = t; i < 4096; i += 256) {
        int y = i >> 6, x = i & 63;
        float acc = 0.f;
#pragma unroll
        for (int ky = 0; ky < 5; ky++)
#pragma unroll
            for (int kx = 0; kx < 5; kx++)
                acc = fmaf(tile[y + ky][x + kx], wk[ky * 5 + kx], acc);
        dst[i] = acc * s + bi;
    }
}

// ---------------- fused flash attention --------------------------------------
// grid: (8 q-tiles, 64 bh), 256 threads.
// Q/K layouts are channel-major: ptr[d*4096 + n]. Softmax over keys m per query n.
#define FA_SMEM ((32*128*3 + 128*128 + 16*128 + 3*128) * 4)

__global__ __launch_bounds__(256) void flash_attn()
{
    extern __shared__ float sm[];
    float* Qs = sm;
    float* Ks = Qs + 4096;
    float* Vs = Ks + 4096;
    float* Ps = Vs + 4096;
    float* red = Ps + 16384;
    float* colmax = red + 2048;
    float* colsum = colmax + 128;
    float* alpha  = colsum + 128;

    const int bh = blockIdx.y;
    const int b = bh >> 5, area = (bh >> 3) & 3, h = bh & 7;
    const float* Qp = g_yqk + b * 512 * 4096 + (h * 32) * 4096 + area * 1024;
    const float* Kp = Qp + 256 * 4096;
    const float* Vp = g_yv + b * 256 * 4096 + (h * 32) * 4096 + area * 1024;
    const int q0 = blockIdx.x * 128;

    const int t = threadIdx.x;
    const int ty = t >> 4, tx = t & 15;     // S phase: m-rows ty*8.., q-cols tx*8..
    const int oy = t >> 5, ox = t & 31;     // O phase: d-rows oy*4.., q-cols ox*4..

    // load Q tile (32 x 128), coalesced float4
#pragma unroll
    for (int i = t * 4; i < 4096; i += 1024) {
        int d = i >> 7, q = i & 127;
        *reinterpret_cast<float4*>(&Qs[d * 128 + q]) =
            *reinterpret_cast<const float4*>(&Qp[d * 4096 + q0 + q]);
    }
    if (t < 128) { colmax[t] = -1e30f; colsum[t] = 0.f; }

    float O[4][4];
#pragma unroll
    for (int i = 0; i < 4; i++)
#pragma unroll
        for (int j = 0; j < 4; j++) O[i][j] = 0.f;

    const float sc = 0.17677669529663687f;  // 32^-0.5

    for (int m0 = 0; m0 < 1024; m0 += 128) {
        __syncthreads();   // previous iteration done with Ks/Vs/Ps/red
#pragma unroll
        for (int i = t * 4; i < 4096; i += 1024) {
            int d = i >> 7, m = i & 127;
            *reinterpret_cast<float4*>(&Ks[d * 128 + m]) =
                *reinterpret_cast<const float4*>(&Kp[d * 4096 + m0 + m]);
            *reinterpret_cast<float4*>(&Vs[d * 128 + m]) =
                *reinterpret_cast<const float4*>(&Vp[d * 4096 + m0 + m]);
        }
        __syncthreads();

        // S[i][j] = sum_d K[d][m=ty*8+i] * Q[d][q=tx*8+j]
        float S[8][8];
#pragma unroll
        for (int i = 0; i < 8; i++)
#pragma unroll
            for (int j = 0; j < 8; j++) S[i][j] = 0.f;
#pragma unroll 8
        for (int d = 0; d < 32; d++) {
            float a[8], bq[8];
            *reinterpret_cast<float4*>(&a[0]) = *reinterpret_cast<float4*>(&Ks[d * 128 + ty * 8]);
            *reinterpret_cast<float4*>(&a[4]) = *reinterpret_cast<float4*>(&Ks[d * 128 + ty * 8 + 4]);
            *reinterpret_cast<float4*>(&bq[0]) = *reinterpret_cast<float4*>(&Qs[d * 128 + tx * 8]);
            *reinterpret_cast<float4*>(&bq[4]) = *reinterpret_cast<float4*>(&Qs[d * 128 + tx * 8 + 4]);
#pragma unroll
            for (int i = 0; i < 8; i++)
#pragma unroll
                for (int j = 0; j < 8; j++)
                    S[i][j] = fmaf(a[i], bq[j], S[i][j]);
        }

        // scale + local column max
        float lm[8];
#pragma unroll
        for (int j = 0; j < 8; j++) {
            lm[j] = -1e30f;
#pragma unroll
            for (int i = 0; i < 8; i++) {
                S[i][j] *= sc;
                lm[j] = fmaxf(lm[j], S[i][j]);
            }
            red[ty * 128 + tx * 8 + j] = lm[j];
        }
        __syncthreads();

        if (t < 128) {
            float mx = red[t];
#pragma unroll
            for (int r = 1; r < 16; r++) mx = fmaxf(mx, red[r * 128 + t]);
            float nm = fmaxf(colmax[t], mx);
            alpha[t] = __expf(colmax[t] - nm);
            colmax[t] = nm;
        }
        __syncthreads();

        // P = exp(S - colmax); stage to smem (float4), local sums; rescale O
#pragma unroll
        for (int j = 0; j < 8; j += 4) {
            float cm0 = colmax[tx * 8 + j + 0];
            float cm1 = colmax[tx * 8 + j + 1];
            float cm2 = colmax[tx * 8 + j + 2];
            float cm3 = colmax[tx * 8 + j + 3];
            float s0 = 0.f, s1 = 0.f, s2 = 0.f, s3 = 0.f;
#pragma unroll
            for (int i = 0; i < 8; i++) {
                float4 p;
                p.x = __expf(S[i][j + 0] - cm0);
                p.y = __expf(S[i][j + 1] - cm1);
                p.z = __expf(S[i][j + 2] - cm2);
                p.w = __expf(S[i][j + 3] - cm3);
                s0 += p.x; s1 += p.y; s2 += p.z; s3 += p.w;
                *reinterpret_cast<float4*>(&Ps[(ty * 8 + i) * 128 + tx * 8 + j]) = p;
            }
            red[ty * 128 + tx * 8 + j + 0] = s0;
            red[ty * 128 + tx * 8 + j + 1] = s1;
            red[ty * 128 + tx * 8 + j + 2] = s2;
            red[ty * 128 + tx * 8 + j + 3] = s3;
        }
#pragma unroll
        for (int j = 0; j < 4; j++) {
            float aq = alpha[ox * 4 + j];
#pragma unroll
            for (int i = 0; i < 4; i++) O[i][j] *= aq;
        }
        __syncthreads();

        if (t < 128) {
            float s = colsum[t] * alpha[t];
#pragma unroll
            for (int r = 0; r < 16; r++) s += red[r * 128 + t];
            colsum[t] = s;
        }

        // O[d][q] += sum_m V[d][m] * P[m][q]
#pragma unroll 4
        for (int k = 0; k < 128; k += 4) {
            float4 va[4], pb[4];
#pragma unroll
            for (int di = 0; di < 4; di++)
                va[di] = *reinterpret_cast<float4*>(&Vs[(oy * 4 + di) * 128 + k]);
#pragma unroll
            for (int kk = 0; kk < 4; kk++)
                pb[kk] = *reinterpret_cast<float4*>(&Ps[(k + kk) * 128 + ox * 4]);
#pragma unroll
            for (int di = 0; di < 4; di++) {
                const float* vv4 = reinterpret_cast<const float*>(&va[di]);
#pragma unroll
                for (int kk = 0; kk < 4; kk++) {
                    O[di][0] = fmaf(vv4[kk], pb[kk].x, O[di][0]);
                    O[di][1] = fmaf(vv4[kk], pb[kk].y, O[di][1]);
                    O[di][2] = fmaf(vv4[kk], pb[kk].z, O[di][2]);
                    O[di][3] = fmaf(vv4[kk], pb[kk].w, O[di][3]);
                }
            }
        }
    }
    __syncthreads();  // final colsum visible

    float inv[4];
#pragma unroll
    for (int j = 0; j < 4; j++) inv[j] = 1.f / colsum[ox * 4 + j];

    float* Op = g_o + b * 256 * 4096 + (h * 32) * 4096 + area * 1024;
#pragma unroll
    for (int i = 0; i < 4; i++) {
        int d = oy * 4 + i;
        float4 o = make_float4(O[i][0] * inv[0], O[i][1] * inv[1],
                               O[i][2] * inv[2], O[i][3] * inv[3]);
        *reinterpret_cast<float4*>(&Op[d * 4096 + q0 + ox * 4]) = o;
    }
}

// ---------------- launch ------------------------------------------------------
extern "C" void kernel_launch(void* const* d_in, const int* in_sizes, int n_in,
                              void* d_out, int out_size)
{
    // Input ordering: setup_inputs() dict order is
    //   x, w_qk, w_v, w_pe, w_proj, qk_g..qk_v, v_g..v_v, pe_g..pe_v, pr_g..pr_v
    // but tolerate reference-signature order too; dispatch on in_sizes[2]
    // (512 => qk_g follows w_qk => signature order; 65536 => w_v => dict order).
    const float *x, *w_qk, *w_v, *w_pe, *w_proj;
    const float *qk_g, *qk_b, *qk_m, *qk_v;
    const float *v_g, *v_b, *v_m, *v_v;
    const float *pe_g, *pe_b, *pe_m, *pe_v;
    const float *pr_g, *pr_b, *pr_m, *pr_v;

    x = (const float*)d_in[0];
    w_qk = (const float*)d_in[1];
    if (in_sizes[2] == 512) {
        // reference-signature order
        qk_g = (const float*)d_in[2];  qk_b = (const float*)d_in[3];
        qk_m = (const float*)d_in[4];  qk_v = (const float*)d_in[5];
        w_v  = (const float*)d_in[6];
        v_g  = (const float*)d_in[7];  v_b  = (const float*)d_in[8];
        v_m  = (const float*)d_in[9];  v_v  = (const float*)d_in[10];
        w_pe = (const float*)d_in[11];
        pe_g = (const float*)d_in[12]; pe_b = (const float*)d_in[13];
        pe_m = (const float*)d_in[14]; pe_v = (const float*)d_in[15];
        w_proj = (const float*)d_in[16];
        pr_g = (const float*)d_in[17]; pr_b = (const float*)d_in[18];
        pr_m = (const float*)d_in[19]; pr_v = (const float*)d_in[20];
    } else {
        // setup_inputs() dict order
        w_v    = (const float*)d_in[2];
        w_pe   = (const float*)d_in[3];
        w_proj = (const float*)d_in[4];
        qk_g = (const float*)d_in[5];  qk_b = (const float*)d_in[6];
        qk_m = (const float*)d_in[7];  qk_v = (const float*)d_in[8];
        v_g  = (const float*)d_in[9];  v_b  = (const float*)d_in[10];
        v_m  = (const float*)d_in[11]; v_v  = (const float*)d_in[12];
        pe_g = (const float*)d_in[13]; pe_b = (const float*)d_in[14];
        pe_m = (const float*)d_in[15]; pe_v = (const float*)d_in[16];
        pr_g = (const float*)d_in[17]; pr_b = (const float*)d_in[18];
        pr_m = (const float*)d_in[19]; pr_v = (const float*)d_in[20];
    }
    float* out = (float*)d_out;

    cudaFuncSetAttribute(flash_attn, cudaFuncAttributeMaxDynamicSharedMemorySize, FA_SMEM);

    // 1. qk = conv1x1(x, w_qk) + BN        -> g_yqk  (B, 512, 4096)
    conv1x1_bn<<<dim3(32, 4, 2), 256>>>(w_qk, x, nullptr, qk_g, qk_b, qk_m, qk_v,
                                        512, 0, 0);
    // 2. v = conv1x1(x, w_v) + BN          -> g_yv   (B, 256, 4096)
    conv1x1_bn<<<dim3(32, 2, 2), 256>>>(w_v, x, nullptr, v_g, v_b, v_m, v_v,
                                        256, 0, 1);
    // 3. pp = dw5x5(v) + BN                -> g_pp
    dw5_bn<<<512, 256>>>(w_pe, pe_g, pe_b, pe_m, pe_v);
    // 4. fused attention                   -> g_o
    flash_attn<<<dim3(8, 64), 256, FA_SMEM>>>();
    // 5. out = conv1x1(O + pp, w_proj) + BN
    conv1x1_bn<<<dim3(32, 2, 2), 256>>>(w_proj, nullptr, out, pr_g, pr_b, pr_m, pr_v,
                                        256, 1, 2);
}

// round 8
// speedup vs baseline: 1.0764x; 1.0764x over previous
#include <cuda_runtime.h>
#include <cuda_bf16.h>

#define BN_EPS 1e-5f

// ---------------- scratch (device globals; no allocation allowed) -------------
__device__ float g_yqk[2 * 512 * 4096];        // qk conv output  (B, 2C, N)
__device__ float g_yv [2 * 256 * 4096];        // v  conv output  (B, C, N)
__device__ float g_pp [2 * 256 * 4096];        // depthwise+BN    (B, C, N)
__device__ float g_o  [2 * 256 * 4096];        // attention output (B, C, N)

// ---------------- conv1x1 + BN (identical to the R3 passing version) ----------
__global__ __launch_bounds__(256) void conv1x1_bn(
    const float* __restrict__ A, const float* __restrict__ xp,
    float* __restrict__ dout,
    const float* __restrict__ gg, const float* __restrict__ bb,
    const float* __restrict__ mm, const float* __restrict__ vv,
    int M, int in_mode, int out_mode)
{
    const int K = 256, N = 4096;
    const int b  = blockIdx.z;
    const int m0 = blockIdx.y * 128, n0 = blockIdx.x * 128;

    const float* X  = (in_mode == 0 ? xp : g_o) + b * K * N;
    const float* X2 = (in_mode == 1 ? g_pp + b * K * N : nullptr);
    float* Y = (out_mode == 0 ? g_yqk : (out_mode == 1 ? g_yv : dout)) + b * M * N;

    __shared__ float As[16][132];
    __shared__ float Bs[16][128];

    const int t  = threadIdx.x;
    const int ty = t >> 4, tx = t & 15;
    const int ra = t >> 2, ca = (t & 3) * 4;
    const int rb = t >> 5, cb = (t & 31) * 4;

    float acc[8][8];
#pragma unroll
    for (int i = 0; i < 8; i++)
#pragma unroll
        for (int j = 0; j < 8; j++) acc[i][j] = 0.f;

    for (int k0 = 0; k0 < K; k0 += 16) {
#pragma unroll
        for (int rr = 0; rr < 2; rr++) {
            int row = ra + rr * 64;
            float4 av = *reinterpret_cast<const float4*>(&A[(m0 + row) * K + k0 + ca]);
            As[ca + 0][row] = av.x; As[ca + 1][row] = av.y;
            As[ca + 2][row] = av.z; As[ca + 3][row] = av.w;
        }
#pragma unroll
        for (int rr = 0; rr < 2; rr++) {
            int row = rb + rr * 8;
            float4 bv = *reinterpret_cast<const float4*>(&X[(k0 + row) * N + n0 + cb]);
            if (X2) {
                float4 b2 = *reinterpret_cast<const float4*>(&X2[(k0 + row) * N + n0 + cb]);
                bv.x += b2.x; bv.y += b2.y; bv.z += b2.z; bv.w += b2.w;
            }
            *reinterpret_cast<float4*>(&Bs[row][cb]) = bv;
        }
        __syncthreads();
#pragma unroll
        for (int k = 0; k < 16; k++) {
            float a[8], bf[8];
            float4 a0 = *reinterpret_cast<const float4*>(&As[k][ty * 8]);
            float4 a1 = *reinterpret_cast<const float4*>(&As[k][ty * 8 + 4]);
            a[0]=a0.x; a[1]=a0.y; a[2]=a0.z; a[3]=a0.w;
            a[4]=a1.x; a[5]=a1.y; a[6]=a1.z; a[7]=a1.w;
            float4 u0 = *reinterpret_cast<const float4*>(&Bs[k][tx * 8]);
            float4 u1 = *reinterpret_cast<const float4*>(&Bs[k][tx * 8 + 4]);
            bf[0]=u0.x; bf[1]=u0.y; bf[2]=u0.z; bf[3]=u0.w;
            bf[4]=u1.x; bf[5]=u1.y; bf[6]=u1.z; bf[7]=u1.w;
#pragma unroll
            for (int i = 0; i < 8; i++)
#pragma unroll
                for (int j = 0; j < 8; j++)
                    acc[i][j] = fmaf(a[i], bf[j], acc[i][j]);
        }
        __syncthreads();
    }

#pragma unroll
    for (int i = 0; i < 8; i++) {
        int row = m0 + ty * 8 + i;
        float s  = gg[row] * rsqrtf(vv[row] + BN_EPS);
        float bi = bb[row] - mm[row] * s;
        float4 o0 = make_float4(acc[i][0]*s+bi, acc[i][1]*s+bi, acc[i][2]*s+bi, acc[i][3]*s+bi);
        float4 o1 = make_float4(acc[i][4]*s+bi, acc[i][5]*s+bi, acc[i][6]*s+bi, acc[i][7]*s+bi);
        *reinterpret_cast<float4*>(&Y[row * N + n0 + tx * 8])     = o0;
        *reinterpret_cast<float4*>(&Y[row * N + n0 + tx * 8 + 4]) = o1;
    }
}

// ---------------- depthwise 5x5 (pad 2) + BN on g_yv -> g_pp ------------------
__global__ __launch_bounds__(256) void dw5_bn(
    const float* __restrict__ w_pe,
    const float* __restrict__ gg, const float* __restrict__ bb,
    const float* __restrict__ mm, const float* __restrict__ vv)
{
    const int bc = blockIdx.x;
    const int c  = bc & 255;
    const float* src = g_yv + bc * 4096;
    float* dst = g_pp + bc * 4096;

    __shared__ float tile[68][68];
    __shared__ float wk[25];
    const int t = threadIdx.x;

    for (int i = t; i < 68 * 68; i += 256) ((float*)tile)[i] = 0.f;
    if (t < 25) wk[t] = w_pe[c * 25 + t];
    __syncthreads();
    for (int i = t; i < 4096; i += 256) tile[(i >> 6) + 2][(i & 63) + 2] = src[i];
    __syncthreads();

    float s  = gg[c] * rsqrtf(vv[c] + BN_EPS);
    float bi = bb[c] - mm[c] * s;

    for (int i = t; i < 4096; i += 256) {
        int y = i >> 6, x = i & 63;
        float acc = 0.f;
#pragma unroll
        for (int ky = 0; ky < 5; ky++)
#pragma unroll
            for (int kx = 0; kx < 5; kx++)
                acc = fmaf(tile[y + ky][x + kx], wk[ky * 5 + kx], acc);
        dst[i] = acc * s + bi;
    }
}

// ================= flash attention via mma.sync (3xBF16 split) ================
__device__ __forceinline__ unsigned smem_u32(const void* p) {
    unsigned a;
    asm("{ .reg .u64 t; cvta.to.shared.u64 t, %1; cvt.u32.u64 %0, t; }" : "=r"(a) : "l"(p));
    return a;
}
__device__ __forceinline__ void ldsm_x4(unsigned& r0, unsigned& r1, unsigned& r2, unsigned& r3,
                                        unsigned addr) {
    asm volatile("ldmatrix.sync.aligned.m8n8.x4.shared.b16 {%0,%1,%2,%3}, [%4];"
                 : "=r"(r0), "=r"(r1), "=r"(r2), "=r"(r3) : "r"(addr));
}
__device__ __forceinline__ void ldsm_x2(unsigned& r0, unsigned& r1, unsigned addr) {
    asm volatile("ldmatrix.sync.aligned.m8n8.x2.shared.b16 {%0,%1}, [%2];"
                 : "=r"(r0), "=r"(r1) : "r"(addr));
}
__device__ __forceinline__ void ldsm_x2t(unsigned& r0, unsigned& r1, unsigned addr) {
    asm volatile("ldmatrix.sync.aligned.m8n8.x2.trans.shared.b16 {%0,%1}, [%2];"
                 : "=r"(r0), "=r"(r1) : "r"(addr));
}
__device__ __forceinline__ void mma16816(float& c0, float& c1, float& c2, float& c3,
                                         unsigned a0, unsigned a1, unsigned a2, unsigned a3,
                                         unsigned b0, unsigned b1) {
    asm volatile(
        "mma.sync.aligned.m16n8k16.row.col.f32.bf16.bf16.f32 "
        "{%0,%1,%2,%3}, {%4,%5,%6,%7}, {%8,%9}, {%0,%1,%2,%3};"
        : "+f"(c0), "+f"(c1), "+f"(c2), "+f"(c3)
        : "r"(a0), "r"(a1), "r"(a2), "r"(a3), "r"(b0), "r"(b1));
}
__device__ __forceinline__ unsigned short bf_hi(float x) {
    return __bfloat16_as_ushort(__float2bfloat16(x));
}
__device__ __forceinline__ unsigned short bf_lo(float x, unsigned short h) {
    __nv_bfloat16 hb = __ushort_as_bfloat16(h);
    return __bfloat16_as_ushort(__float2bfloat16(x - __bfloat162float(hb)));
}
__device__ __forceinline__ unsigned pk(unsigned short a, unsigned short b) {
    return ((unsigned)b << 16) | (unsigned)a;
}

// smem: bf16 tiles [128 rows][32 cols], row stride 80 bytes (conflict-free ldmatrix)
#define SQH 0
#define SQL 10240
#define SKH 20480
#define SKL 30720
#define SVH 40960
#define SVL 51200
#define FM_SMEM 61440

__global__ __launch_bounds__(256) void flash_mma()
{
    extern __shared__ char smbuf[];
    const unsigned sb = smem_u32(smbuf);
    const int t = threadIdx.x, lane = t & 31, w = t >> 5;

    const int bh = blockIdx.y;
    const int b = bh >> 5, area = (bh >> 3) & 3, h = bh & 7;
    const float* Qp = g_yqk + b * 512 * 4096 + (h * 32) * 4096 + area * 1024;
    const float* Kp = Qp + 256 * 4096;
    const float* Vp = g_yv + b * 256 * 4096 + (h * 32) * 4096 + area * 1024;
    const int q0 = blockIdx.x * 128;
    const float sc = 0.17677669529663687f;   // 32^-0.5, folded into Q split

    // ---- convert Q (scaled) -> Qhi/Qlo smem [q][d], stride 80B ----
    for (int i = t * 4; i < 4096; i += 1024) {
        int d = i >> 7, q = i & 127;
        float4 v = *(const float4*)&Qp[d * 4096 + q0 + q];
        float va[4] = {v.x, v.y, v.z, v.w};
#pragma unroll
        for (int jj = 0; jj < 4; jj++) {
            float x = va[jj] * sc;
            unsigned short hi = bf_hi(x), lo = bf_lo(x, hi);
            *(unsigned short*)(smbuf + SQH + (q + jj) * 80 + d * 2) = hi;
            *(unsigned short*)(smbuf + SQL + (q + jj) * 80 + d * 2) = lo;
        }
    }
    __syncthreads();

    // ---- load persistent Q A-fragments: qa[split][kstep][4] ----
    const int arow = w * 16 + (lane & 7) + ((lane >> 3) & 1) * 8;
    const unsigned aoff = (unsigned)arow * 80 + ((lane >> 4) & 1) * 16;
    unsigned qa[2][2][4];
#pragma unroll
    for (int sp = 0; sp < 2; sp++)
#pragma unroll
        for (int s = 0; s < 2; s++) {
            unsigned base = sb + (sp ? SQL : SQH) + aoff + s * 32;
            ldsm_x4(qa[sp][s][0], qa[sp][s][1], qa[sp][s][2], qa[sp][s][3], base);
        }

    float Oacc[4][4];
#pragma unroll
    for (int dn = 0; dn < 4; dn++)
#pragma unroll
        for (int c = 0; c < 4; c++) Oacc[dn][c] = 0.f;
    float mr0 = -1e30f, mr1 = -1e30f, lr0 = 0.f, lr1 = 0.f;

    const int krow = (lane & 7);                     // ntile-relative B row
    const unsigned kdo = ((lane >> 3) & 1) * 16;     // tile0/tile1 d-offset
    const int vrowbase = (lane & 7) + ((lane >> 3) & 1) * 8;

    for (int kt = 0; kt < 8; kt++) {
        const int m0 = kt * 128;
        __syncthreads();   // prior iteration's ldmatrix reads done

        // ---- convert K, V -> smem hi/lo [m][d] ----
        for (int i = t * 4; i < 4096; i += 1024) {
            int d = i >> 7, m = i & 127;
            float4 kv = *(const float4*)&Kp[d * 4096 + m0 + m];
            float4 vv = *(const float4*)&Vp[d * 4096 + m0 + m];
            float ka[4] = {kv.x, kv.y, kv.z, kv.w};
            float va[4] = {vv.x, vv.y, vv.z, vv.w};
#pragma unroll
            for (int jj = 0; jj < 4; jj++) {
                unsigned short kh = bf_hi(ka[jj]), kl = bf_lo(ka[jj], kh);
                unsigned short vh = bf_hi(va[jj]), vl = bf_lo(va[jj], vh);
                *(unsigned short*)(smbuf + SKH + (m + jj) * 80 + d * 2) = kh;
                *(unsigned short*)(smbuf + SKL + (m + jj) * 80 + d * 2) = kl;
                *(unsigned short*)(smbuf + SVH + (m + jj) * 80 + d * 2) = vh;
                *(unsigned short*)(smbuf + SVL + (m + jj) * 80 + d * 2) = vl;
            }
        }
        __syncthreads();

        // ---- MMA1: S[16 ntiles][4] = Q·K^T (3 split passes) ----
        float S[16][4];
#pragma unroll
        for (int j = 0; j < 16; j++) {
            float s0 = 0.f, s1 = 0.f, s2 = 0.f, s3 = 0.f;
            unsigned kbase = sb + SKH + (unsigned)(8 * j + krow) * 80 + kdo;
            unsigned lbase = kbase + (SKL - SKH);
            unsigned kh0, kh1, kh2, kh3, kl0, kl1, kl2, kl3;
            ldsm_x2(kh0, kh1, kbase);
            ldsm_x2(kh2, kh3, kbase + 32);
            ldsm_x2(kl0, kl1, lbase);
            ldsm_x2(kl2, kl3, lbase + 32);
            mma16816(s0, s1, s2, s3, qa[0][0][0], qa[0][0][1], qa[0][0][2], qa[0][0][3], kh0, kh1);
            mma16816(s0, s1, s2, s3, qa[0][1][0], qa[0][1][1], qa[0][1][2], qa[0][1][3], kh2, kh3);
            mma16816(s0, s1, s2, s3, qa[0][0][0], qa[0][0][1], qa[0][0][2], qa[0][0][3], kl0, kl1);
            mma16816(s0, s1, s2, s3, qa[0][1][0], qa[0][1][1], qa[0][1][2], qa[0][1][3], kl2, kl3);
            mma16816(s0, s1, s2, s3, qa[1][0][0], qa[1][0][1], qa[1][0][2], qa[1][0][3], kh0, kh1);
            mma16816(s0, s1, s2, s3, qa[1][1][0], qa[1][1][1], qa[1][1][2], qa[1][1][3], kh2, kh3);
            S[j][0] = s0; S[j][1] = s1; S[j][2] = s2; S[j][3] = s3;
        }

        // ---- online softmax over keys (rows r=lane/4 and r+8) ----
        float mx0 = -1e30f, mx1 = -1e30f;
#pragma unroll
        for (int j = 0; j < 16; j++) {
            mx0 = fmaxf(mx0, fmaxf(S[j][0], S[j][1]));
            mx1 = fmaxf(mx1, fmaxf(S[j][2], S[j][3]));
        }
        mx0 = fmaxf(mx0, __shfl_xor_sync(0xFFFFFFFFu, mx0, 1));
        mx0 = fmaxf(mx0, __shfl_xor_sync(0xFFFFFFFFu, mx0, 2));
        mx1 = fmaxf(mx1, __shfl_xor_sync(0xFFFFFFFFu, mx1, 1));
        mx1 = fmaxf(mx1, __shfl_xor_sync(0xFFFFFFFFu, mx1, 2));
        float nm0 = fmaxf(mr0, mx0), nm1 = fmaxf(mr1, mx1);
        float be0 = __expf(mr0 - nm0), be1 = __expf(mr1 - nm1);
        float lt0 = 0.f, lt1 = 0.f;
#pragma unroll
        for (int j = 0; j < 16; j++) {
            S[j][0] = __expf(S[j][0] - nm0); lt0 += S[j][0];
            S[j][1] = __expf(S[j][1] - nm0); lt0 += S[j][1];
            S[j][2] = __expf(S[j][2] - nm1); lt1 += S[j][2];
            S[j][3] = __expf(S[j][3] - nm1); lt1 += S[j][3];
        }
        lt0 += __shfl_xor_sync(0xFFFFFFFFu, lt0, 1);
        lt0 += __shfl_xor_sync(0xFFFFFFFFu, lt0, 2);
        lt1 += __shfl_xor_sync(0xFFFFFFFFu, lt1, 1);
        lt1 += __shfl_xor_sync(0xFFFFFFFFu, lt1, 2);
        lr0 = lr0 * be0 + lt0; lr1 = lr1 * be1 + lt1;
        mr0 = nm0; mr1 = nm1;
#pragma unroll
        for (int dn = 0; dn < 4; dn++) {
            Oacc[dn][0] *= be0; Oacc[dn][1] *= be0;
            Oacc[dn][2] *= be1; Oacc[dn][3] *= be1;
        }

        // ---- MMA2: O += P·V  (P from S-frags, 3 split passes) ----
#pragma unroll
        for (int tt = 0; tt < 8; tt++) {
            unsigned ah[4], al[4];
            {
                unsigned short h0 = bf_hi(S[2*tt][0]), h1 = bf_hi(S[2*tt][1]);
                unsigned short h2 = bf_hi(S[2*tt][2]), h3 = bf_hi(S[2*tt][3]);
                unsigned short h4 = bf_hi(S[2*tt+1][0]), h5 = bf_hi(S[2*tt+1][1]);
                unsigned short h6 = bf_hi(S[2*tt+1][2]), h7 = bf_hi(S[2*tt+1][3]);
                ah[0] = pk(h0, h1); ah[1] = pk(h2, h3);
                ah[2] = pk(h4, h5); ah[3] = pk(h6, h7);
                al[0] = pk(bf_lo(S[2*tt][0], h0),   bf_lo(S[2*tt][1], h1));
                al[1] = pk(bf_lo(S[2*tt][2], h2),   bf_lo(S[2*tt][3], h3));
                al[2] = pk(bf_lo(S[2*tt+1][0], h4), bf_lo(S[2*tt+1][1], h5));
                al[3] = pk(bf_lo(S[2*tt+1][2], h6), bf_lo(S[2*tt+1][3], h7));
            }
            unsigned vbase = sb + SVH + (unsigned)(16 * tt + vrowbase) * 80;
#pragma unroll
            for (int dn = 0; dn < 4; dn++) {
                unsigned vh0, vh1, vl0, vl1;
                ldsm_x2t(vh0, vh1, vbase + dn * 16);
                ldsm_x2t(vl0, vl1, vbase + (SVL - SVH) + dn * 16);
                mma16816(Oacc[dn][0], Oacc[dn][1], Oacc[dn][2], Oacc[dn][3],
                         ah[0], ah[1], ah[2], ah[3], vh0, vh1);
                mma16816(Oacc[dn][0], Oacc[dn][1], Oacc[dn][2], Oacc[dn][3],
                         ah[0], ah[1], ah[2], ah[3], vl0, vl1);
                mma16816(Oacc[dn][0], Oacc[dn][1], Oacc[dn][2], Oacc[dn][3],
                         al[0], al[1], al[2], al[3], vh0, vh1);
            }
        }
    }

    // ---- normalize + stage O [q][d] (stride 33 floats) in Q smem region ----
    __syncthreads();
    {
        float inv0 = 1.f / lr0, inv1 = 1.f / lr1;
        int r = w * 16 + (lane >> 2);
        int dc = (lane & 3) * 2;
        float* Os = (float*)(smbuf);
#pragma unroll
        for (int dn = 0; dn < 4; dn++) {
            int d = dn * 8 + dc;
            Os[r * 33 + d]       = Oacc[dn][0] * inv0;
            Os[r * 33 + d + 1]   = Oacc[dn][1] * inv0;
            Os[(r + 8) * 33 + d]     = Oacc[dn][2] * inv1;
            Os[(r + 8) * 33 + d + 1] = Oacc[dn][3] * inv1;
        }
    }
    __syncthreads();

    float* Op = g_o + b * 256 * 4096 + (h * 32) * 4096 + area * 1024;
    const float* Os = (const float*)(smbuf);
    for (int i = t * 4; i < 4096; i += 1024) {
        int d = i >> 7, q = i & 127;
        float4 o;
        o.x = Os[(q + 0) * 33 + d];
        o.y = Os[(q + 1) * 33 + d];
        o.z = Os[(q + 2) * 33 + d];
        o.w = Os[(q + 3) * 33 + d];
        *(float4*)&Op[d * 4096 + q0 + q] = o;
    }
}

// ---------------- launch ------------------------------------------------------
extern "C" void kernel_launch(void* const* d_in, const int* in_sizes, int n_in,
                              void* d_out, int out_size)
{
    const float *x, *w_qk, *w_v, *w_pe, *w_proj;
    const float *qk_g, *qk_b, *qk_m, *qk_v;
    const float *v_g, *v_b, *v_m, *v_v;
    const float *pe_g, *pe_b, *pe_m, *pe_v;
    const float *pr_g, *pr_b, *pr_m, *pr_v;

    x = (const float*)d_in[0];
    w_qk = (const float*)d_in[1];
    if (in_sizes[2] == 512) {
        qk_g = (const float*)d_in[2];  qk_b = (const float*)d_in[3];
        qk_m = (const float*)d_in[4];  qk_v = (const float*)d_in[5];
        w_v  = (const float*)d_in[6];
        v_g  = (const float*)d_in[7];  v_b  = (const float*)d_in[8];
        v_m  = (const float*)d_in[9];  v_v  = (const float*)d_in[10];
        w_pe = (const float*)d_in[11];
        pe_g = (const float*)d_in[12]; pe_b = (const float*)d_in[13];
        pe_m = (const float*)d_in[14]; pe_v = (const float*)d_in[15];
        w_proj = (const float*)d_in[16];
        pr_g = (const float*)d_in[17]; pr_b = (const float*)d_in[18];
        pr_m = (const float*)d_in[19]; pr_v = (const float*)d_in[20];
    } else {
        w_v    = (const float*)d_in[2];
        w_pe   = (const float*)d_in[3];
        w_proj = (const float*)d_in[4];
        qk_g = (const float*)d_in[5];  qk_b = (const float*)d_in[6];
        qk_m = (const float*)d_in[7];  qk_v = (const float*)d_in[8];
        v_g  = (const float*)d_in[9];  v_b  = (const float*)d_in[10];
        v_m  = (const float*)d_in[11]; v_v  = (const float*)d_in[12];
        pe_g = (const float*)d_in[13]; pe_b = (const float*)d_in[14];
        pe_m = (const float*)d_in[15]; pe_v = (const float*)d_in[16];
        pr_g = (const float*)d_in[17]; pr_b = (const float*)d_in[18];
        pr_m = (const float*)d_in[19]; pr_v = (const float*)d_in[20];
    }
    float* out = (float*)d_out;

    cudaFuncSetAttribute(flash_mma, cudaFuncAttributeMaxDynamicSharedMemorySize, FM_SMEM);

    conv1x1_bn<<<dim3(32, 4, 2), 256>>>(w_qk, x, nullptr, qk_g, qk_b, qk_m, qk_v,
                                        512, 0, 0);
    conv1x1_bn<<<dim3(32, 2, 2), 256>>>(w_v, x, nullptr, v_g, v_b, v_m, v_v,
                                        256, 0, 1);
    dw5_bn<<<512, 256>>>(w_pe, pe_g, pe_b, pe_m, pe_v);
    flash_mma<<<dim3(8, 64), 256, FM_SMEM>>>();
    conv1x1_bn<<<dim3(32, 2, 2), 256>>>(w_proj, nullptr, out, pr_g, pr_b, pr_m, pr_v,
                                        256, 1, 2);
}

// round 9
// speedup vs baseline: 1.5173x; 1.4096x over previous
#include <cuda_runtime.h>
#include <cuda_bf16.h>

#define BN_EPS 1e-5f
#define SC 0.17677669529663687f

// ---------------- scratch (device globals; no allocation allowed) -------------
__device__ float g_yv [2 * 256 * 4096];                 // v conv fp32 (for dw)
__device__ float g_pp [2 * 256 * 4096];                 // depthwise+BN
__device__ float g_o  [2 * 256 * 4096];                 // attention output
__device__ __nv_bfloat16 g_qk_hi[2 * 512 * 4096];       // qk conv bf16 hi (Q pre-scaled)
__device__ __nv_bfloat16 g_qk_lo[2 * 512 * 4096];       // qk conv bf16 lo
__device__ __nv_bfloat16 g_v_hi [2 * 256 * 4096];       // v conv bf16 hi
__device__ __nv_bfloat16 g_v_lo [2 * 256 * 4096];       // v conv bf16 lo

__device__ __forceinline__ unsigned short bf_hi(float x) {
    return __bfloat16_as_ushort(__float2bfloat16(x));
}
__device__ __forceinline__ unsigned short bf_lo(float x, unsigned short h) {
    __nv_bfloat16 hb = __ushort_as_bfloat16(h);
    return __bfloat16_as_ushort(__float2bfloat16(x - __bfloat162float(hb)));
}
__device__ __forceinline__ unsigned pk(unsigned short a, unsigned short b) {
    return ((unsigned)b << 16) | (unsigned)a;
}

// ---------------- conv1x1 + BN (+ bf16 hi/lo emission) ------------------------
// out_mode 0: qk -> bf16 hi/lo only (rows<256 scaled by SC)
// out_mode 1: v  -> fp32 g_yv + bf16 hi/lo
// out_mode 2: proj -> dout fp32 (input = g_o + g_pp)
__global__ __launch_bounds__(256) void conv1x1_bn(
    const float* __restrict__ A, const float* __restrict__ xp,
    float* __restrict__ dout,
    const float* __restrict__ gg, const float* __restrict__ bb,
    const float* __restrict__ mm, const float* __restrict__ vv,
    int M, int in_mode, int out_mode)
{
    const int K = 256, N = 4096;
    const int b  = blockIdx.z;
    const int m0 = blockIdx.y * 128, n0 = blockIdx.x * 128;

    const float* X  = (in_mode == 0 ? xp : g_o) + b * K * N;
    const float* X2 = (in_mode == 1 ? g_pp + b * K * N : nullptr);

    __shared__ float As[16][132];
    __shared__ float Bs[16][128];

    const int t  = threadIdx.x;
    const int ty = t >> 4, tx = t & 15;
    const int ra = t >> 2, ca = (t & 3) * 4;
    const int rb = t >> 5, cb = (t & 31) * 4;

    float acc[8][8];
#pragma unroll
    for (int i = 0; i < 8; i++)
#pragma unroll
        for (int j = 0; j < 8; j++) acc[i][j] = 0.f;

    for (int k0 = 0; k0 < K; k0 += 16) {
#pragma unroll
        for (int rr = 0; rr < 2; rr++) {
            int row = ra + rr * 64;
            float4 av = *reinterpret_cast<const float4*>(&A[(m0 + row) * K + k0 + ca]);
            As[ca + 0][row] = av.x; As[ca + 1][row] = av.y;
            As[ca + 2][row] = av.z; As[ca + 3][row] = av.w;
        }
#pragma unroll
        for (int rr = 0; rr < 2; rr++) {
            int row = rb + rr * 8;
            float4 bv = *reinterpret_cast<const float4*>(&X[(k0 + row) * N + n0 + cb]);
            if (X2) {
                float4 b2 = *reinterpret_cast<const float4*>(&X2[(k0 + row) * N + n0 + cb]);
                bv.x += b2.x; bv.y += b2.y; bv.z += b2.z; bv.w += b2.w;
            }
            *reinterpret_cast<float4*>(&Bs[row][cb]) = bv;
        }
        __syncthreads();
#pragma unroll
        for (int k = 0; k < 16; k++) {
            float a[8], bf[8];
            float4 a0 = *reinterpret_cast<const float4*>(&As[k][ty * 8]);
            float4 a1 = *reinterpret_cast<const float4*>(&As[k][ty * 8 + 4]);
            a[0]=a0.x; a[1]=a0.y; a[2]=a0.z; a[3]=a0.w;
            a[4]=a1.x; a[5]=a1.y; a[6]=a1.z; a[7]=a1.w;
            float4 u0 = *reinterpret_cast<const float4*>(&Bs[k][tx * 8]);
            float4 u1 = *reinterpret_cast<const float4*>(&Bs[k][tx * 8 + 4]);
            bf[0]=u0.x; bf[1]=u0.y; bf[2]=u0.z; bf[3]=u0.w;
            bf[4]=u1.x; bf[5]=u1.y; bf[6]=u1.z; bf[7]=u1.w;
#pragma unroll
            for (int i = 0; i < 8; i++)
#pragma unroll
                for (int j = 0; j < 8; j++)
                    acc[i][j] = fmaf(a[i], bf[j], acc[i][j]);
        }
        __syncthreads();
    }

#pragma unroll
    for (int i = 0; i < 8; i++) {
        int row = m0 + ty * 8 + i;
        float s  = gg[row] * rsqrtf(vv[row] + BN_EPS);
        float bi = bb[row] - mm[row] * s;
        if (out_mode == 0 && row < 256) { s *= SC; bi *= SC; }
        float o[8];
#pragma unroll
        for (int j = 0; j < 8; j++) o[j] = acc[i][j] * s + bi;

        long idx = (long)b * M * N + (long)row * N + n0 + tx * 8;
        if (out_mode == 2) {
            *reinterpret_cast<float4*>(&dout[idx])     = make_float4(o[0], o[1], o[2], o[3]);
            *reinterpret_cast<float4*>(&dout[idx + 4]) = make_float4(o[4], o[5], o[6], o[7]);
        } else {
            if (out_mode == 1) {
                *reinterpret_cast<float4*>(&g_yv[idx])     = make_float4(o[0], o[1], o[2], o[3]);
                *reinterpret_cast<float4*>(&g_yv[idx + 4]) = make_float4(o[4], o[5], o[6], o[7]);
            }
            unsigned short hi[8], lo[8];
#pragma unroll
            for (int j = 0; j < 8; j++) { hi[j] = bf_hi(o[j]); lo[j] = bf_lo(o[j], hi[j]); }
            uint4 uh, ul;
            uh.x = pk(hi[0], hi[1]); uh.y = pk(hi[2], hi[3]);
            uh.z = pk(hi[4], hi[5]); uh.w = pk(hi[6], hi[7]);
            ul.x = pk(lo[0], lo[1]); ul.y = pk(lo[2], lo[3]);
            ul.z = pk(lo[4], lo[5]); ul.w = pk(lo[6], lo[7]);
            __nv_bfloat16* H = (out_mode == 0 ? g_qk_hi : g_v_hi);
            __nv_bfloat16* L = (out_mode == 0 ? g_qk_lo : g_v_lo);
            *reinterpret_cast<uint4*>(&H[idx]) = uh;
            *reinterpret_cast<uint4*>(&L[idx]) = ul;
        }
    }
}

// ---------------- depthwise 5x5 (pad 2) + BN on g_yv -> g_pp ------------------
__global__ __launch_bounds__(256) void dw5_bn(
    const float* __restrict__ w_pe,
    const float* __restrict__ gg, const float* __restrict__ bb,
    const float* __restrict__ mm, const float* __restrict__ vv)
{
    const int bc = blockIdx.x;
    const int c  = bc & 255;
    const float* src = g_yv + bc * 4096;
    float* dst = g_pp + bc * 4096;

    __shared__ float tile[68][68];
    __shared__ float wk[25];
    const int t = threadIdx.x;

    for (int i = t; i < 68 * 68; i += 256) ((float*)tile)[i] = 0.f;
    if (t < 25) wk[t] = w_pe[c * 25 + t];
    __syncthreads();
    for (int i = t; i < 4096; i += 256) tile[(i >> 6) + 2][(i & 63) + 2] = src[i];
    __syncthreads();

    float s  = gg[c] * rsqrtf(vv[c] + BN_EPS);
    float bi = bb[c] - mm[c] * s;

    for (int i = t; i < 4096; i += 256) {
        int y = i >> 6, x = i & 63;
        float acc = 0.f;
#pragma unroll
        for (int ky = 0; ky < 5; ky++)
#pragma unroll
            for (int kx = 0; kx < 5; kx++)
                acc = fmaf(tile[y + ky][x + kx], wk[ky * 5 + kx], acc);
        dst[i] = acc * s + bi;
    }
}

// ================= flash attention: mma.sync, cp.async double buffer ==========
__device__ __forceinline__ unsigned smem_u32(const void* p) {
    unsigned a;
    asm("{ .reg .u64 t; cvta.to.shared.u64 t, %1; cvt.u32.u64 %0, t; }" : "=r"(a) : "l"(p));
    return a;
}
__device__ __forceinline__ void ldsm_x4(unsigned& r0, unsigned& r1, unsigned& r2, unsigned& r3,
                                        unsigned addr) {
    asm volatile("ldmatrix.sync.aligned.m8n8.x4.shared.b16 {%0,%1,%2,%3}, [%4];"
                 : "=r"(r0), "=r"(r1), "=r"(r2), "=r"(r3) : "r"(addr));
}
__device__ __forceinline__ void ldsm_x4t(unsigned& r0, unsigned& r1, unsigned& r2, unsigned& r3,
                                         unsigned addr) {
    asm volatile("ldmatrix.sync.aligned.m8n8.x4.trans.shared.b16 {%0,%1,%2,%3}, [%4];"
                 : "=r"(r0), "=r"(r1), "=r"(r2), "=r"(r3) : "r"(addr));
}
__device__ __forceinline__ void mma16816(float& c0, float& c1, float& c2, float& c3,
                                         unsigned a0, unsigned a1, unsigned a2, unsigned a3,
                                         unsigned b0, unsigned b1) {
    asm volatile(
        "mma.sync.aligned.m16n8k16.row.col.f32.bf16.bf16.f32 "
        "{%0,%1,%2,%3}, {%4,%5,%6,%7}, {%8,%9}, {%0,%1,%2,%3};"
        : "+f"(c0), "+f"(c1), "+f"(c2), "+f"(c3)
        : "r"(a0), "r"(a1), "r"(a2), "r"(a3), "r"(b0), "r"(b1));
}
__device__ __forceinline__ void cp_async16(unsigned dst, const void* src) {
    asm volatile("cp.async.cg.shared.global [%0], [%1], 16;" :: "r"(dst), "l"(src) : "memory");
}
__device__ __forceinline__ void cp_commit() {
    asm volatile("cp.async.commit_group;" ::: "memory");
}
__device__ __forceinline__ void cp_wait_all() {
    asm volatile("cp.async.wait_group 0;" ::: "memory");
}

// smem layout: all tiles [32 d-rows][128 cols bf16], row stride 272B (pad, conflict-free)
#define TS 272
#define QH_OFF 0
#define QL_OFF 8704
#define BUF0   17408
#define BUFSZ  34816          /* KH 0 / KL 8704 / VH 17408 / VL 26112 */
#define FM_SMEM (BUF0 + 2 * BUFSZ)   /* 87040 */

__device__ __forceinline__ void kv_copy(unsigned base, int t,
    const __nv_bfloat16* Kh, const __nv_bfloat16* Kl,
    const __nv_bfloat16* Vh, const __nv_bfloat16* Vl, int m0)
{
#pragma unroll
    for (int c = t; c < 2048; c += 256) {
        int arr = c >> 9, d = (c >> 4) & 31, mb = c & 15;
        const __nv_bfloat16* s =
            (arr == 0 ? Kh : (arr == 1 ? Kl : (arr == 2 ? Vh : Vl))) + d * 4096 + m0 + mb * 8;
        cp_async16(base + arr * 8704 + d * TS + mb * 16, s);
    }
    cp_commit();
}

__global__ __launch_bounds__(256) void flash_mma()
{
    extern __shared__ char smbuf[];
    const unsigned sb = smem_u32(smbuf);
    const int t = threadIdx.x, lane = t & 31, w = t >> 5;

    const int bh = blockIdx.y;
    const int b = bh >> 5, area = (bh >> 3) & 3, h = bh & 7;
    const int q0 = blockIdx.x * 128;

    const int qch = (b * 512 + h * 32) * 4096 + area * 1024;
    const int kch = (b * 512 + 256 + h * 32) * 4096 + area * 1024;
    const int vch = (b * 256 + h * 32) * 4096 + area * 1024;
    const __nv_bfloat16* Qh = g_qk_hi + qch + q0;
    const __nv_bfloat16* Ql = g_qk_lo + qch + q0;
    const __nv_bfloat16* Kh = g_qk_hi + kch;
    const __nv_bfloat16* Kl = g_qk_lo + kch;
    const __nv_bfloat16* Vh = g_v_hi + vch;
    const __nv_bfloat16* Vl = g_v_lo + vch;

    // prefetch kt=0 K/V
    kv_copy(sb + BUF0, t, Kh, Kl, Vh, Vl, 0);

    // Q copy: [d][q] direct from global (both bf16, 16B chunks)
#pragma unroll
    for (int c = t; c < 1024; c += 256) {
        int arr = c >> 9, d = (c >> 4) & 31, qb = c & 15;
        const __nv_bfloat16* s = (arr ? Ql : Qh) + d * 4096 + qb * 8;
        *reinterpret_cast<uint4*>(smbuf + (arr ? QL_OFF : QH_OFF) + d * TS + qb * 16) =
            *reinterpret_cast<const uint4*>(s);
    }
    __syncthreads();   // Q smem ready

    // persistent Q A-fragments via x4 trans on [d][q]
    unsigned qa[2][2][4];
#pragma unroll
    for (int sp = 0; sp < 2; sp++)
#pragma unroll
        for (int s = 0; s < 2; s++) {
            unsigned drow = s * 16 + ((lane >> 4) & 1) * 8 + (lane & 7);
            unsigned col  = (unsigned)w * 32 + ((lane >> 3) & 1) * 16;
            ldsm_x4t(qa[sp][s][0], qa[sp][s][1], qa[sp][s][2], qa[sp][s][3],
                     sb + (sp ? QL_OFF : QH_OFF) + drow * TS + col);
        }

    float Oacc[4][4];
#pragma unroll
    for (int dn = 0; dn < 4; dn++)
#pragma unroll
        for (int c = 0; c < 4; c++) Oacc[dn][c] = 0.f;
    float mr0 = -1e30f, mr1 = -1e30f, lr0 = 0.f, lr1 = 0.f;

    for (int kt = 0; kt < 8; kt++) {
        cp_wait_all();
        __syncthreads();   // tile ready for all; prior buffer reads finished
        if (kt < 7)
            kv_copy(sb + BUF0 + ((kt + 1) & 1) * BUFSZ, t, Kh, Kl, Vh, Vl, (kt + 1) * 128);
        const unsigned kb = sb + BUF0 + (kt & 1) * BUFSZ;

        // ---- MMA1: S = Q.K^T, 3 bf16-split passes, split accumulators ----
        float S[16][4];
#pragma unroll
        for (int j = 0; j < 16; j++) {
            unsigned kh0, kh1, kh2, kh3, kl0, kl1, kl2, kl3;
            ldsm_x4t(kh0, kh1, kh2, kh3, kb + lane * TS + j * 16);
            ldsm_x4t(kl0, kl1, kl2, kl3, kb + 8704 + lane * TS + j * 16);
            float a0 = 0.f, a1 = 0.f, a2 = 0.f, a3 = 0.f;
            float b0 = 0.f, b1 = 0.f, b2 = 0.f, b3 = 0.f;
            mma16816(a0, a1, a2, a3, qa[0][0][0], qa[0][0][1], qa[0][0][2], qa[0][0][3], kh0, kh1);
            mma16816(a0, a1, a2, a3, qa[0][1][0], qa[0][1][1], qa[0][1][2], qa[0][1][3], kh2, kh3);
            mma16816(b0, b1, b2, b3, qa[0][0][0], qa[0][0][1], qa[0][0][2], qa[0][0][3], kl0, kl1);
            mma16816(b0, b1, b2, b3, qa[0][1][0], qa[0][1][1], qa[0][1][2], qa[0][1][3], kl2, kl3);
            mma16816(b0, b1, b2, b3, qa[1][0][0], qa[1][0][1], qa[1][0][2], qa[1][0][3], kh0, kh1);
            mma16816(b0, b1, b2, b3, qa[1][1][0], qa[1][1][1], qa[1][1][2], qa[1][1][3], kh2, kh3);
            S[j][0] = a0 + b0; S[j][1] = a1 + b1; S[j][2] = a2 + b2; S[j][3] = a3 + b3;
        }

        // ---- online softmax (rows r=lane>>2 and r+8) ----
        float mx0 = -1e30f, mx1 = -1e30f;
#pragma unroll
        for (int j = 0; j < 16; j++) {
            mx0 = fmaxf(mx0, fmaxf(S[j][0], S[j][1]));
            mx1 = fmaxf(mx1, fmaxf(S[j][2], S[j][3]));
        }
        mx0 = fmaxf(mx0, __shfl_xor_sync(0xFFFFFFFFu, mx0, 1));
        mx0 = fmaxf(mx0, __shfl_xor_sync(0xFFFFFFFFu, mx0, 2));
        mx1 = fmaxf(mx1, __shfl_xor_sync(0xFFFFFFFFu, mx1, 1));
        mx1 = fmaxf(mx1, __shfl_xor_sync(0xFFFFFFFFu, mx1, 2));
        float nm0 = fmaxf(mr0, mx0), nm1 = fmaxf(mr1, mx1);
        float be0 = __expf(mr0 - nm0), be1 = __expf(mr1 - nm1);
        float lt0 = 0.f, lt1 = 0.f;
#pragma unroll
        for (int j = 0; j < 16; j++) {
            S[j][0] = __expf(S[j][0] - nm0); lt0 += S[j][0];
            S[j][1] = __expf(S[j][1] - nm0); lt0 += S[j][1];
            S[j][2] = __expf(S[j][2] - nm1); lt1 += S[j][2];
            S[j][3] = __expf(S[j][3] - nm1); lt1 += S[j][3];
        }
        lt0 += __shfl_xor_sync(0xFFFFFFFFu, lt0, 1);
        lt0 += __shfl_xor_sync(0xFFFFFFFFu, lt0, 2);
        lt1 += __shfl_xor_sync(0xFFFFFFFFu, lt1, 1);
        lt1 += __shfl_xor_sync(0xFFFFFFFFu, lt1, 2);
        lr0 = lr0 * be0 + lt0; lr1 = lr1 * be1 + lt1;
        mr0 = nm0; mr1 = nm1;
#pragma unroll
        for (int dn = 0; dn < 4; dn++) {
            Oacc[dn][0] *= be0; Oacc[dn][1] *= be0;
            Oacc[dn][2] *= be1; Oacc[dn][3] *= be1;
        }

        // ---- MMA2: O += P.V (P frags from S, V via x4 non-trans) ----
#pragma unroll
        for (int tt = 0; tt < 8; tt++) {
            unsigned ah[4], al[4];
            {
                unsigned short h0 = bf_hi(S[2*tt][0]),   h1 = bf_hi(S[2*tt][1]);
                unsigned short h2 = bf_hi(S[2*tt][2]),   h3 = bf_hi(S[2*tt][3]);
                unsigned short h4 = bf_hi(S[2*tt+1][0]), h5 = bf_hi(S[2*tt+1][1]);
                unsigned short h6 = bf_hi(S[2*tt+1][2]), h7 = bf_hi(S[2*tt+1][3]);
                ah[0] = pk(h0, h1); ah[1] = pk(h2, h3);
                ah[2] = pk(h4, h5); ah[3] = pk(h6, h7);
                al[0] = pk(bf_lo(S[2*tt][0], h0),   bf_lo(S[2*tt][1], h1));
                al[1] = pk(bf_lo(S[2*tt][2], h2),   bf_lo(S[2*tt][3], h3));
                al[2] = pk(bf_lo(S[2*tt+1][0], h4), bf_lo(S[2*tt+1][1], h5));
                al[3] = pk(bf_lo(S[2*tt+1][2], h6), bf_lo(S[2*tt+1][3], h7));
            }
#pragma unroll
            for (int p = 0; p < 2; p++) {
                unsigned drow = (unsigned)p * 16 + ((lane >> 4) & 1) * 8 + (lane & 7);
                unsigned colb = (unsigned)tt * 32 + ((lane >> 3) & 1) * 16;
                unsigned vh0, vh1, vh2, vh3, vl0, vl1, vl2, vl3;
                ldsm_x4(vh0, vh1, vh2, vh3, kb + 17408 + drow * TS + colb);
                ldsm_x4(vl0, vl1, vl2, vl3, kb + 26112 + drow * TS + colb);
                int d0 = p * 2, d1 = p * 2 + 1;
                mma16816(Oacc[d0][0], Oacc[d0][1], Oacc[d0][2], Oacc[d0][3],
                         ah[0], ah[1], ah[2], ah[3], vh0, vh1);
                mma16816(Oacc[d0][0], Oacc[d0][1], Oacc[d0][2], Oacc[d0][3],
                         ah[0], ah[1], ah[2], ah[3], vl0, vl1);
                mma16816(Oacc[d0][0], Oacc[d0][1], Oacc[d0][2], Oacc[d0][3],
                         al[0], al[1], al[2], al[3], vh0, vh1);
                mma16816(Oacc[d1][0], Oacc[d1][1], Oacc[d1][2], Oacc[d1][3],
                         ah[0], ah[1], ah[2], ah[3], vh2, vh3);
                mma16816(Oacc[d1][0], Oacc[d1][1], Oacc[d1][2], Oacc[d1][3],
                         ah[0], ah[1], ah[2], ah[3], vl2, vl3);
                mma16816(Oacc[d1][0], Oacc[d1][1], Oacc[d1][2], Oacc[d1][3],
                         al[0], al[1], al[2], al[3], vh2, vh3);
            }
        }
    }

    // ---- normalize + stage O [q][d] (stride 33 floats) in Q smem region ----
    __syncthreads();
    {
        float inv0 = 1.f / lr0, inv1 = 1.f / lr1;
        int r = w * 16 + (lane >> 2);
        int dc = (lane & 3) * 2;
        float* Os = (float*)(smbuf);
#pragma unroll
        for (int dn = 0; dn < 4; dn++) {
            int d = dn * 8 + dc;
            Os[r * 33 + d]           = Oacc[dn][0] * inv0;
            Os[r * 33 + d + 1]       = Oacc[dn][1] * inv0;
            Os[(r + 8) * 33 + d]     = Oacc[dn][2] * inv1;
            Os[(r + 8) * 33 + d + 1] = Oacc[dn][3] * inv1;
        }
    }
    __syncthreads();

    float* Op = g_o + (b * 256 + h * 32) * 4096 + area * 1024;
    const float* Os = (const float*)(smbuf);
    for (int i = t * 4; i < 4096; i += 1024) {
        int d = i >> 7, q = i & 127;
        float4 o;
        o.x = Os[(q + 0) * 33 + d];
        o.y = Os[(q + 1) * 33 + d];
        o.z = Os[(q + 2) * 33 + d];
        o.w = Os[(q + 3) * 33 + d];
        *(float4*)&Op[d * 4096 + q0 + q] = o;
    }
}

// ---------------- launch ------------------------------------------------------
extern "C" void kernel_launch(void* const* d_in, const int* in_sizes, int n_in,
                              void* d_out, int out_size)
{
    const float *x, *w_qk, *w_v, *w_pe, *w_proj;
    const float *qk_g, *qk_b, *qk_m, *qk_v;
    const float *v_g, *v_b, *v_m, *v_v;
    const float *pe_g, *pe_b, *pe_m, *pe_v;
    const float *pr_g, *pr_b, *pr_m, *pr_v;

    x = (const float*)d_in[0];
    w_qk = (const float*)d_in[1];
    if (in_sizes[2] == 512) {
        qk_g = (const float*)d_in[2];  qk_b = (const float*)d_in[3];
        qk_m = (const float*)d_in[4];  qk_v = (const float*)d_in[5];
        w_v  = (const float*)d_in[6];
        v_g  = (const float*)d_in[7];  v_b  = (const float*)d_in[8];
        v_m  = (const float*)d_in[9];  v_v  = (const float*)d_in[10];
        w_pe = (const float*)d_in[11];
        pe_g = (const float*)d_in[12]; pe_b = (const float*)d_in[13];
        pe_m = (const float*)d_in[14]; pe_v = (const float*)d_in[15];
        w_proj = (const float*)d_in[16];
        pr_g = (const float*)d_in[17]; pr_b = (const float*)d_in[18];
        pr_m = (const float*)d_in[19]; pr_v = (const float*)d_in[20];
    } else {
        w_v    = (const float*)d_in[2];
        w_pe   = (const float*)d_in[3];
        w_proj = (const float*)d_in[4];
        qk_g = (const float*)d_in[5];  qk_b = (const float*)d_in[6];
        qk_m = (const float*)d_in[7];  qk_v = (const float*)d_in[8];
        v_g  = (const float*)d_in[9];  v_b  = (const float*)d_in[10];
        v_m  = (const float*)d_in[11]; v_v  = (const float*)d_in[12];
        pe_g = (const float*)d_in[13]; pe_b = (const float*)d_in[14];
        pe_m = (const float*)d_in[15]; pe_v = (const float*)d_in[16];
        pr_g = (const float*)d_in[17]; pr_b = (const float*)d_in[18];
        pr_m = (const float*)d_in[19]; pr_v = (const float*)d_in[20];
    }
    float* out = (float*)d_out;

    cudaFuncSetAttribute(flash_mma, cudaFuncAttributeMaxDynamicSharedMemorySize, FM_SMEM);

    conv1x1_bn<<<dim3(32, 4, 2), 256>>>(w_qk, x, nullptr, qk_g, qk_b, qk_m, qk_v,
                                        512, 0, 0);
    conv1x1_bn<<<dim3(32, 2, 2), 256>>>(w_v, x, nullptr, v_g, v_b, v_m, v_v,
                                        256, 0, 1);
    dw5_bn<<<512, 256>>>(w_pe, pe_g, pe_b, pe_m, pe_v);
    flash_mma<<<dim3(8, 64), 256, FM_SMEM>>>();
    conv1x1_bn<<<dim3(32, 2, 2), 256>>>(w_proj, nullptr, out, pr_g, pr_b, pr_m, pr_v,
                                        256, 1, 2);
}

// round 10
// speedup vs baseline: 1.6107x; 1.0615x over previous
#include <cuda_runtime.h>
#include <cuda_bf16.h>

#define BN_EPS 1e-5f
#define SC 0.17677669529663687f

// ---------------- scratch (device globals; no allocation allowed) -------------
__device__ float g_yv [2 * 256 * 4096];                 // v conv fp32 (for dw)
__device__ float g_pp [2 * 256 * 4096];                 // depthwise+BN
__device__ float g_o  [2 * 256 * 4096];                 // attention output
__device__ __nv_bfloat16 g_qk_hi[2 * 512 * 4096];       // qk conv bf16 hi (Q pre-scaled)
__device__ __nv_bfloat16 g_qk_lo[2 * 512 * 4096];       // qk conv bf16 lo
__device__ __nv_bfloat16 g_v_hi [2 * 256 * 4096];       // v conv bf16 hi
__device__ __nv_bfloat16 g_v_lo [2 * 256 * 4096];       // v conv bf16 lo

__device__ __forceinline__ unsigned short bf_hi(float x) {
    return __bfloat16_as_ushort(__float2bfloat16(x));
}
__device__ __forceinline__ unsigned short bf_lo(float x, unsigned short h) {
    __nv_bfloat16 hb = __ushort_as_bfloat16(h);
    return __bfloat16_as_ushort(__float2bfloat16(x - __bfloat162float(hb)));
}
__device__ __forceinline__ unsigned pk(unsigned short a, unsigned short b) {
    return ((unsigned)b << 16) | (unsigned)a;
}
__device__ __forceinline__ unsigned smem_u32(const void* p) {
    unsigned a;
    asm("{ .reg .u64 t; cvta.to.shared.u64 t, %1; cvt.u32.u64 %0, t; }" : "=r"(a) : "l"(p));
    return a;
}
__device__ __forceinline__ void ldsm_x4(unsigned& r0, unsigned& r1, unsigned& r2, unsigned& r3,
                                        unsigned addr) {
    asm volatile("ldmatrix.sync.aligned.m8n8.x4.shared.b16 {%0,%1,%2,%3}, [%4];"
                 : "=r"(r0), "=r"(r1), "=r"(r2), "=r"(r3) : "r"(addr));
}
__device__ __forceinline__ void ldsm_x4t(unsigned& r0, unsigned& r1, unsigned& r2, unsigned& r3,
                                         unsigned addr) {
    asm volatile("ldmatrix.sync.aligned.m8n8.x4.trans.shared.b16 {%0,%1,%2,%3}, [%4];"
                 : "=r"(r0), "=r"(r1), "=r"(r2), "=r"(r3) : "r"(addr));
}
__device__ __forceinline__ void mma16816(float& c0, float& c1, float& c2, float& c3,
                                         unsigned a0, unsigned a1, unsigned a2, unsigned a3,
                                         unsigned b0, unsigned b1) {
    asm volatile(
        "mma.sync.aligned.m16n8k16.row.col.f32.bf16.bf16.f32 "
        "{%0,%1,%2,%3}, {%4,%5,%6,%7}, {%8,%9}, {%0,%1,%2,%3};"
        : "+f"(c0), "+f"(c1), "+f"(c2), "+f"(c3)
        : "r"(a0), "r"(a1), "r"(a2), "r"(a3), "r"(b0), "r"(b1));
}
__device__ __forceinline__ void cp_async16(unsigned dst, const void* src) {
    asm volatile("cp.async.cg.shared.global [%0], [%1], 16;" :: "r"(dst), "l"(src) : "memory");
}
__device__ __forceinline__ void cp_commit() {
    asm volatile("cp.async.commit_group;" ::: "memory");
}
__device__ __forceinline__ void cp_wait_all() {
    asm volatile("cp.async.wait_group 0;" ::: "memory");
}

// =============== tensor-core conv1x1 + BN (3xBF16 split GEMM) =================
// Y[b][m][n] = BN(sum_k W[m][k] X[b][k][n]), K=256, N=4096.
// NT = n-tiles per warp row (16 -> 128-wide CTA tile, 8 -> 64-wide).
// out_mode 0: qk -> g_qk hi/lo (rows<256 scaled by SC)
// out_mode 1: v  -> g_yv fp32 + g_v hi/lo
// out_mode 2: proj (input g_o+g_pp) -> dout fp32
#define CWH 0
#define CWL 8704
#define CXH 17408
#define CXL 26112

template<int NT>
__global__ __launch_bounds__(256) void conv_tc(
    const float* __restrict__ W, const float* __restrict__ xp,
    float* __restrict__ dout,
    const float* __restrict__ gg, const float* __restrict__ bb,
    const float* __restrict__ mm, const float* __restrict__ vv,
    int M, int out_mode)
{
    __shared__ char csm[34816];
    const unsigned sbc = smem_u32(csm);
    const int K = 256, N = 4096;
    const int t = threadIdx.x, lane = t & 31, w = t >> 5;
    const int b = blockIdx.z;
    const int m0 = blockIdx.y * 128, n0 = blockIdx.x * (NT * 8);

    const float* X  = (out_mode == 2 ? g_o : xp) + b * K * N;
    const float* X2 = (out_mode == 2 ? g_pp + b * K * N : nullptr);

    float S[NT][4];
#pragma unroll
    for (int j = 0; j < NT; j++)
#pragma unroll
        for (int c = 0; c < 4; c++) S[j][c] = 0.f;

    for (int c0 = 0; c0 < 8; c0++) {
        const int k0 = c0 * 32;
        __syncthreads();
        // ---- W[m0..+128][k0..+32] -> Whi/Wlo [k][m] (transposed) ----
        for (int u = t; u < 1024; u += 256) {
            int m = u >> 3, kq = (u & 7) * 4;
            float4 wv = *reinterpret_cast<const float4*>(&W[(m0 + m) * K + k0 + kq]);
            float wa[4] = {wv.x, wv.y, wv.z, wv.w};
#pragma unroll
            for (int j = 0; j < 4; j++) {
                unsigned short hi = bf_hi(wa[j]), lo = bf_lo(wa[j], hi);
                *(unsigned short*)(csm + CWH + (kq + j) * 272 + m * 2) = hi;
                *(unsigned short*)(csm + CWL + (kq + j) * 272 + m * 2) = lo;
            }
        }
        // ---- X[k0..+32][n0..+NT*8] (+X2) -> Xhi/Xlo [k][n] ----
        for (int u = t; u < NT * 64; u += 256) {
            int k = u / (NT * 2), nq = (u % (NT * 2)) * 4;
            float4 xv = *reinterpret_cast<const float4*>(&X[(k0 + k) * N + n0 + nq]);
            if (X2) {
                float4 x2 = *reinterpret_cast<const float4*>(&X2[(k0 + k) * N + n0 + nq]);
                xv.x += x2.x; xv.y += x2.y; xv.z += x2.z; xv.w += x2.w;
            }
            float xa[4] = {xv.x, xv.y, xv.z, xv.w};
            unsigned short h[4], l[4];
#pragma unroll
            for (int j = 0; j < 4; j++) { h[j] = bf_hi(xa[j]); l[j] = bf_lo(xa[j], h[j]); }
            uint2 uh = make_uint2(pk(h[0], h[1]), pk(h[2], h[3]));
            uint2 ul = make_uint2(pk(l[0], l[1]), pk(l[2], l[3]));
            *reinterpret_cast<uint2*>(csm + CXH + k * 272 + nq * 2) = uh;
            *reinterpret_cast<uint2*>(csm + CXL + k * 272 + nq * 2) = ul;
        }
        __syncthreads();

        // ---- W A-fragments (same mapping as flash Q frags) ----
        unsigned wa_[2][2][4];
#pragma unroll
        for (int sp = 0; sp < 2; sp++)
#pragma unroll
            for (int s = 0; s < 2; s++) {
                unsigned drow = s * 16 + ((lane >> 4) & 1) * 8 + (lane & 7);
                unsigned col  = (unsigned)w * 32 + ((lane >> 3) & 1) * 16;
                ldsm_x4t(wa_[sp][s][0], wa_[sp][s][1], wa_[sp][s][2], wa_[sp][s][3],
                         sbc + (sp ? CWL : CWH) + drow * 272 + col);
            }
        // ---- per n-tile: B frags + 6 mma (3 split passes x 2 ksteps) ----
#pragma unroll
        for (int j = 0; j < NT; j++) {
            unsigned xh0, xh1, xh2, xh3, xl0, xl1, xl2, xl3;
            ldsm_x4t(xh0, xh1, xh2, xh3, sbc + CXH + lane * 272 + j * 16);
            ldsm_x4t(xl0, xl1, xl2, xl3, sbc + CXL + lane * 272 + j * 16);
            mma16816(S[j][0], S[j][1], S[j][2], S[j][3],
                     wa_[0][0][0], wa_[0][0][1], wa_[0][0][2], wa_[0][0][3], xh0, xh1);
            mma16816(S[j][0], S[j][1], S[j][2], S[j][3],
                     wa_[0][1][0], wa_[0][1][1], wa_[0][1][2], wa_[0][1][3], xh2, xh3);
            mma16816(S[j][0], S[j][1], S[j][2], S[j][3],
                     wa_[0][0][0], wa_[0][0][1], wa_[0][0][2], wa_[0][0][3], xl0, xl1);
            mma16816(S[j][0], S[j][1], S[j][2], S[j][3],
                     wa_[0][1][0], wa_[0][1][1], wa_[0][1][2], wa_[0][1][3], xl2, xl3);
            mma16816(S[j][0], S[j][1], S[j][2], S[j][3],
                     wa_[1][0][0], wa_[1][0][1], wa_[1][0][2], wa_[1][0][3], xh0, xh1);
            mma16816(S[j][0], S[j][1], S[j][2], S[j][3],
                     wa_[1][1][0], wa_[1][1][1], wa_[1][1][2], wa_[1][1][3], xh2, xh3);
        }
    }

    // ---- epilogue: BN + writes. c0/c1 -> row r0, c2/c3 -> row r0+8 ----
    const int r0 = m0 + w * 16 + (lane >> 2);
    const int r1 = r0 + 8;
    float s0 = gg[r0] * rsqrtf(vv[r0] + BN_EPS);
    float bi0 = bb[r0] - mm[r0] * s0;
    float s1 = gg[r1] * rsqrtf(vv[r1] + BN_EPS);
    float bi1 = bb[r1] - mm[r1] * s1;
    if (out_mode == 0 && r0 < 256) { s0 *= SC; bi0 *= SC; }
    if (out_mode == 0 && r1 < 256) { s1 *= SC; bi1 *= SC; }

#pragma unroll
    for (int j = 0; j < NT; j++) {
        int n = n0 + j * 8 + (lane & 3) * 2;
        float o0 = S[j][0] * s0 + bi0, o1 = S[j][1] * s0 + bi0;
        float o2 = S[j][2] * s1 + bi1, o3 = S[j][3] * s1 + bi1;
        long i0 = (long)b * M * N + (long)r0 * N + n;
        long i1 = (long)b * M * N + (long)r1 * N + n;
        if (out_mode == 2) {
            *reinterpret_cast<float2*>(&dout[i0]) = make_float2(o0, o1);
            *reinterpret_cast<float2*>(&dout[i1]) = make_float2(o2, o3);
        } else {
            if (out_mode == 1) {
                *reinterpret_cast<float2*>(&g_yv[i0]) = make_float2(o0, o1);
                *reinterpret_cast<float2*>(&g_yv[i1]) = make_float2(o2, o3);
            }
            __nv_bfloat16* H = (out_mode == 0 ? g_qk_hi : g_v_hi);
            __nv_bfloat16* L = (out_mode == 0 ? g_qk_lo : g_v_lo);
            unsigned short h0 = bf_hi(o0), h1 = bf_hi(o1);
            unsigned short h2 = bf_hi(o2), h3 = bf_hi(o3);
            *reinterpret_cast<unsigned*>(&H[i0]) = pk(h0, h1);
            *reinterpret_cast<unsigned*>(&H[i1]) = pk(h2, h3);
            *reinterpret_cast<unsigned*>(&L[i0]) = pk(bf_lo(o0, h0), bf_lo(o1, h1));
            *reinterpret_cast<unsigned*>(&L[i1]) = pk(bf_lo(o2, h2), bf_lo(o3, h3));
        }
    }
}

// ---------------- depthwise 5x5 (pad 2) + BN on g_yv -> g_pp ------------------
__global__ __launch_bounds__(256) void dw5_bn(
    const float* __restrict__ w_pe,
    const float* __restrict__ gg, const float* __restrict__ bb,
    const float* __restrict__ mm, const float* __restrict__ vv)
{
    const int bc = blockIdx.x;
    const int c  = bc & 255;
    const float* src = g_yv + bc * 4096;
    float* dst = g_pp + bc * 4096;

    __shared__ float tile[68][68];
    __shared__ float wk[25];
    const int t = threadIdx.x;

    for (int i = t; i < 68 * 68; i += 256) ((float*)tile)[i] = 0.f;
    if (t < 25) wk[t] = w_pe[c * 25 + t];
    __syncthreads();
    for (int i = t; i < 4096; i += 256) tile[(i >> 6) + 2][(i & 63) + 2] = src[i];
    __syncthreads();

    float s  = gg[c] * rsqrtf(vv[c] + BN_EPS);
    float bi = bb[c] - mm[c] * s;

    for (int i = t; i < 4096; i += 256) {
        int y = i >> 6, x = i & 63;
        float acc = 0.f;
#pragma unroll
        for (int ky = 0; ky < 5; ky++)
#pragma unroll
            for (int kx = 0; kx < 5; kx++)
                acc = fmaf(tile[y + ky][x + kx], wk[ky * 5 + kx], acc);
        dst[i] = acc * s + bi;
    }
}

// ================= flash attention (unchanged from R9 WIN) ====================
#define TS 272
#define QH_OFF 0
#define QL_OFF 8704
#define BUF0   17408
#define BUFSZ  34816
#define FM_SMEM (BUF0 + 2 * BUFSZ)

__device__ __forceinline__ void kv_copy(unsigned base, int t,
    const __nv_bfloat16* Kh, const __nv_bfloat16* Kl,
    const __nv_bfloat16* Vh, const __nv_bfloat16* Vl, int m0)
{
#pragma unroll
    for (int c = t; c < 2048; c += 256) {
        int arr = c >> 9, d = (c >> 4) & 31, mb = c & 15;
        const __nv_bfloat16* s =
            (arr == 0 ? Kh : (arr == 1 ? Kl : (arr == 2 ? Vh : Vl))) + d * 4096 + m0 + mb * 8;
        cp_async16(base + arr * 8704 + d * TS + mb * 16, s);
    }
    cp_commit();
}

__global__ __launch_bounds__(256) void flash_mma()
{
    extern __shared__ char smbuf[];
    const unsigned sb = smem_u32(smbuf);
    const int t = threadIdx.x, lane = t & 31, w = t >> 5;

    const int bh = blockIdx.y;
    const int b = bh >> 5, area = (bh >> 3) & 3, h = bh & 7;
    const int q0 = blockIdx.x * 128;

    const int qch = (b * 512 + h * 32) * 4096 + area * 1024;
    const int kch = (b * 512 + 256 + h * 32) * 4096 + area * 1024;
    const int vch = (b * 256 + h * 32) * 4096 + area * 1024;
    const __nv_bfloat16* Qh = g_qk_hi + qch + q0;
    const __nv_bfloat16* Ql = g_qk_lo + qch + q0;
    const __nv_bfloat16* Kh = g_qk_hi + kch;
    const __nv_bfloat16* Kl = g_qk_lo + kch;
    const __nv_bfloat16* Vh = g_v_hi + vch;
    const __nv_bfloat16* Vl = g_v_lo + vch;

    kv_copy(sb + BUF0, t, Kh, Kl, Vh, Vl, 0);

#pragma unroll
    for (int c = t; c < 1024; c += 256) {
        int arr = c >> 9, d = (c >> 4) & 31, qb = c & 15;
        const __nv_bfloat16* s = (arr ? Ql : Qh) + d * 4096 + qb * 8;
        *reinterpret_cast<uint4*>(smbuf + (arr ? QL_OFF : QH_OFF) + d * TS + qb * 16) =
            *reinterpret_cast<const uint4*>(s);
    }
    __syncthreads();

    unsigned qa[2][2][4];
#pragma unroll
    for (int sp = 0; sp < 2; sp++)
#pragma unroll
        for (int s = 0; s < 2; s++) {
            unsigned drow = s * 16 + ((lane >> 4) & 1) * 8 + (lane & 7);
            unsigned col  = (unsigned)w * 32 + ((lane >> 3) & 1) * 16;
            ldsm_x4t(qa[sp][s][0], qa[sp][s][1], qa[sp][s][2], qa[sp][s][3],
                     sb + (sp ? QL_OFF : QH_OFF) + drow * TS + col);
        }

    float Oacc[4][4];
#pragma unroll
    for (int dn = 0; dn < 4; dn++)
#pragma unroll
        for (int c = 0; c < 4; c++) Oacc[dn][c] = 0.f;
    float mr0 = -1e30f, mr1 = -1e30f, lr0 = 0.f, lr1 = 0.f;

    for (int kt = 0; kt < 8; kt++) {
        cp_wait_all();
        __syncthreads();
        if (kt < 7)
            kv_copy(sb + BUF0 + ((kt + 1) & 1) * BUFSZ, t, Kh, Kl, Vh, Vl, (kt + 1) * 128);
        const unsigned kb = sb + BUF0 + (kt & 1) * BUFSZ;

        float S[16][4];
#pragma unroll
        for (int j = 0; j < 16; j++) {
            unsigned kh0, kh1, kh2, kh3, kl0, kl1, kl2, kl3;
            ldsm_x4t(kh0, kh1, kh2, kh3, kb + lane * TS + j * 16);
            ldsm_x4t(kl0, kl1, kl2, kl3, kb + 8704 + lane * TS + j * 16);
            float a0 = 0.f, a1 = 0.f, a2 = 0.f, a3 = 0.f;
            float b0 = 0.f, b1 = 0.f, b2 = 0.f, b3 = 0.f;
            mma16816(a0, a1, a2, a3, qa[0][0][0], qa[0][0][1], qa[0][0][2], qa[0][0][3], kh0, kh1);
            mma16816(a0, a1, a2, a3, qa[0][1][0], qa[0][1][1], qa[0][1][2], qa[0][1][3], kh2, kh3);
            mma16816(b0, b1, b2, b3, qa[0][0][0], qa[0][0][1], qa[0][0][2], qa[0][0][3], kl0, kl1);
            mma16816(b0, b1, b2, b3, qa[0][1][0], qa[0][1][1], qa[0][1][2], qa[0][1][3], kl2, kl3);
            mma16816(b0, b1, b2, b3, qa[1][0][0], qa[1][0][1], qa[1][0][2], qa[1][0][3], kh0, kh1);
            mma16816(b0, b1, b2, b3, qa[1][1][0], qa[1][1][1], qa[1][1][2], qa[1][1][3], kh2, kh3);
            S[j][0] = a0 + b0; S[j][1] = a1 + b1; S[j][2] = a2 + b2; S[j][3] = a3 + b3;
        }

        float mx0 = -1e30f, mx1 = -1e30f;
#pragma unroll
        for (int j = 0; j < 16; j++) {
            mx0 = fmaxf(mx0, fmaxf(S[j][0], S[j][1]));
            mx1 = fmaxf(mx1, fmaxf(S[j][2], S[j][3]));
        }
        mx0 = fmaxf(mx0, __shfl_xor_sync(0xFFFFFFFFu, mx0, 1));
        mx0 = fmaxf(mx0, __shfl_xor_sync(0xFFFFFFFFu, mx0, 2));
        mx1 = fmaxf(mx1, __shfl_xor_sync(0xFFFFFFFFu, mx1, 1));
        mx1 = fmaxf(mx1, __shfl_xor_sync(0xFFFFFFFFu, mx1, 2));
        float nm0 = fmaxf(mr0, mx0), nm1 = fmaxf(mr1, mx1);
        float be0 = __expf(mr0 - nm0), be1 = __expf(mr1 - nm1);
        float lt0 = 0.f, lt1 = 0.f;
#pragma unroll
        for (int j = 0; j < 16; j++) {
            S[j][0] = __expf(S[j][0] - nm0); lt0 += S[j][0];
            S[j][1] = __expf(S[j][1] - nm0); lt0 += S[j][1];
            S[j][2] = __expf(S[j][2] - nm1); lt1 += S[j][2];
            S[j][3] = __expf(S[j][3] - nm1); lt1 += S[j][3];
        }
        lt0 += __shfl_xor_sync(0xFFFFFFFFu, lt0, 1);
        lt0 += __shfl_xor_sync(0xFFFFFFFFu, lt0, 2);
        lt1 += __shfl_xor_sync(0xFFFFFFFFu, lt1, 1);
        lt1 += __shfl_xor_sync(0xFFFFFFFFu, lt1, 2);
        lr0 = lr0 * be0 + lt0; lr1 = lr1 * be1 + lt1;
        mr0 = nm0; mr1 = nm1;
#pragma unroll
        for (int dn = 0; dn < 4; dn++) {
            Oacc[dn][0] *= be0; Oacc[dn][1] *= be0;
            Oacc[dn][2] *= be1; Oacc[dn][3] *= be1;
        }

#pragma unroll
        for (int tt = 0; tt < 8; tt++) {
            unsigned ah[4], al[4];
            {
                unsigned short h0 = bf_hi(S[2*tt][0]),   h1 = bf_hi(S[2*tt][1]);
                unsigned short h2 = bf_hi(S[2*tt][2]),   h3 = bf_hi(S[2*tt][3]);
                unsigned short h4 = bf_hi(S[2*tt+1][0]), h5 = bf_hi(S[2*tt+1][1]);
                unsigned short h6 = bf_hi(S[2*tt+1][2]), h7 = bf_hi(S[2*tt+1][3]);
                ah[0] = pk(h0, h1); ah[1] = pk(h2, h3);
                ah[2] = pk(h4, h5); ah[3] = pk(h6, h7);
                al[0] = pk(bf_lo(S[2*tt][0], h0),   bf_lo(S[2*tt][1], h1));
                al[1] = pk(bf_lo(S[2*tt][2], h2),   bf_lo(S[2*tt][3], h3));
                al[2] = pk(bf_lo(S[2*tt+1][0], h4), bf_lo(S[2*tt+1][1], h5));
                al[3] = pk(bf_lo(S[2*tt+1][2], h6), bf_lo(S[2*tt+1][3], h7));
            }
#pragma unroll
            for (int p = 0; p < 2; p++) {
                unsigned drow = (unsigned)p * 16 + ((lane >> 4) & 1) * 8 + (lane & 7);
                unsigned colb = (unsigned)tt * 32 + ((lane >> 3) & 1) * 16;
                unsigned vh0, vh1, vh2, vh3, vl0, vl1, vl2, vl3;
                ldsm_x4(vh0, vh1, vh2, vh3, kb + 17408 + drow * TS + colb);
                ldsm_x4(vl0, vl1, vl2, vl3, kb + 26112 + drow * TS + colb);
                int d0 = p * 2, d1 = p * 2 + 1;
                mma16816(Oacc[d0][0], Oacc[d0][1], Oacc[d0][2], Oacc[d0][3],
                         ah[0], ah[1], ah[2], ah[3], vh0, vh1);
                mma16816(Oacc[d0][0], Oacc[d0][1], Oacc[d0][2], Oacc[d0][3],
                         ah[0], ah[1], ah[2], ah[3], vl0, vl1);
                mma16816(Oacc[d0][0], Oacc[d0][1], Oacc[d0][2], Oacc[d0][3],
                         al[0], al[1], al[2], al[3], vh0, vh1);
                mma16816(Oacc[d1][0], Oacc[d1][1], Oacc[d1][2], Oacc[d1][3],
                         ah[0], ah[1], ah[2], ah[3], vh2, vh3);
                mma16816(Oacc[d1][0], Oacc[d1][1], Oacc[d1][2], Oacc[d1][3],
                         ah[0], ah[1], ah[2], ah[3], vl2, vl3);
                mma16816(Oacc[d1][0], Oacc[d1][1], Oacc[d1][2], Oacc[d1][3],
                         al[0], al[1], al[2], al[3], vh2, vh3);
            }
        }
    }

    __syncthreads();
    {
        float inv0 = 1.f / lr0, inv1 = 1.f / lr1;
        int r = w * 16 + (lane >> 2);
        int dc = (lane & 3) * 2;
        float* Os = (float*)(smbuf);
#pragma unroll
        for (int dn = 0; dn < 4; dn++) {
            int d = dn * 8 + dc;
            Os[r * 33 + d]           = Oacc[dn][0] * inv0;
            Os[r * 33 + d + 1]       = Oacc[dn][1] * inv0;
            Os[(r + 8) * 33 + d]     = Oacc[dn][2] * inv1;
            Os[(r + 8) * 33 + d + 1] = Oacc[dn][3] * inv1;
        }
    }
    __syncthreads();

    float* Op = g_o + (b * 256 + h * 32) * 4096 + area * 1024;
    const float* Os = (const float*)(smbuf);
    for (int i = t * 4; i < 4096; i += 1024) {
        int d = i >> 7, q = i & 127;
        float4 o;
        o.x = Os[(q + 0) * 33 + d];
        o.y = Os[(q + 1) * 33 + d];
        o.z = Os[(q + 2) * 33 + d];
        o.w = Os[(q + 3) * 33 + d];
        *(float4*)&Op[d * 4096 + q0 + q] = o;
    }
}

// ---------------- launch ------------------------------------------------------
extern "C" void kernel_launch(void* const* d_in, const int* in_sizes, int n_in,
                              void* d_out, int out_size)
{
    const float *x, *w_qk, *w_v, *w_pe, *w_proj;
    const float *qk_g, *qk_b, *qk_m, *qk_v;
    const float *v_g, *v_b, *v_m, *v_v;
    const float *pe_g, *pe_b, *pe_m, *pe_v;
    const float *pr_g, *pr_b, *pr_m, *pr_v;

    x = (const float*)d_in[0];
    w_qk = (const float*)d_in[1];
    if (in_sizes[2] == 512) {
        qk_g = (const float*)d_in[2];  qk_b = (const float*)d_in[3];
        qk_m = (const float*)d_in[4];  qk_v = (const float*)d_in[5];
        w_v  = (const float*)d_in[6];
        v_g  = (const float*)d_in[7];  v_b  = (const float*)d_in[8];
        v_m  = (const float*)d_in[9];  v_v  = (const float*)d_in[10];
        w_pe = (const float*)d_in[11];
        pe_g = (const float*)d_in[12]; pe_b = (const float*)d_in[13];
        pe_m = (const float*)d_in[14]; pe_v = (const float*)d_in[15];
        w_proj = (const float*)d_in[16];
        pr_g = (const float*)d_in[17]; pr_b = (const float*)d_in[18];
        pr_m = (const float*)d_in[19]; pr_v = (const float*)d_in[20];
    } else {
        w_v    = (const float*)d_in[2];
        w_pe   = (const float*)d_in[3];
        w_proj = (const float*)d_in[4];
        qk_g = (const float*)d_in[5];  qk_b = (const float*)d_in[6];
        qk_m = (const float*)d_in[7];  qk_v = (const float*)d_in[8];
        v_g  = (const float*)d_in[9];  v_b  = (const float*)d_in[10];
        v_m  = (const float*)d_in[11]; v_v  = (const float*)d_in[12];
        pe_g = (const float*)d_in[13]; pe_b = (const float*)d_in[14];
        pe_m = (const float*)d_in[15]; pe_v = (const float*)d_in[16];
        pr_g = (const float*)d_in[17]; pr_b = (const float*)d_in[18];
        pr_m = (const float*)d_in[19]; pr_v = (const float*)d_in[20];
    }
    float* out = (float*)d_out;

    cudaFuncSetAttribute(flash_mma, cudaFuncAttributeMaxDynamicSharedMemorySize, FM_SMEM);

    // 1. qk conv (tensor): M=512, 128-wide tiles
    conv_tc<16><<<dim3(32, 4, 2), 256>>>(w_qk, x, nullptr,
                                         qk_g, qk_b, qk_m, qk_v, 512, 0);
    // 2. v conv (tensor): M=256, 64-wide tiles (more CTAs)
    conv_tc<8><<<dim3(64, 2, 2), 256>>>(w_v, x, nullptr,
                                        v_g, v_b, v_m, v_v, 256, 1);
    // 3. depthwise
    dw5_bn<<<512, 256>>>(w_pe, pe_g, pe_b, pe_m, pe_v);
    // 4. flash attention
    flash_mma<<<dim3(8, 64), 256, FM_SMEM>>>();
    // 5. proj conv (tensor, input g_o+g_pp)
    conv_tc<8><<<dim3(64, 2, 2), 256>>>(w_proj, nullptr, out,
                                        pr_g, pr_b, pr_m, pr_v, 256, 2);
}

// round 11
// speedup vs baseline: 1.6482x; 1.0233x over previous
#include <cuda_runtime.h>
#include <cuda_bf16.h>

#define BN_EPS 1e-5f
#define SC 0.17677669529663687f

// ---------------- scratch (device globals; no allocation allowed) -------------
__device__ float g_yv [2 * 256 * 4096];                 // v conv fp32 (for dw)
__device__ float g_pp [2 * 256 * 4096];                 // depthwise+BN
__device__ float g_o  [2 * 256 * 4096];                 // attention output
__device__ __nv_bfloat16 g_qk_hi[2 * 512 * 4096];       // qk conv bf16 hi (Q pre-scaled)
__device__ __nv_bfloat16 g_qk_lo[2 * 512 * 4096];       // qk conv bf16 lo
__device__ __nv_bfloat16 g_v_hi [2 * 256 * 4096];       // v conv bf16 hi
__device__ __nv_bfloat16 g_v_lo [2 * 256 * 4096];       // v conv bf16 lo

__device__ __forceinline__ unsigned short bf_hi(float x) {
    return __bfloat16_as_ushort(__float2bfloat16(x));
}
__device__ __forceinline__ unsigned short bf_lo(float x, unsigned short h) {
    __nv_bfloat16 hb = __ushort_as_bfloat16(h);
    return __bfloat16_as_ushort(__float2bfloat16(x - __bfloat162float(hb)));
}
__device__ __forceinline__ unsigned pk(unsigned short a, unsigned short b) {
    return ((unsigned)b << 16) | (unsigned)a;
}
__device__ __forceinline__ unsigned smem_u32(const void* p) {
    unsigned a;
    asm("{ .reg .u64 t; cvta.to.shared.u64 t, %1; cvt.u32.u64 %0, t; }" : "=r"(a) : "l"(p));
    return a;
}
__device__ __forceinline__ void ldsm_x4(unsigned& r0, unsigned& r1, unsigned& r2, unsigned& r3,
                                        unsigned addr) {
    asm volatile("ldmatrix.sync.aligned.m8n8.x4.shared.b16 {%0,%1,%2,%3}, [%4];"
                 : "=r"(r0), "=r"(r1), "=r"(r2), "=r"(r3) : "r"(addr));
}
__device__ __forceinline__ void ldsm_x4t(unsigned& r0, unsigned& r1, unsigned& r2, unsigned& r3,
                                         unsigned addr) {
    asm volatile("ldmatrix.sync.aligned.m8n8.x4.trans.shared.b16 {%0,%1,%2,%3}, [%4];"
                 : "=r"(r0), "=r"(r1), "=r"(r2), "=r"(r3) : "r"(addr));
}
__device__ __forceinline__ void mma16816(float& c0, float& c1, float& c2, float& c3,
                                         unsigned a0, unsigned a1, unsigned a2, unsigned a3,
                                         unsigned b0, unsigned b1) {
    asm volatile(
        "mma.sync.aligned.m16n8k16.row.col.f32.bf16.bf16.f32 "
        "{%0,%1,%2,%3}, {%4,%5,%6,%7}, {%8,%9}, {%0,%1,%2,%3};"
        : "+f"(c0), "+f"(c1), "+f"(c2), "+f"(c3)
        : "r"(a0), "r"(a1), "r"(a2), "r"(a3), "r"(b0), "r"(b1));
}
__device__ __forceinline__ void cp_async16(unsigned dst, const void* src) {
    asm volatile("cp.async.cg.shared.global [%0], [%1], 16;" :: "r"(dst), "l"(src) : "memory");
}
__device__ __forceinline__ void cp_commit() {
    asm volatile("cp.async.commit_group;" ::: "memory");
}
__device__ __forceinline__ void cp_wait_all() {
    asm volatile("cp.async.wait_group 0;" ::: "memory");
}

// =============== tensor-core conv1x1 + BN (3xBF16 split GEMM) =================
#define CWH 0
#define CWL 8704
#define CXH 17408
#define CXL 26112

template<int NT>
__global__ __launch_bounds__(256) void conv_tc(
    const float* __restrict__ W, const float* __restrict__ xp,
    float* __restrict__ dout,
    const float* __restrict__ gg, const float* __restrict__ bb,
    const float* __restrict__ mm, const float* __restrict__ vv,
    int M, int out_mode)
{
    __shared__ char csm[34816];
    const unsigned sbc = smem_u32(csm);
    const int K = 256, N = 4096;
    const int t = threadIdx.x, lane = t & 31, w = t >> 5;
    const int b = blockIdx.z;
    const int m0 = blockIdx.y * 128, n0 = blockIdx.x * (NT * 8);

    const float* X  = (out_mode == 2 ? g_o : xp) + b * K * N;
    const float* X2 = (out_mode == 2 ? g_pp + b * K * N : nullptr);

    float S[NT][4];
#pragma unroll
    for (int j = 0; j < NT; j++)
#pragma unroll
        for (int c = 0; c < 4; c++) S[j][c] = 0.f;

    for (int c0 = 0; c0 < 8; c0++) {
        const int k0 = c0 * 32;
        __syncthreads();
        for (int u = t; u < 1024; u += 256) {
            int m = u >> 3, kq = (u & 7) * 4;
            float4 wv = *reinterpret_cast<const float4*>(&W[(m0 + m) * K + k0 + kq]);
            float wa[4] = {wv.x, wv.y, wv.z, wv.w};
#pragma unroll
            for (int j = 0; j < 4; j++) {
                unsigned short hi = bf_hi(wa[j]), lo = bf_lo(wa[j], hi);
                *(unsigned short*)(csm + CWH + (kq + j) * 272 + m * 2) = hi;
                *(unsigned short*)(csm + CWL + (kq + j) * 272 + m * 2) = lo;
            }
        }
        for (int u = t; u < NT * 64; u += 256) {
            int k = u / (NT * 2), nq = (u % (NT * 2)) * 4;
            float4 xv = *reinterpret_cast<const float4*>(&X[(k0 + k) * N + n0 + nq]);
            if (X2) {
                float4 x2 = *reinterpret_cast<const float4*>(&X2[(k0 + k) * N + n0 + nq]);
                xv.x += x2.x; xv.y += x2.y; xv.z += x2.z; xv.w += x2.w;
            }
            float xa[4] = {xv.x, xv.y, xv.z, xv.w};
            unsigned short h[4], l[4];
#pragma unroll
            for (int j = 0; j < 4; j++) { h[j] = bf_hi(xa[j]); l[j] = bf_lo(xa[j], h[j]); }
            uint2 uh = make_uint2(pk(h[0], h[1]), pk(h[2], h[3]));
            uint2 ul = make_uint2(pk(l[0], l[1]), pk(l[2], l[3]));
            *reinterpret_cast<uint2*>(csm + CXH + k * 272 + nq * 2) = uh;
            *reinterpret_cast<uint2*>(csm + CXL + k * 272 + nq * 2) = ul;
        }
        __syncthreads();

        unsigned wa_[2][2][4];
#pragma unroll
        for (int sp = 0; sp < 2; sp++)
#pragma unroll
            for (int s = 0; s < 2; s++) {
                unsigned drow = s * 16 + ((lane >> 4) & 1) * 8 + (lane & 7);
                unsigned col  = (unsigned)w * 32 + ((lane >> 3) & 1) * 16;
                ldsm_x4t(wa_[sp][s][0], wa_[sp][s][1], wa_[sp][s][2], wa_[sp][s][3],
                         sbc + (sp ? CWL : CWH) + drow * 272 + col);
            }
#pragma unroll
        for (int j = 0; j < NT; j++) {
            unsigned xh0, xh1, xh2, xh3, xl0, xl1, xl2, xl3;
            ldsm_x4t(xh0, xh1, xh2, xh3, sbc + CXH + lane * 272 + j * 16);
            ldsm_x4t(xl0, xl1, xl2, xl3, sbc + CXL + lane * 272 + j * 16);
            mma16816(S[j][0], S[j][1], S[j][2], S[j][3],
                     wa_[0][0][0], wa_[0][0][1], wa_[0][0][2], wa_[0][0][3], xh0, xh1);
            mma16816(S[j][0], S[j][1], S[j][2], S[j][3],
                     wa_[0][1][0], wa_[0][1][1], wa_[0][1][2], wa_[0][1][3], xh2, xh3);
            mma16816(S[j][0], S[j][1], S[j][2], S[j][3],
                     wa_[0][0][0], wa_[0][0][1], wa_[0][0][2], wa_[0][0][3], xl0, xl1);
            mma16816(S[j][0], S[j][1], S[j][2], S[j][3],
                     wa_[0][1][0], wa_[0][1][1], wa_[0][1][2], wa_[0][1][3], xl2, xl3);
            mma16816(S[j][0], S[j][1], S[j][2], S[j][3],
                     wa_[1][0][0], wa_[1][0][1], wa_[1][0][2], wa_[1][0][3], xh0, xh1);
            mma16816(S[j][0], S[j][1], S[j][2], S[j][3],
                     wa_[1][1][0], wa_[1][1][1], wa_[1][1][2], wa_[1][1][3], xh2, xh3);
        }
    }

    const int r0 = m0 + w * 16 + (lane >> 2);
    const int r1 = r0 + 8;
    float s0 = gg[r0] * rsqrtf(vv[r0] + BN_EPS);
    float bi0 = bb[r0] - mm[r0] * s0;
    float s1 = gg[r1] * rsqrtf(vv[r1] + BN_EPS);
    float bi1 = bb[r1] - mm[r1] * s1;
    if (out_mode == 0 && r0 < 256) { s0 *= SC; bi0 *= SC; }
    if (out_mode == 0 && r1 < 256) { s1 *= SC; bi1 *= SC; }

#pragma unroll
    for (int j = 0; j < NT; j++) {
        int n = n0 + j * 8 + (lane & 3) * 2;
        float o0 = S[j][0] * s0 + bi0, o1 = S[j][1] * s0 + bi0;
        float o2 = S[j][2] * s1 + bi1, o3 = S[j][3] * s1 + bi1;
        long i0 = (long)b * M * N + (long)r0 * N + n;
        long i1 = (long)b * M * N + (long)r1 * N + n;
        if (out_mode == 2) {
            *reinterpret_cast<float2*>(&dout[i0]) = make_float2(o0, o1);
            *reinterpret_cast<float2*>(&dout[i1]) = make_float2(o2, o3);
        } else {
            if (out_mode == 1) {
                *reinterpret_cast<float2*>(&g_yv[i0]) = make_float2(o0, o1);
                *reinterpret_cast<float2*>(&g_yv[i1]) = make_float2(o2, o3);
            }
            __nv_bfloat16* H = (out_mode == 0 ? g_qk_hi : g_v_hi);
            __nv_bfloat16* L = (out_mode == 0 ? g_qk_lo : g_v_lo);
            unsigned short h0 = bf_hi(o0), h1 = bf_hi(o1);
            unsigned short h2 = bf_hi(o2), h3 = bf_hi(o3);
            *reinterpret_cast<unsigned*>(&H[i0]) = pk(h0, h1);
            *reinterpret_cast<unsigned*>(&H[i1]) = pk(h2, h3);
            *reinterpret_cast<unsigned*>(&L[i0]) = pk(bf_lo(o0, h0), bf_lo(o1, h1));
            *reinterpret_cast<unsigned*>(&L[i1]) = pk(bf_lo(o2, h2), bf_lo(o3, h3));
        }
    }
}

// ---------------- depthwise 5x5 (pad 2) + BN on g_yv -> g_pp ------------------
__global__ __launch_bounds__(256) void dw5_bn(
    const float* __restrict__ w_pe,
    const float* __restrict__ gg, const float* __restrict__ bb,
    const float* __restrict__ mm, const float* __restrict__ vv)
{
    const int bc = blockIdx.x;
    const int c  = bc & 255;
    const float* src = g_yv + bc * 4096;
    float* dst = g_pp + bc * 4096;

    __shared__ float tile[68][68];
    __shared__ float wk[25];
    const int t = threadIdx.x;

    for (int i = t; i < 68 * 68; i += 256) ((float*)tile)[i] = 0.f;
    if (t < 25) wk[t] = w_pe[c * 25 + t];
    __syncthreads();
    for (int i = t; i < 4096; i += 256) tile[(i >> 6) + 2][(i & 63) + 2] = src[i];
    __syncthreads();

    float s  = gg[c] * rsqrtf(vv[c] + BN_EPS);
    float bi = bb[c] - mm[c] * s;

    for (int i = t; i < 4096; i += 256) {
        int y = i >> 6, x = i & 63;
        float acc = 0.f;
#pragma unroll
        for (int ky = 0; ky < 5; ky++)
#pragma unroll
            for (int kx = 0; kx < 5; kx++)
                acc = fmaf(tile[y + ky][x + kx], wk[ky * 5 + kx], acc);
        dst[i] = acc * s + bi;
    }
}

// ================= flash attention: 128-thr CTA / 64-q tile (2 CTAs/SM) =======
#define TS 272
#define QH_OFF 0
#define QL_OFF 8704
#define BUF0   17408
#define BUFSZ  34816
#define FM_SMEM (BUF0 + 2 * BUFSZ)

__device__ __forceinline__ void kv_copy(unsigned base, int t,
    const __nv_bfloat16* Kh, const __nv_bfloat16* Kl,
    const __nv_bfloat16* Vh, const __nv_bfloat16* Vl, int m0)
{
#pragma unroll
    for (int c = t; c < 2048; c += 128) {
        int arr = c >> 9, d = (c >> 4) & 31, mb = c & 15;
        const __nv_bfloat16* s =
            (arr == 0 ? Kh : (arr == 1 ? Kl : (arr == 2 ? Vh : Vl))) + d * 4096 + m0 + mb * 8;
        cp_async16(base + arr * 8704 + d * TS + mb * 16, s);
    }
    cp_commit();
}

__global__ __launch_bounds__(128) void flash_mma()
{
    extern __shared__ char smbuf[];
    const unsigned sb = smem_u32(smbuf);
    const int t = threadIdx.x, lane = t & 31, w = t >> 5;   // w in [0,4)

    const int bh = blockIdx.y;
    const int b = bh >> 5, area = (bh >> 3) & 3, h = bh & 7;
    const int q0 = blockIdx.x * 64;

    const int qch = (b * 512 + h * 32) * 4096 + area * 1024;
    const int kch = (b * 512 + 256 + h * 32) * 4096 + area * 1024;
    const int vch = (b * 256 + h * 32) * 4096 + area * 1024;
    const __nv_bfloat16* Qh = g_qk_hi + qch + q0;
    const __nv_bfloat16* Ql = g_qk_lo + qch + q0;
    const __nv_bfloat16* Kh = g_qk_hi + kch;
    const __nv_bfloat16* Kl = g_qk_lo + kch;
    const __nv_bfloat16* Vh = g_v_hi + vch;
    const __nv_bfloat16* Vl = g_v_lo + vch;

    kv_copy(sb + BUF0, t, Kh, Kl, Vh, Vl, 0);

    // Q copy: 2 arrays x 32 d-rows x 64 q (16B chunks)
#pragma unroll
    for (int c = t; c < 512; c += 128) {
        int arr = c >> 8, d = (c >> 3) & 31, qb = c & 7;
        const __nv_bfloat16* s = (arr ? Ql : Qh) + d * 4096 + qb * 8;
        *reinterpret_cast<uint4*>(smbuf + (arr ? QL_OFF : QH_OFF) + d * TS + qb * 16) =
            *reinterpret_cast<const uint4*>(s);
    }
    __syncthreads();

    unsigned qa[2][2][4];
#pragma unroll
    for (int sp = 0; sp < 2; sp++)
#pragma unroll
        for (int s = 0; s < 2; s++) {
            unsigned drow = s * 16 + ((lane >> 4) & 1) * 8 + (lane & 7);
            unsigned col  = (unsigned)w * 32 + ((lane >> 3) & 1) * 16;
            ldsm_x4t(qa[sp][s][0], qa[sp][s][1], qa[sp][s][2], qa[sp][s][3],
                     sb + (sp ? QL_OFF : QH_OFF) + drow * TS + col);
        }

    float Oacc[4][4];
#pragma unroll
    for (int dn = 0; dn < 4; dn++)
#pragma unroll
        for (int c = 0; c < 4; c++) Oacc[dn][c] = 0.f;
    float mr0 = -1e30f, mr1 = -1e30f, lr0 = 0.f, lr1 = 0.f;

    for (int kt = 0; kt < 8; kt++) {
        cp_wait_all();
        __syncthreads();
        if (kt < 7)
            kv_copy(sb + BUF0 + ((kt + 1) & 1) * BUFSZ, t, Kh, Kl, Vh, Vl, (kt + 1) * 128);
        const unsigned kb = sb + BUF0 + (kt & 1) * BUFSZ;

        float S[16][4];
#pragma unroll
        for (int j = 0; j < 16; j++) {
            unsigned kh0, kh1, kh2, kh3, kl0, kl1, kl2, kl3;
            ldsm_x4t(kh0, kh1, kh2, kh3, kb + lane * TS + j * 16);
            ldsm_x4t(kl0, kl1, kl2, kl3, kb + 8704 + lane * TS + j * 16);
            float a0 = 0.f, a1 = 0.f, a2 = 0.f, a3 = 0.f;
            float b0 = 0.f, b1 = 0.f, b2 = 0.f, b3 = 0.f;
            mma16816(a0, a1, a2, a3, qa[0][0][0], qa[0][0][1], qa[0][0][2], qa[0][0][3], kh0, kh1);
            mma16816(a0, a1, a2, a3, qa[0][1][0], qa[0][1][1], qa[0][1][2], qa[0][1][3], kh2, kh3);
            mma16816(b0, b1, b2, b3, qa[0][0][0], qa[0][0][1], qa[0][0][2], qa[0][0][3], kl0, kl1);
            mma16816(b0, b1, b2, b3, qa[0][1][0], qa[0][1][1], qa[0][1][2], qa[0][1][3], kl2, kl3);
            mma16816(b0, b1, b2, b3, qa[1][0][0], qa[1][0][1], qa[1][0][2], qa[1][0][3], kh0, kh1);
            mma16816(b0, b1, b2, b3, qa[1][1][0], qa[1][1][1], qa[1][1][2], qa[1][1][3], kh2, kh3);
            S[j][0] = a0 + b0; S[j][1] = a1 + b1; S[j][2] = a2 + b2; S[j][3] = a3 + b3;
        }

        float mx0 = -1e30f, mx1 = -1e30f;
#pragma unroll
        for (int j = 0; j < 16; j++) {
            mx0 = fmaxf(mx0, fmaxf(S[j][0], S[j][1]));
            mx1 = fmaxf(mx1, fmaxf(S[j][2], S[j][3]));
        }
        mx0 = fmaxf(mx0, __shfl_xor_sync(0xFFFFFFFFu, mx0, 1));
        mx0 = fmaxf(mx0, __shfl_xor_sync(0xFFFFFFFFu, mx0, 2));
        mx1 = fmaxf(mx1, __shfl_xor_sync(0xFFFFFFFFu, mx1, 1));
        mx1 = fmaxf(mx1, __shfl_xor_sync(0xFFFFFFFFu, mx1, 2));
        float nm0 = fmaxf(mr0, mx0), nm1 = fmaxf(mr1, mx1);
        float be0 = __expf(mr0 - nm0), be1 = __expf(mr1 - nm1);
        float lt0 = 0.f, lt1 = 0.f;
#pragma unroll
        for (int j = 0; j < 16; j++) {
            S[j][0] = __expf(S[j][0] - nm0); lt0 += S[j][0];
            S[j][1] = __expf(S[j][1] - nm0); lt0 += S[j][1];
            S[j][2] = __expf(S[j][2] - nm1); lt1 += S[j][2];
            S[j][3] = __expf(S[j][3] - nm1); lt1 += S[j][3];
        }
        lt0 += __shfl_xor_sync(0xFFFFFFFFu, lt0, 1);
        lt0 += __shfl_xor_sync(0xFFFFFFFFu, lt0, 2);
        lt1 += __shfl_xor_sync(0xFFFFFFFFu, lt1, 1);
        lt1 += __shfl_xor_sync(0xFFFFFFFFu, lt1, 2);
        lr0 = lr0 * be0 + lt0; lr1 = lr1 * be1 + lt1;
        mr0 = nm0; mr1 = nm1;
#pragma unroll
        for (int dn = 0; dn < 4; dn++) {
            Oacc[dn][0] *= be0; Oacc[dn][1] *= be0;
            Oacc[dn][2] *= be1; Oacc[dn][3] *= be1;
        }

#pragma unroll
        for (int tt = 0; tt < 8; tt++) {
            unsigned ah[4], al[4];
            {
                unsigned short h0 = bf_hi(S[2*tt][0]),   h1 = bf_hi(S[2*tt][1]);
                unsigned short h2 = bf_hi(S[2*tt][2]),   h3 = bf_hi(S[2*tt][3]);
                unsigned short h4 = bf_hi(S[2*tt+1][0]), h5 = bf_hi(S[2*tt+1][1]);
                unsigned short h6 = bf_hi(S[2*tt+1][2]), h7 = bf_hi(S[2*tt+1][3]);
                ah[0] = pk(h0, h1); ah[1] = pk(h2, h3);
                ah[2] = pk(h4, h5); ah[3] = pk(h6, h7);
                al[0] = pk(bf_lo(S[2*tt][0], h0),   bf_lo(S[2*tt][1], h1));
                al[1] = pk(bf_lo(S[2*tt][2], h2),   bf_lo(S[2*tt][3], h3));
                al[2] = pk(bf_lo(S[2*tt+1][0], h4), bf_lo(S[2*tt+1][1], h5));
                al[3] = pk(bf_lo(S[2*tt+1][2], h6), bf_lo(S[2*tt+1][3], h7));
            }
#pragma unroll
            for (int p = 0; p < 2; p++) {
                unsigned drow = (unsigned)p * 16 + ((lane >> 4) & 1) * 8 + (lane & 7);
                unsigned colb = (unsigned)tt * 32 + ((lane >> 3) & 1) * 16;
                unsigned vh0, vh1, vh2, vh3, vl0, vl1, vl2, vl3;
                ldsm_x4(vh0, vh1, vh2, vh3, kb + 17408 + drow * TS + colb);
                ldsm_x4(vl0, vl1, vl2, vl3, kb + 26112 + drow * TS + colb);
                int d0 = p * 2, d1 = p * 2 + 1;
                mma16816(Oacc[d0][0], Oacc[d0][1], Oacc[d0][2], Oacc[d0][3],
                         ah[0], ah[1], ah[2], ah[3], vh0, vh1);
                mma16816(Oacc[d0][0], Oacc[d0][1], Oacc[d0][2], Oacc[d0][3],
                         ah[0], ah[1], ah[2], ah[3], vl0, vl1);
                mma16816(Oacc[d0][0], Oacc[d0][1], Oacc[d0][2], Oacc[d0][3],
                         al[0], al[1], al[2], al[3], vh0, vh1);
                mma16816(Oacc[d1][0], Oacc[d1][1], Oacc[d1][2], Oacc[d1][3],
                         ah[0], ah[1], ah[2], ah[3], vh2, vh3);
                mma16816(Oacc[d1][0], Oacc[d1][1], Oacc[d1][2], Oacc[d1][3],
                         ah[0], ah[1], ah[2], ah[3], vl2, vl3);
                mma16816(Oacc[d1][0], Oacc[d1][1], Oacc[d1][2], Oacc[d1][3],
                         al[0], al[1], al[2], al[3], vh2, vh3);
            }
        }
    }

    // ---- normalize + stage O [q][d] (stride 33 floats) in Q smem region ----
    __syncthreads();
    {
        float inv0 = 1.f / lr0, inv1 = 1.f / lr1;
        int r = w * 16 + (lane >> 2);
        int dc = (lane & 3) * 2;
        float* Os = (float*)(smbuf);
#pragma unroll
        for (int dn = 0; dn < 4; dn++) {
            int d = dn * 8 + dc;
            Os[r * 33 + d]           = Oacc[dn][0] * inv0;
            Os[r * 33 + d + 1]       = Oacc[dn][1] * inv0;
            Os[(r + 8) * 33 + d]     = Oacc[dn][2] * inv1;
            Os[(r + 8) * 33 + d + 1] = Oacc[dn][3] * inv1;
        }
    }
    __syncthreads();

    float* Op = g_o + (b * 256 + h * 32) * 4096 + area * 1024;
    const float* Os = (const float*)(smbuf);
    for (int i = t * 4; i < 2048; i += 512) {
        int d = i >> 6, q = i & 63;
        float4 o;
        o.x = Os[(q + 0) * 33 + d];
        o.y = Os[(q + 1) * 33 + d];
        o.z = Os[(q + 2) * 33 + d];
        o.w = Os[(q + 3) * 33 + d];
        *(float4*)&Op[d * 4096 + q0 + q] = o;
    }
}

// ---------------- launch ------------------------------------------------------
extern "C" void kernel_launch(void* const* d_in, const int* in_sizes, int n_in,
                              void* d_out, int out_size)
{
    const float *x, *w_qk, *w_v, *w_pe, *w_proj;
    const float *qk_g, *qk_b, *qk_m, *qk_v;
    const float *v_g, *v_b, *v_m, *v_v;
    const float *pe_g, *pe_b, *pe_m, *pe_v;
    const float *pr_g, *pr_b, *pr_m, *pr_v;

    x = (const float*)d_in[0];
    w_qk = (const float*)d_in[1];
    if (in_sizes[2] == 512) {
        qk_g = (const float*)d_in[2];  qk_b = (const float*)d_in[3];
        qk_m = (const float*)d_in[4];  qk_v = (const float*)d_in[5];
        w_v  = (const float*)d_in[6];
        v_g  = (const float*)d_in[7];  v_b  = (const float*)d_in[8];
        v_m  = (const float*)d_in[9];  v_v  = (const float*)d_in[10];
        w_pe = (const float*)d_in[11];
        pe_g = (const float*)d_in[12]; pe_b = (const float*)d_in[13];
        pe_m = (const float*)d_in[14]; pe_v = (const float*)d_in[15];
        w_proj = (const float*)d_in[16];
        pr_g = (const float*)d_in[17]; pr_b = (const float*)d_in[18];
        pr_m = (const float*)d_in[19]; pr_v = (const float*)d_in[20];
    } else {
        w_v    = (const float*)d_in[2];
        w_pe   = (const float*)d_in[3];
        w_proj = (const float*)d_in[4];
        qk_g = (const float*)d_in[5];  qk_b = (const float*)d_in[6];
        qk_m = (const float*)d_in[7];  qk_v = (const float*)d_in[8];
        v_g  = (const float*)d_in[9];  v_b  = (const float*)d_in[10];
        v_m  = (const float*)d_in[11]; v_v  = (const float*)d_in[12];
        pe_g = (const float*)d_in[13]; pe_b = (const float*)d_in[14];
        pe_m = (const float*)d_in[15]; pe_v = (const float*)d_in[16];
        pr_g = (const float*)d_in[17]; pr_b = (const float*)d_in[18];
        pr_m = (const float*)d_in[19]; pr_v = (const float*)d_in[20];
    }
    float* out = (float*)d_out;

    cudaFuncSetAttribute(flash_mma, cudaFuncAttributeMaxDynamicSharedMemorySize, FM_SMEM);

    conv_tc<16><<<dim3(32, 4, 2), 256>>>(w_qk, x, nullptr,
                                         qk_g, qk_b, qk_m, qk_v, 512, 0);
    conv_tc<8><<<dim3(64, 2, 2), 256>>>(w_v, x, nullptr,
                                        v_g, v_b, v_m, v_v, 256, 1);
    dw5_bn<<<512, 256>>>(w_pe, pe_g, pe_b, pe_m, pe_v);
    flash_mma<<<dim3(16, 64), 128, FM_SMEM>>>();
    conv_tc<8><<<dim3(64, 2, 2), 256>>>(w_proj, nullptr, out,
                                        pr_g, pr_b, pr_m, pr_v, 256, 2);
}

// round 13
// speedup vs baseline: 1.9723x; 1.1966x over previous
#include <cuda_runtime.h>
#include <cuda_bf16.h>

#define BN_EPS 1e-5f
#define SC 0.17677669529663687f

// ---------------- scratch (device globals; no allocation allowed) -------------
__device__ float g_yv [2 * 256 * 4096];                 // v conv fp32 (for dw)
__device__ float g_pp [2 * 256 * 4096];                 // depthwise+BN
__device__ float g_o  [2 * 256 * 4096];                 // attention output
__device__ __nv_bfloat16 g_qk_hi[2 * 512 * 4096];
__device__ __nv_bfloat16 g_qk_lo[2 * 512 * 4096];
__device__ __nv_bfloat16 g_v_hi [2 * 256 * 4096];
__device__ __nv_bfloat16 g_v_lo [2 * 256 * 4096];
__device__ __nv_bfloat16 g_xh  [2 * 256 * 4096];        // x split
__device__ __nv_bfloat16 g_xl  [2 * 256 * 4096];
__device__ __nv_bfloat16 g_oph [2 * 256 * 4096];        // (g_o+g_pp) split
__device__ __nv_bfloat16 g_opl [2 * 256 * 4096];
__device__ __nv_bfloat16 g_wqkt_h[256 * 512], g_wqkt_l[256 * 512];   // [k][m]
__device__ __nv_bfloat16 g_wvt_h [256 * 256], g_wvt_l [256 * 256];
__device__ __nv_bfloat16 g_wprt_h[256 * 256], g_wprt_l[256 * 256];

__device__ __forceinline__ unsigned short bf_hi(float x) {
    return __bfloat16_as_ushort(__float2bfloat16(x));
}
__device__ __forceinline__ unsigned short bf_lo(float x, unsigned short h) {
    __nv_bfloat16 hb = __ushort_as_bfloat16(h);
    return __bfloat16_as_ushort(__float2bfloat16(x - __bfloat162float(hb)));
}
__device__ __forceinline__ unsigned pk(unsigned short a, unsigned short b) {
    return ((unsigned)b << 16) | (unsigned)a;
}
__device__ __forceinline__ unsigned smem_u32(const void* p) {
    unsigned a;
    asm("{ .reg .u64 t; cvta.to.shared.u64 t, %1; cvt.u32.u64 %0, t; }" : "=r"(a) : "l"(p));
    return a;
}
__device__ __forceinline__ void ldsm_x4(unsigned& r0, unsigned& r1, unsigned& r2, unsigned& r3,
                                        unsigned addr) {
    asm volatile("ldmatrix.sync.aligned.m8n8.x4.shared.b16 {%0,%1,%2,%3}, [%4];"
                 : "=r"(r0), "=r"(r1), "=r"(r2), "=r"(r3) : "r"(addr));
}
__device__ __forceinline__ void ldsm_x4t(unsigned& r0, unsigned& r1, unsigned& r2, unsigned& r3,
                                         unsigned addr) {
    asm volatile("ldmatrix.sync.aligned.m8n8.x4.trans.shared.b16 {%0,%1,%2,%3}, [%4];"
                 : "=r"(r0), "=r"(r1), "=r"(r2), "=r"(r3) : "r"(addr));
}
__device__ __forceinline__ void mma16816(float& c0, float& c1, float& c2, float& c3,
                                         unsigned a0, unsigned a1, unsigned a2, unsigned a3,
                                         unsigned b0, unsigned b1) {
    asm volatile(
        "mma.sync.aligned.m16n8k16.row.col.f32.bf16.bf16.f32 "
        "{%0,%1,%2,%3}, {%4,%5,%6,%7}, {%8,%9}, {%0,%1,%2,%3};"
        : "+f"(c0), "+f"(c1), "+f"(c2), "+f"(c3)
        : "r"(a0), "r"(a1), "r"(a2), "r"(a3), "r"(b0), "r"(b1));
}
__device__ __forceinline__ void cp_async16(unsigned dst, const void* src) {
    asm volatile("cp.async.cg.shared.global [%0], [%1], 16;" :: "r"(dst), "l"(src) : "memory");
}
__device__ __forceinline__ void cp_commit() {
    asm volatile("cp.async.commit_group;" ::: "memory");
}
__device__ __forceinline__ void cp_wait_all() {
    asm volatile("cp.async.wait_group 0;" ::: "memory");
}

// ---------------- prep kernels -------------------------------------------------
__global__ __launch_bounds__(256) void prep_split(
    const float* __restrict__ a, const float* __restrict__ b,
    __nv_bfloat16* __restrict__ h, __nv_bfloat16* __restrict__ l, int n)
{
    int i = (blockIdx.x * 256 + threadIdx.x) * 4;
    if (i >= n) return;
    float4 v = *reinterpret_cast<const float4*>(&a[i]);
    if (b) {
        float4 v2 = *reinterpret_cast<const float4*>(&b[i]);
        v.x += v2.x; v.y += v2.y; v.z += v2.z; v.w += v2.w;
    }
    float va[4] = {v.x, v.y, v.z, v.w};
    unsigned short hh[4], ll[4];
#pragma unroll
    for (int j = 0; j < 4; j++) { hh[j] = bf_hi(va[j]); ll[j] = bf_lo(va[j], hh[j]); }
    *reinterpret_cast<uint2*>(&h[i]) = make_uint2(pk(hh[0], hh[1]), pk(hh[2], hh[3]));
    *reinterpret_cast<uint2*>(&l[i]) = make_uint2(pk(ll[0], ll[1]), pk(ll[2], ll[3]));
}

__global__ __launch_bounds__(256) void prep_wt(
    const float* __restrict__ W, __nv_bfloat16* __restrict__ th,
    __nv_bfloat16* __restrict__ tl, int M, int K, int sc_rows)
{
    int idx = blockIdx.x * 256 + threadIdx.x;      // idx = k*M + m
    if (idx >= M * K) return;
    int k = idx / M, m = idx - k * M;
    float v = W[m * K + k];
    if (m < sc_rows) v *= SC;
    unsigned short h = bf_hi(v);
    th[idx] = __ushort_as_bfloat16(h);
    tl[idx] = __ushort_as_bfloat16(bf_lo(v, h));
}

// =============== all-bf16 conv1x1 + BN (cp.async pipelined) ===================
// Y[b][m][n] = BN(sum_k W[m][k] X[b][k][n]); Wt=[k][m] hi/lo, X=[k][n] hi/lo.
// CTA: 64m x 128n, 128 threads, K chunks of 32, double buffered (dynamic smem).
#define BW_L 4608
#define BX_H 9216
#define BX_L 17920
#define BUFB 26624
#define CB_SMEM (2 * BUFB)

__global__ __launch_bounds__(128) void conv_bf(
    const __nv_bfloat16* __restrict__ Wth, const __nv_bfloat16* __restrict__ Wtl,
    const __nv_bfloat16* __restrict__ Xh0, const __nv_bfloat16* __restrict__ Xl0,
    float* __restrict__ dout,
    const float* __restrict__ gg, const float* __restrict__ bb,
    const float* __restrict__ mm, const float* __restrict__ vv,
    int M, int out_mode)
{
    extern __shared__ char csm[];
    const unsigned sbc = smem_u32(csm);
    const int N = 4096;
    const int t = threadIdx.x, lane = t & 31, w = t >> 5;
    const int b = blockIdx.z;
    const int m0 = blockIdx.y * 64, n0 = blockIdx.x * 128;

    const __nv_bfloat16* Xh = Xh0 + b * 256 * 4096;
    const __nv_bfloat16* Xl = Xl0 + b * 256 * 4096;

    auto chunk_copy = [&](unsigned base, int k0) {
#pragma unroll
        for (int c = t; c < 1536; c += 128) {
            if (c < 512) {
                int arr = c >> 8, rem = c & 255, r = rem >> 3, c16 = rem & 7;
                const __nv_bfloat16* s = (arr ? Wtl : Wth) + (k0 + r) * M + m0 + c16 * 8;
                cp_async16(base + arr * BW_L + r * 144 + c16 * 16, s);
            } else {
                int c2 = c - 512;
                int arr = c2 >> 9, rem = c2 & 511, r = rem >> 4, c16 = rem & 15;
                const __nv_bfloat16* s = (arr ? Xl : Xh) + (k0 + r) * N + n0 + c16 * 8;
                cp_async16(base + BX_H + arr * (BX_L - BX_H) + r * 272 + c16 * 16, s);
            }
        }
        cp_commit();
    };

    chunk_copy(sbc, 0);

    float S[16][4];
#pragma unroll
    for (int j = 0; j < 16; j++)
#pragma unroll
        for (int c = 0; c < 4; c++) S[j][c] = 0.f;

    for (int c0 = 0; c0 < 8; c0++) {
        cp_wait_all();
        __syncthreads();
        if (c0 < 7) chunk_copy(sbc + ((c0 + 1) & 1) * BUFB, (c0 + 1) * 32);
        const unsigned bbuf = sbc + (c0 & 1) * BUFB;

        unsigned wa_[2][2][4];
#pragma unroll
        for (int sp = 0; sp < 2; sp++)
#pragma unroll
            for (int s = 0; s < 2; s++) {
                unsigned drow = s * 16 + ((lane >> 4) & 1) * 8 + (lane & 7);
                unsigned col  = (unsigned)w * 32 + ((lane >> 3) & 1) * 16;
                ldsm_x4t(wa_[sp][s][0], wa_[sp][s][1], wa_[sp][s][2], wa_[sp][s][3],
                         bbuf + sp * BW_L + drow * 144 + col);
            }
#pragma unroll
        for (int j = 0; j < 16; j++) {
            unsigned xh0, xh1, xh2, xh3, xl0, xl1, xl2, xl3;
            ldsm_x4t(xh0, xh1, xh2, xh3, bbuf + BX_H + lane * 272 + j * 16);
            ldsm_x4t(xl0, xl1, xl2, xl3, bbuf + BX_L + lane * 272 + j * 16);
            mma16816(S[j][0], S[j][1], S[j][2], S[j][3],
                     wa_[0][0][0], wa_[0][0][1], wa_[0][0][2], wa_[0][0][3], xh0, xh1);
            mma16816(S[j][0], S[j][1], S[j][2], S[j][3],
                     wa_[0][1][0], wa_[0][1][1], wa_[0][1][2], wa_[0][1][3], xh2, xh3);
            mma16816(S[j][0], S[j][1], S[j][2], S[j][3],
                     wa_[0][0][0], wa_[0][0][1], wa_[0][0][2], wa_[0][0][3], xl0, xl1);
            mma16816(S[j][0], S[j][1], S[j][2], S[j][3],
                     wa_[0][1][0], wa_[0][1][1], wa_[0][1][2], wa_[0][1][3], xl2, xl3);
            mma16816(S[j][0], S[j][1], S[j][2], S[j][3],
                     wa_[1][0][0], wa_[1][0][1], wa_[1][0][2], wa_[1][0][3], xh0, xh1);
            mma16816(S[j][0], S[j][1], S[j][2], S[j][3],
                     wa_[1][1][0], wa_[1][1][1], wa_[1][1][2], wa_[1][1][3], xh2, xh3);
        }
    }

    // ---- epilogue: BN + writes ----
    const int r0 = m0 + w * 16 + (lane >> 2);
    const int r1 = r0 + 8;
    float s0 = gg[r0] * rsqrtf(vv[r0] + BN_EPS);
    float bi0 = bb[r0] - mm[r0] * s0;
    float s1 = gg[r1] * rsqrtf(vv[r1] + BN_EPS);
    float bi1 = bb[r1] - mm[r1] * s1;
    // qk: W pre-scaled by SC for Q rows, so S = SC*conv. Output = SC*(conv*s+bi)
    // = S*s + SC*bi -> scale bias only.
    if (out_mode == 0 && r0 < 256) { bi0 *= SC; }
    if (out_mode == 0 && r1 < 256) { bi1 *= SC; }

#pragma unroll
    for (int j = 0; j < 16; j++) {
        int n = n0 + j * 8 + (lane & 3) * 2;
        float o0 = S[j][0] * s0 + bi0, o1 = S[j][1] * s0 + bi0;
        float o2 = S[j][2] * s1 + bi1, o3 = S[j][3] * s1 + bi1;
        long i0 = (long)b * M * 4096 + (long)r0 * 4096 + n;
        long i1 = (long)b * M * 4096 + (long)r1 * 4096 + n;
        if (out_mode == 2) {
            *reinterpret_cast<float2*>(&dout[i0]) = make_float2(o0, o1);
            *reinterpret_cast<float2*>(&dout[i1]) = make_float2(o2, o3);
        } else {
            if (out_mode == 1) {
                *reinterpret_cast<float2*>(&g_yv[i0]) = make_float2(o0, o1);
                *reinterpret_cast<float2*>(&g_yv[i1]) = make_float2(o2, o3);
            }
            __nv_bfloat16* H = (out_mode == 0 ? g_qk_hi : g_v_hi);
            __nv_bfloat16* L = (out_mode == 0 ? g_qk_lo : g_v_lo);
            unsigned short h0 = bf_hi(o0), h1 = bf_hi(o1);
            unsigned short h2 = bf_hi(o2), h3 = bf_hi(o3);
            *reinterpret_cast<unsigned*>(&H[i0]) = pk(h0, h1);
            *reinterpret_cast<unsigned*>(&H[i1]) = pk(h2, h3);
            *reinterpret_cast<unsigned*>(&L[i0]) = pk(bf_lo(o0, h0), bf_lo(o1, h1));
            *reinterpret_cast<unsigned*>(&L[i1]) = pk(bf_lo(o2, h2), bf_lo(o3, h3));
        }
    }
}

// ---------------- depthwise 5x5 (pad 2) + BN on g_yv -> g_pp ------------------
__global__ __launch_bounds__(256) void dw5_bn(
    const float* __restrict__ w_pe,
    const float* __restrict__ gg, const float* __restrict__ bb,
    const float* __restrict__ mm, const float* __restrict__ vv)
{
    const int bc = blockIdx.x;
    const int c  = bc & 255;
    const float* src = g_yv + bc * 4096;
    float* dst = g_pp + bc * 4096;

    __shared__ float tile[68][68];
    __shared__ float wk[25];
    const int t = threadIdx.x;

    for (int i = t; i < 68 * 68; i += 256) ((float*)tile)[i] = 0.f;
    if (t < 25) wk[t] = w_pe[c * 25 + t];
    __syncthreads();
    for (int i = t; i < 4096; i += 256) tile[(i >> 6) + 2][(i & 63) + 2] = src[i];
    __syncthreads();

    float s  = gg[c] * rsqrtf(vv[c] + BN_EPS);
    float bi = bb[c] - mm[c] * s;

    for (int i = t; i < 4096; i += 256) {
        int y = i >> 6, x = i & 63;
        float acc = 0.f;
#pragma unroll
        for (int ky = 0; ky < 5; ky++)
#pragma unroll
            for (int kx = 0; kx < 5; kx++)
                acc = fmaf(tile[y + ky][x + kx], wk[ky * 5 + kx], acc);
        dst[i] = acc * s + bi;
    }
}

// ================= flash attention (unchanged) ================================
#define TS 272
#define QH_OFF 0
#define QL_OFF 8704
#define BUF0   17408
#define BUFSZ  34816
#define FM_SMEM (BUF0 + 2 * BUFSZ)

__device__ __forceinline__ void kv_copy(unsigned base, int t,
    const __nv_bfloat16* Kh, const __nv_bfloat16* Kl,
    const __nv_bfloat16* Vh, const __nv_bfloat16* Vl, int m0)
{
#pragma unroll
    for (int c = t; c < 2048; c += 128) {
        int arr = c >> 9, d = (c >> 4) & 31, mb = c & 15;
        const __nv_bfloat16* s =
            (arr == 0 ? Kh : (arr == 1 ? Kl : (arr == 2 ? Vh : Vl))) + d * 4096 + m0 + mb * 8;
        cp_async16(base + arr * 8704 + d * TS + mb * 16, s);
    }
    cp_commit();
}

__global__ __launch_bounds__(128) void flash_mma()
{
    extern __shared__ char smbuf[];
    const unsigned sb = smem_u32(smbuf);
    const int t = threadIdx.x, lane = t & 31, w = t >> 5;

    const int bh = blockIdx.y;
    const int b = bh >> 5, area = (bh >> 3) & 3, h = bh & 7;
    const int q0 = blockIdx.x * 64;

    const int qch = (b * 512 + h * 32) * 4096 + area * 1024;
    const int kch = (b * 512 + 256 + h * 32) * 4096 + area * 1024;
    const int vch = (b * 256 + h * 32) * 4096 + area * 1024;
    const __nv_bfloat16* Qh = g_qk_hi + qch + q0;
    const __nv_bfloat16* Ql = g_qk_lo + qch + q0;
    const __nv_bfloat16* Kh = g_qk_hi + kch;
    const __nv_bfloat16* Kl = g_qk_lo + kch;
    const __nv_bfloat16* Vh = g_v_hi + vch;
    const __nv_bfloat16* Vl = g_v_lo + vch;

    kv_copy(sb + BUF0, t, Kh, Kl, Vh, Vl, 0);

#pragma unroll
    for (int c = t; c < 512; c += 128) {
        int arr = c >> 8, d = (c >> 3) & 31, qb = c & 7;
        const __nv_bfloat16* s = (arr ? Ql : Qh) + d * 4096 + qb * 8;
        *reinterpret_cast<uint4*>(smbuf + (arr ? QL_OFF : QH_OFF) + d * TS + qb * 16) =
            *reinterpret_cast<const uint4*>(s);
    }
    __syncthreads();

    unsigned qa[2][2][4];
#pragma unroll
    for (int sp = 0; sp < 2; sp++)
#pragma unroll
        for (int s = 0; s < 2; s++) {
            unsigned drow = s * 16 + ((lane >> 4) & 1) * 8 + (lane & 7);
            unsigned col  = (unsigned)w * 32 + ((lane >> 3) & 1) * 16;
            ldsm_x4t(qa[sp][s][0], qa[sp][s][1], qa[sp][s][2], qa[sp][s][3],
                     sb + (sp ? QL_OFF : QH_OFF) + drow * TS + col);
        }

    float Oacc[4][4];
#pragma unroll
    for (int dn = 0; dn < 4; dn++)
#pragma unroll
        for (int c = 0; c < 4; c++) Oacc[dn][c] = 0.f;
    float mr0 = -1e30f, mr1 = -1e30f, lr0 = 0.f, lr1 = 0.f;

    for (int kt = 0; kt < 8; kt++) {
        cp_wait_all();
        __syncthreads();
        if (kt < 7)
            kv_copy(sb + BUF0 + ((kt + 1) & 1) * BUFSZ, t, Kh, Kl, Vh, Vl, (kt + 1) * 128);
        const unsigned kb = sb + BUF0 + (kt & 1) * BUFSZ;

        float S[16][4];
#pragma unroll
        for (int j = 0; j < 16; j++) {
            unsigned kh0, kh1, kh2, kh3, kl0, kl1, kl2, kl3;
            ldsm_x4t(kh0, kh1, kh2, kh3, kb + lane * TS + j * 16);
            ldsm_x4t(kl0, kl1, kl2, kl3, kb + 8704 + lane * TS + j * 16);
            float a0 = 0.f, a1 = 0.f, a2 = 0.f, a3 = 0.f;
            float b0 = 0.f, b1 = 0.f, b2 = 0.f, b3 = 0.f;
            mma16816(a0, a1, a2, a3, qa[0][0][0], qa[0][0][1], qa[0][0][2], qa[0][0][3], kh0, kh1);
            mma16816(a0, a1, a2, a3, qa[0][1][0], qa[0][1][1], qa[0][1][2], qa[0][1][3], kh2, kh3);
            mma16816(b0, b1, b2, b3, qa[0][0][0], qa[0][0][1], qa[0][0][2], qa[0][0][3], kl0, kl1);
            mma16816(b0, b1, b2, b3, qa[0][1][0], qa[0][1][1], qa[0][1][2], qa[0][1][3], kl2, kl3);
            mma16816(b0, b1, b2, b3, qa[1][0][0], qa[1][0][1], qa[1][0][2], qa[1][0][3], kh0, kh1);
            mma16816(b0, b1, b2, b3, qa[1][1][0], qa[1][1][1], qa[1][1][2], qa[1][1][3], kh2, kh3);
            S[j][0] = a0 + b0; S[j][1] = a1 + b1; S[j][2] = a2 + b2; S[j][3] = a3 + b3;
        }

        float mx0 = -1e30f, mx1 = -1e30f;
#pragma unroll
        for (int j = 0; j < 16; j++) {
            mx0 = fmaxf(mx0, fmaxf(S[j][0], S[j][1]));
            mx1 = fmaxf(mx1, fmaxf(S[j][2], S[j][3]));
        }
        mx0 = fmaxf(mx0, __shfl_xor_sync(0xFFFFFFFFu, mx0, 1));
        mx0 = fmaxf(mx0, __shfl_xor_sync(0xFFFFFFFFu, mx0, 2));
        mx1 = fmaxf(mx1, __shfl_xor_sync(0xFFFFFFFFu, mx1, 1));
        mx1 = fmaxf(mx1, __shfl_xor_sync(0xFFFFFFFFu, mx1, 2));
        float nm0 = fmaxf(mr0, mx0), nm1 = fmaxf(mr1, mx1);
        float be0 = __expf(mr0 - nm0), be1 = __expf(mr1 - nm1);
        float lt0 = 0.f, lt1 = 0.f;
#pragma unroll
        for (int j = 0; j < 16; j++) {
            S[j][0] = __expf(S[j][0] - nm0); lt0 += S[j][0];
            S[j][1] = __expf(S[j][1] - nm0); lt0 += S[j][1];
            S[j][2] = __expf(S[j][2] - nm1); lt1 += S[j][2];
            S[j][3] = __expf(S[j][3] - nm1); lt1 += S[j][3];
        }
        lt0 += __shfl_xor_sync(0xFFFFFFFFu, lt0, 1);
        lt0 += __shfl_xor_sync(0xFFFFFFFFu, lt0, 2);
        lt1 += __shfl_xor_sync(0xFFFFFFFFu, lt1, 1);
        lt1 += __shfl_xor_sync(0xFFFFFFFFu, lt1, 2);
        lr0 = lr0 * be0 + lt0; lr1 = lr1 * be1 + lt1;
        mr0 = nm0; mr1 = nm1;
#pragma unroll
        for (int dn = 0; dn < 4; dn++) {
            Oacc[dn][0] *= be0; Oacc[dn][1] *= be0;
            Oacc[dn][2] *= be1; Oacc[dn][3] *= be1;
        }

#pragma unroll
        for (int tt = 0; tt < 8; tt++) {
            unsigned ah[4], al[4];
            {
                unsigned short h0 = bf_hi(S[2*tt][0]),   h1 = bf_hi(S[2*tt][1]);
                unsigned short h2 = bf_hi(S[2*tt][2]),   h3 = bf_hi(S[2*tt][3]);
                unsigned short h4 = bf_hi(S[2*tt+1][0]), h5 = bf_hi(S[2*tt+1][1]);
                unsigned short h6 = bf_hi(S[2*tt+1][2]), h7 = bf_hi(S[2*tt+1][3]);
                ah[0] = pk(h0, h1); ah[1] = pk(h2, h3);
                ah[2] = pk(h4, h5); ah[3] = pk(h6, h7);
                al[0] = pk(bf_lo(S[2*tt][0], h0),   bf_lo(S[2*tt][1], h1));
                al[1] = pk(bf_lo(S[2*tt][2], h2),   bf_lo(S[2*tt][3], h3));
                al[2] = pk(bf_lo(S[2*tt+1][0], h4), bf_lo(S[2*tt+1][1], h5));
                al[3] = pk(bf_lo(S[2*tt+1][2], h6), bf_lo(S[2*tt+1][3], h7));
            }
#pragma unroll
            for (int p = 0; p < 2; p++) {
                unsigned drow = (unsigned)p * 16 + ((lane >> 4) & 1) * 8 + (lane & 7);
                unsigned colb = (unsigned)tt * 32 + ((lane >> 3) & 1) * 16;
                unsigned vh0, vh1, vh2, vh3, vl0, vl1, vl2, vl3;
                ldsm_x4(vh0, vh1, vh2, vh3, kb + 17408 + drow * TS + colb);
                ldsm_x4(vl0, vl1, vl2, vl3, kb + 26112 + drow * TS + colb);
                int d0 = p * 2, d1 = p * 2 + 1;
                mma16816(Oacc[d0][0], Oacc[d0][1], Oacc[d0][2], Oacc[d0][3],
                         ah[0], ah[1], ah[2], ah[3], vh0, vh1);
                mma16816(Oacc[d0][0], Oacc[d0][1], Oacc[d0][2], Oacc[d0][3],
                         ah[0], ah[1], ah[2], ah[3], vl0, vl1);
                mma16816(Oacc[d0][0], Oacc[d0][1], Oacc[d0][2], Oacc[d0][3],
                         al[0], al[1], al[2], al[3], vh0, vh1);
                mma16816(Oacc[d1][0], Oacc[d1][1], Oacc[d1][2], Oacc[d1][3],
                         ah[0], ah[1], ah[2], ah[3], vh2, vh3);
                mma16816(Oacc[d1][0], Oacc[d1][1], Oacc[d1][2], Oacc[d1][3],
                         ah[0], ah[1], ah[2], ah[3], vl2, vl3);
                mma16816(Oacc[d1][0], Oacc[d1][1], Oacc[d1][2], Oacc[d1][3],
                         al[0], al[1], al[2], al[3], vh2, vh3);
            }
        }
    }

    __syncthreads();
    {
        float inv0 = 1.f / lr0, inv1 = 1.f / lr1;
        int r = w * 16 + (lane >> 2);
        int dc = (lane & 3) * 2;
        float* Os = (float*)(smbuf);
#pragma unroll
        for (int dn = 0; dn < 4; dn++) {
            int d = dn * 8 + dc;
            Os[r * 33 + d]           = Oacc[dn][0] * inv0;
            Os[r * 33 + d + 1]       = Oacc[dn][1] * inv0;
            Os[(r + 8) * 33 + d]     = Oacc[dn][2] * inv1;
            Os[(r + 8) * 33 + d + 1] = Oacc[dn][3] * inv1;
        }
    }
    __syncthreads();

    float* Op = g_o + (b * 256 + h * 32) * 4096 + area * 1024;
    const float* Os = (const float*)(smbuf);
    for (int i = t * 4; i < 2048; i += 512) {
        int d = i >> 6, q = i & 63;
        float4 o;
        o.x = Os[(q + 0) * 33 + d];
        o.y = Os[(q + 1) * 33 + d];
        o.z = Os[(q + 2) * 33 + d];
        o.w = Os[(q + 3) * 33 + d];
        *(float4*)&Op[d * 4096 + q0 + q] = o;
    }
}

// ---------------- helpers to get device-global addresses ----------------------
static void* dev_addr(const void* sym) {
    void* p = nullptr;
    cudaGetSymbolAddress(&p, sym);
    return p;
}

// ---------------- launch ------------------------------------------------------
extern "C" void kernel_launch(void* const* d_in, const int* in_sizes, int n_in,
                              void* d_out, int out_size)
{
    const float *x, *w_qk, *w_v, *w_pe, *w_proj;
    const float *qk_g, *qk_b, *qk_m, *qk_v;
    const float *v_g, *v_b, *v_m, *v_v;
    const float *pe_g, *pe_b, *pe_m, *pe_v;
    const float *pr_g, *pr_b, *pr_m, *pr_v;

    x = (const float*)d_in[0];
    w_qk = (const float*)d_in[1];
    if (in_sizes[2] == 512) {
        qk_g = (const float*)d_in[2];  qk_b = (const float*)d_in[3];
        qk_m = (const float*)d_in[4];  qk_v = (const float*)d_in[5];
        w_v  = (const float*)d_in[6];
        v_g  = (const float*)d_in[7];  v_b  = (const float*)d_in[8];
        v_m  = (const float*)d_in[9];  v_v  = (const float*)d_in[10];
        w_pe = (const float*)d_in[11];
        pe_g = (const float*)d_in[12]; pe_b = (const float*)d_in[13];
        pe_m = (const float*)d_in[14]; pe_v = (const float*)d_in[15];
        w_proj = (const float*)d_in[16];
        pr_g = (const float*)d_in[17]; pr_b = (const float*)d_in[18];
        pr_m = (const float*)d_in[19]; pr_v = (const float*)d_in[20];
    } else {
        w_v    = (const float*)d_in[2];
        w_pe   = (const float*)d_in[3];
        w_proj = (const float*)d_in[4];
        qk_g = (const float*)d_in[5];  qk_b = (const float*)d_in[6];
        qk_m = (const float*)d_in[7];  qk_v = (const float*)d_in[8];
        v_g  = (const float*)d_in[9];  v_b  = (const float*)d_in[10];
        v_m  = (const float*)d_in[11]; v_v  = (const float*)d_in[12];
        pe_g = (const float*)d_in[13]; pe_b = (const float*)d_in[14];
        pe_m = (const float*)d_in[15]; pe_v = (const float*)d_in[16];
        pr_g = (const float*)d_in[17]; pr_b = (const float*)d_in[18];
        pr_m = (const float*)d_in[19]; pr_v = (const float*)d_in[20];
    }
    float* out = (float*)d_out;

    static __nv_bfloat16* p_wqkt_h = (__nv_bfloat16*)dev_addr(g_wqkt_h);
    static __nv_bfloat16* p_wqkt_l = (__nv_bfloat16*)dev_addr(g_wqkt_l);
    static __nv_bfloat16* p_wvt_h  = (__nv_bfloat16*)dev_addr(g_wvt_h);
    static __nv_bfloat16* p_wvt_l  = (__nv_bfloat16*)dev_addr(g_wvt_l);
    static __nv_bfloat16* p_wprt_h = (__nv_bfloat16*)dev_addr(g_wprt_h);
    static __nv_bfloat16* p_wprt_l = (__nv_bfloat16*)dev_addr(g_wprt_l);
    static __nv_bfloat16* p_xh = (__nv_bfloat16*)dev_addr(g_xh);
    static __nv_bfloat16* p_xl = (__nv_bfloat16*)dev_addr(g_xl);
    static __nv_bfloat16* p_oph = (__nv_bfloat16*)dev_addr(g_oph);
    static __nv_bfloat16* p_opl = (__nv_bfloat16*)dev_addr(g_opl);
    static float* p_o  = (float*)dev_addr(g_o);
    static float* p_pp = (float*)dev_addr(g_pp);

    cudaFuncSetAttribute(flash_mma, cudaFuncAttributeMaxDynamicSharedMemorySize, FM_SMEM);
    cudaFuncSetAttribute(conv_bf, cudaFuncAttributeMaxDynamicSharedMemorySize, CB_SMEM);

    const int NX = 2 * 256 * 4096;
    prep_wt<<<512, 256>>>(w_qk, p_wqkt_h, p_wqkt_l, 512, 256, 256);
    prep_wt<<<256, 256>>>(w_v, p_wvt_h, p_wvt_l, 256, 256, 0);
    prep_wt<<<256, 256>>>(w_proj, p_wprt_h, p_wprt_l, 256, 256, 0);
    prep_split<<<NX / 1024, 256>>>(x, nullptr, p_xh, p_xl, NX);

    conv_bf<<<dim3(32, 8, 2), 128, CB_SMEM>>>(p_wqkt_h, p_wqkt_l, p_xh, p_xl, nullptr,
                                              qk_g, qk_b, qk_m, qk_v, 512, 0);
    conv_bf<<<dim3(32, 4, 2), 128, CB_SMEM>>>(p_wvt_h, p_wvt_l, p_xh, p_xl, nullptr,
                                              v_g, v_b, v_m, v_v, 256, 1);
    dw5_bn<<<512, 256>>>(w_pe, pe_g, pe_b, pe_m, pe_v);
    flash_mma<<<dim3(16, 64), 128, FM_SMEM>>>();
    prep_split<<<NX / 1024, 256>>>(p_o, p_pp, p_oph, p_opl, NX);
    conv_bf<<<dim3(32, 4, 2), 128, CB_SMEM>>>(p_wprt_h, p_wprt_l, p_oph, p_opl, out,
                                              pr_g, pr_b, pr_m, pr_v, 256, 2);
}

// round 14
// speedup vs baseline: 2.3299x; 1.1813x over previous
#include <cuda_runtime.h>
#include <cuda_bf16.h>

#define BN_EPS 1e-5f
#define SC 0.17677669529663687f

// ---------------- scratch (device globals; no allocation allowed) -------------
__device__ float g_yv [2 * 256 * 4096];                 // v conv fp32 (for dw)
__device__ float g_pp [2 * 256 * 4096];                 // depthwise+BN
__device__ __nv_bfloat16 g_qk_hi[2 * 512 * 4096];
__device__ __nv_bfloat16 g_qk_lo[2 * 512 * 4096];
__device__ __nv_bfloat16 g_v_hi [2 * 256 * 4096];
__device__ __nv_bfloat16 g_v_lo [2 * 256 * 4096];
__device__ __nv_bfloat16 g_xh  [2 * 256 * 4096];        // x split
__device__ __nv_bfloat16 g_xl  [2 * 256 * 4096];
__device__ __nv_bfloat16 g_oph [2 * 256 * 4096];        // (o+pp) split (flash epi)
__device__ __nv_bfloat16 g_opl [2 * 256 * 4096];
__device__ __nv_bfloat16 g_wqkt_h[256 * 512], g_wqkt_l[256 * 512];   // [k][m]
__device__ __nv_bfloat16 g_wvt_h [256 * 256], g_wvt_l [256 * 256];
__device__ __nv_bfloat16 g_wprt_h[256 * 256], g_wprt_l[256 * 256];

__device__ __forceinline__ unsigned short bf_hi(float x) {
    return __bfloat16_as_ushort(__float2bfloat16(x));
}
__device__ __forceinline__ unsigned short bf_lo(float x, unsigned short h) {
    __nv_bfloat16 hb = __ushort_as_bfloat16(h);
    return __bfloat16_as_ushort(__float2bfloat16(x - __bfloat162float(hb)));
}
__device__ __forceinline__ unsigned pk(unsigned short a, unsigned short b) {
    return ((unsigned)b << 16) | (unsigned)a;
}
__device__ __forceinline__ unsigned smem_u32(const void* p) {
    unsigned a;
    asm("{ .reg .u64 t; cvta.to.shared.u64 t, %1; cvt.u32.u64 %0, t; }" : "=r"(a) : "l"(p));
    return a;
}
__device__ __forceinline__ void ldsm_x4(unsigned& r0, unsigned& r1, unsigned& r2, unsigned& r3,
                                        unsigned addr) {
    asm volatile("ldmatrix.sync.aligned.m8n8.x4.shared.b16 {%0,%1,%2,%3}, [%4];"
                 : "=r"(r0), "=r"(r1), "=r"(r2), "=r"(r3) : "r"(addr));
}
__device__ __forceinline__ void ldsm_x4t(unsigned& r0, unsigned& r1, unsigned& r2, unsigned& r3,
                                         unsigned addr) {
    asm volatile("ldmatrix.sync.aligned.m8n8.x4.trans.shared.b16 {%0,%1,%2,%3}, [%4];"
                 : "=r"(r0), "=r"(r1), "=r"(r2), "=r"(r3) : "r"(addr));
}
__device__ __forceinline__ void mma16816(float& c0, float& c1, float& c2, float& c3,
                                         unsigned a0, unsigned a1, unsigned a2, unsigned a3,
                                         unsigned b0, unsigned b1) {
    asm volatile(
        "mma.sync.aligned.m16n8k16.row.col.f32.bf16.bf16.f32 "
        "{%0,%1,%2,%3}, {%4,%5,%6,%7}, {%8,%9}, {%0,%1,%2,%3};"
        : "+f"(c0), "+f"(c1), "+f"(c2), "+f"(c3)
        : "r"(a0), "r"(a1), "r"(a2), "r"(a3), "r"(b0), "r"(b1));
}
__device__ __forceinline__ void cp_async16(unsigned dst, const void* src) {
    asm volatile("cp.async.cg.shared.global [%0], [%1], 16;" :: "r"(dst), "l"(src) : "memory");
}
__device__ __forceinline__ void cp_commit() {
    asm volatile("cp.async.commit_group;" ::: "memory");
}
__device__ __forceinline__ void cp_wait_all() {
    asm volatile("cp.async.wait_group 0;" ::: "memory");
}

// ---------------- prep kernels -------------------------------------------------
__global__ __launch_bounds__(256) void prep_split(
    const float* __restrict__ a, const float* __restrict__ b,
    __nv_bfloat16* __restrict__ h, __nv_bfloat16* __restrict__ l, int n)
{
    int i = (blockIdx.x * 256 + threadIdx.x) * 4;
    if (i >= n) return;
    float4 v = *reinterpret_cast<const float4*>(&a[i]);
    if (b) {
        float4 v2 = *reinterpret_cast<const float4*>(&b[i]);
        v.x += v2.x; v.y += v2.y; v.z += v2.z; v.w += v2.w;
    }
    float va[4] = {v.x, v.y, v.z, v.w};
    unsigned short hh[4], ll[4];
#pragma unroll
    for (int j = 0; j < 4; j++) { hh[j] = bf_hi(va[j]); ll[j] = bf_lo(va[j], hh[j]); }
    *reinterpret_cast<uint2*>(&h[i]) = make_uint2(pk(hh[0], hh[1]), pk(hh[2], hh[3]));
    *reinterpret_cast<uint2*>(&l[i]) = make_uint2(pk(ll[0], ll[1]), pk(ll[2], ll[3]));
}

__global__ __launch_bounds__(256) void prep_wt(
    const float* __restrict__ W, __nv_bfloat16* __restrict__ th,
    __nv_bfloat16* __restrict__ tl, int M, int K, int sc_rows)
{
    int idx = blockIdx.x * 256 + threadIdx.x;      // idx = k*M + m
    if (idx >= M * K) return;
    int k = idx / M, m = idx - k * M;
    float v = W[m * K + k];
    if (m < sc_rows) v *= SC;
    unsigned short h = bf_hi(v);
    th[idx] = __ushort_as_bfloat16(h);
    tl[idx] = __ushort_as_bfloat16(bf_lo(v, h));
}

// =============== all-bf16 conv1x1 + BN (cp.async pipelined) ===================
#define BW_L 4608
#define BX_H 9216
#define BX_L 17920
#define BUFB 26624
#define CB_SMEM (2 * BUFB)

__global__ __launch_bounds__(128) void conv_bf(
    const __nv_bfloat16* __restrict__ Wth, const __nv_bfloat16* __restrict__ Wtl,
    const __nv_bfloat16* __restrict__ Xh0, const __nv_bfloat16* __restrict__ Xl0,
    float* __restrict__ dout,
    const float* __restrict__ gg, const float* __restrict__ bb,
    const float* __restrict__ mm, const float* __restrict__ vv,
    int M, int out_mode)
{
    extern __shared__ char csm[];
    const unsigned sbc = smem_u32(csm);
    const int N = 4096;
    const int t = threadIdx.x, lane = t & 31, w = t >> 5;
    const int b = blockIdx.z;
    const int m0 = blockIdx.y * 64, n0 = blockIdx.x * 128;

    const __nv_bfloat16* Xh = Xh0 + b * 256 * 4096;
    const __nv_bfloat16* Xl = Xl0 + b * 256 * 4096;

    auto chunk_copy = [&](unsigned base, int k0) {
#pragma unroll
        for (int c = t; c < 1536; c += 128) {
            if (c < 512) {
                int arr = c >> 8, rem = c & 255, r = rem >> 3, c16 = rem & 7;
                const __nv_bfloat16* s = (arr ? Wtl : Wth) + (k0 + r) * M + m0 + c16 * 8;
                cp_async16(base + arr * BW_L + r * 144 + c16 * 16, s);
            } else {
                int c2 = c - 512;
                int arr = c2 >> 9, rem = c2 & 511, r = rem >> 4, c16 = rem & 15;
                const __nv_bfloat16* s = (arr ? Xl : Xh) + (k0 + r) * N + n0 + c16 * 8;
                cp_async16(base + BX_H + arr * (BX_L - BX_H) + r * 272 + c16 * 16, s);
            }
        }
        cp_commit();
    };

    chunk_copy(sbc, 0);

    float S[16][4];
#pragma unroll
    for (int j = 0; j < 16; j++)
#pragma unroll
        for (int c = 0; c < 4; c++) S[j][c] = 0.f;

    for (int c0 = 0; c0 < 8; c0++) {
        cp_wait_all();
        __syncthreads();
        if (c0 < 7) chunk_copy(sbc + ((c0 + 1) & 1) * BUFB, (c0 + 1) * 32);
        const unsigned bbuf = sbc + (c0 & 1) * BUFB;

        unsigned wa_[2][2][4];
#pragma unroll
        for (int sp = 0; sp < 2; sp++)
#pragma unroll
            for (int s = 0; s < 2; s++) {
                unsigned drow = s * 16 + ((lane >> 4) & 1) * 8 + (lane & 7);
                unsigned col  = (unsigned)w * 32 + ((lane >> 3) & 1) * 16;
                ldsm_x4t(wa_[sp][s][0], wa_[sp][s][1], wa_[sp][s][2], wa_[sp][s][3],
                         bbuf + sp * BW_L + drow * 144 + col);
            }
#pragma unroll
        for (int j = 0; j < 16; j++) {
            unsigned xh0, xh1, xh2, xh3, xl0, xl1, xl2, xl3;
            ldsm_x4t(xh0, xh1, xh2, xh3, bbuf + BX_H + lane * 272 + j * 16);
            ldsm_x4t(xl0, xl1, xl2, xl3, bbuf + BX_L + lane * 272 + j * 16);
            mma16816(S[j][0], S[j][1], S[j][2], S[j][3],
                     wa_[0][0][0], wa_[0][0][1], wa_[0][0][2], wa_[0][0][3], xh0, xh1);
            mma16816(S[j][0], S[j][1], S[j][2], S[j][3],
                     wa_[0][1][0], wa_[0][1][1], wa_[0][1][2], wa_[0][1][3], xh2, xh3);
            mma16816(S[j][0], S[j][1], S[j][2], S[j][3],
                     wa_[0][0][0], wa_[0][0][1], wa_[0][0][2], wa_[0][0][3], xl0, xl1);
            mma16816(S[j][0], S[j][1], S[j][2], S[j][3],
                     wa_[0][1][0], wa_[0][1][1], wa_[0][1][2], wa_[0][1][3], xl2, xl3);
            mma16816(S[j][0], S[j][1], S[j][2], S[j][3],
                     wa_[1][0][0], wa_[1][0][1], wa_[1][0][2], wa_[1][0][3], xh0, xh1);
            mma16816(S[j][0], S[j][1], S[j][2], S[j][3],
                     wa_[1][1][0], wa_[1][1][1], wa_[1][1][2], wa_[1][1][3], xh2, xh3);
        }
    }

    const int r0 = m0 + w * 16 + (lane >> 2);
    const int r1 = r0 + 8;
    float s0 = gg[r0] * rsqrtf(vv[r0] + BN_EPS);
    float bi0 = bb[r0] - mm[r0] * s0;
    float s1 = gg[r1] * rsqrtf(vv[r1] + BN_EPS);
    float bi1 = bb[r1] - mm[r1] * s1;
    if (out_mode == 0 && r0 < 256) { bi0 *= SC; }
    if (out_mode == 0 && r1 < 256) { bi1 *= SC; }

#pragma unroll
    for (int j = 0; j < 16; j++) {
        int n = n0 + j * 8 + (lane & 3) * 2;
        float o0 = S[j][0] * s0 + bi0, o1 = S[j][1] * s0 + bi0;
        float o2 = S[j][2] * s1 + bi1, o3 = S[j][3] * s1 + bi1;
        long i0 = (long)b * M * 4096 + (long)r0 * 4096 + n;
        long i1 = (long)b * M * 4096 + (long)r1 * 4096 + n;
        if (out_mode == 2) {
            *reinterpret_cast<float2*>(&dout[i0]) = make_float2(o0, o1);
            *reinterpret_cast<float2*>(&dout[i1]) = make_float2(o2, o3);
        } else {
            if (out_mode == 1) {
                *reinterpret_cast<float2*>(&g_yv[i0]) = make_float2(o0, o1);
                *reinterpret_cast<float2*>(&g_yv[i1]) = make_float2(o2, o3);
            }
            __nv_bfloat16* H = (out_mode == 0 ? g_qk_hi : g_v_hi);
            __nv_bfloat16* L = (out_mode == 0 ? g_qk_lo : g_v_lo);
            unsigned short h0 = bf_hi(o0), h1 = bf_hi(o1);
            unsigned short h2 = bf_hi(o2), h3 = bf_hi(o3);
            *reinterpret_cast<unsigned*>(&H[i0]) = pk(h0, h1);
            *reinterpret_cast<unsigned*>(&H[i1]) = pk(h2, h3);
            *reinterpret_cast<unsigned*>(&L[i0]) = pk(bf_lo(o0, h0), bf_lo(o1, h1));
            *reinterpret_cast<unsigned*>(&L[i1]) = pk(bf_lo(o2, h2), bf_lo(o3, h3));
        }
    }
}

// ---------------- depthwise 5x5 (pad 2) + BN, vectorized ----------------------
__global__ __launch_bounds__(256) void dw5_bn(
    const float* __restrict__ w_pe,
    const float* __restrict__ gg, const float* __restrict__ bb,
    const float* __restrict__ mm, const float* __restrict__ vv)
{
    const int bc = blockIdx.x;
    const int c  = bc & 255;
    const float* src = g_yv + bc * 4096;
    float* dst = g_pp + bc * 4096;

    __shared__ float tile[68][68];
    __shared__ float wk[25];
    const int t = threadIdx.x;

    // zero full tile (float4)
    for (int i = t * 4; i < 68 * 68; i += 1024)
        *reinterpret_cast<float4*>(&((float*)tile)[i]) = make_float4(0.f, 0.f, 0.f, 0.f);
    if (t >= 68 * 68 / 4 * 4 && false) {}
    if (t < 25) wk[t] = w_pe[c * 25 + t];
    __syncthreads();
    // (68*68=4624, divisible by 4 -> full coverage)
    for (int i = t * 4; i < 4096; i += 1024) {
        float4 v = *reinterpret_cast<const float4*>(&src[i]);
        int y = (i >> 6) + 2, x = (i & 63) + 2;
        tile[y][x] = v.x; tile[y][x + 1] = v.y; tile[y][x + 2] = v.z; tile[y][x + 3] = v.w;
    }
    __syncthreads();

    float s  = gg[c] * rsqrtf(vv[c] + BN_EPS);
    float bi = bb[c] - mm[c] * s;

    for (int i = t * 4; i < 4096; i += 1024) {
        int y = i >> 6, x = i & 63;
        float a0 = 0.f, a1 = 0.f, a2 = 0.f, a3 = 0.f;
#pragma unroll
        for (int ky = 0; ky < 5; ky++)
#pragma unroll
            for (int kx = 0; kx < 5; kx++) {
                float wv = wk[ky * 5 + kx];
                a0 = fmaf(tile[y + ky][x + kx],     wv, a0);
                a1 = fmaf(tile[y + ky][x + kx + 1], wv, a1);
                a2 = fmaf(tile[y + ky][x + kx + 2], wv, a2);
                a3 = fmaf(tile[y + ky][x + kx + 3], wv, a3);
            }
        *reinterpret_cast<float4*>(&dst[i]) =
            make_float4(a0 * s + bi, a1 * s + bi, a2 * s + bi, a3 * s + bi);
    }
}

// ================= flash attention: 3 CTAs/SM attempt =========================
// smem: KV double buffer only (Q staged transiently inside buffer 0)
#define TS 272
#define BUFSZ  34816
#define FM_SMEM (2 * BUFSZ)   /* 69632 */

__device__ __forceinline__ void kv_copy(unsigned base, int t,
    const __nv_bfloat16* Kh, const __nv_bfloat16* Kl,
    const __nv_bfloat16* Vh, const __nv_bfloat16* Vl, int m0)
{
#pragma unroll
    for (int c = t; c < 2048; c += 128) {
        int arr = c >> 9, d = (c >> 4) & 31, mb = c & 15;
        const __nv_bfloat16* s =
            (arr == 0 ? Kh : (arr == 1 ? Kl : (arr == 2 ? Vh : Vl))) + d * 4096 + m0 + mb * 8;
        cp_async16(base + arr * 8704 + d * TS + mb * 16, s);
    }
    cp_commit();
}

__global__ __launch_bounds__(128, 3) void flash_mma()
{
    extern __shared__ char smbuf[];
    const unsigned sb = smem_u32(smbuf);
    const int t = threadIdx.x, lane = t & 31, w = t >> 5;

    const int bh = blockIdx.y;
    const int b = bh >> 5, area = (bh >> 3) & 3, h = bh & 7;
    const int q0 = blockIdx.x * 64;

    const int qch = (b * 512 + h * 32) * 4096 + area * 1024;
    const int kch = (b * 512 + 256 + h * 32) * 4096 + area * 1024;
    const int vch = (b * 256 + h * 32) * 4096 + area * 1024;
    const __nv_bfloat16* Qh = g_qk_hi + qch + q0;
    const __nv_bfloat16* Ql = g_qk_lo + qch + q0;
    const __nv_bfloat16* Kh = g_qk_hi + kch;
    const __nv_bfloat16* Kl = g_qk_lo + kch;
    const __nv_bfloat16* Vh = g_v_hi + vch;
    const __nv_bfloat16* Vl = g_v_lo + vch;

    // ---- stage Q into buffer0 region transiently, load frags, then free it ---
#pragma unroll
    for (int c = t; c < 512; c += 128) {
        int arr = c >> 8, d = (c >> 3) & 31, qb = c & 7;
        const __nv_bfloat16* s = (arr ? Ql : Qh) + d * 4096 + qb * 8;
        *reinterpret_cast<uint4*>(smbuf + arr * 8704 + d * TS + qb * 16) =
            *reinterpret_cast<const uint4*>(s);
    }
    __syncthreads();

    unsigned qa[2][2][4];
#pragma unroll
    for (int sp = 0; sp < 2; sp++)
#pragma unroll
        for (int s = 0; s < 2; s++) {
            unsigned drow = s * 16 + ((lane >> 4) & 1) * 8 + (lane & 7);
            unsigned col  = (unsigned)w * 32 + ((lane >> 3) & 1) * 16;
            ldsm_x4t(qa[sp][s][0], qa[sp][s][1], qa[sp][s][2], qa[sp][s][3],
                     sb + sp * 8704 + drow * TS + col);
        }
    __syncthreads();   // Q consumed; buffer 0 free for KV

    kv_copy(sb, t, Kh, Kl, Vh, Vl, 0);

    float Oacc[4][4];
#pragma unroll
    for (int dn = 0; dn < 4; dn++)
#pragma unroll
        for (int c = 0; c < 4; c++) Oacc[dn][c] = 0.f;
    float mr0 = -1e30f, mr1 = -1e30f, lr0 = 0.f, lr1 = 0.f;

    for (int kt = 0; kt < 8; kt++) {
        cp_wait_all();
        __syncthreads();
        if (kt < 7)
            kv_copy(sb + ((kt + 1) & 1) * BUFSZ, t, Kh, Kl, Vh, Vl, (kt + 1) * 128);
        const unsigned kb = sb + (kt & 1) * BUFSZ;

        float S[16][4];
#pragma unroll
        for (int j = 0; j < 16; j++) {
            unsigned kh0, kh1, kh2, kh3, kl0, kl1, kl2, kl3;
            ldsm_x4t(kh0, kh1, kh2, kh3, kb + lane * TS + j * 16);
            ldsm_x4t(kl0, kl1, kl2, kl3, kb + 8704 + lane * TS + j * 16);
            float a0 = 0.f, a1 = 0.f, a2 = 0.f, a3 = 0.f;
            float b0 = 0.f, b1 = 0.f, b2 = 0.f, b3 = 0.f;
            mma16816(a0, a1, a2, a3, qa[0][0][0], qa[0][0][1], qa[0][0][2], qa[0][0][3], kh0, kh1);
            mma16816(a0, a1, a2, a3, qa[0][1][0], qa[0][1][1], qa[0][1][2], qa[0][1][3], kh2, kh3);
            mma16816(b0, b1, b2, b3, qa[0][0][0], qa[0][0][1], qa[0][0][2], qa[0][0][3], kl0, kl1);
            mma16816(b0, b1, b2, b3, qa[0][1][0], qa[0][1][1], qa[0][1][2], qa[0][1][3], kl2, kl3);
            mma16816(b0, b1, b2, b3, qa[1][0][0], qa[1][0][1], qa[1][0][2], qa[1][0][3], kh0, kh1);
            mma16816(b0, b1, b2, b3, qa[1][1][0], qa[1][1][1], qa[1][1][2], qa[1][1][3], kh2, kh3);
            S[j][0] = a0 + b0; S[j][1] = a1 + b1; S[j][2] = a2 + b2; S[j][3] = a3 + b3;
        }

        float mx0 = -1e30f, mx1 = -1e30f;
#pragma unroll
        for (int j = 0; j < 16; j++) {
            mx0 = fmaxf(mx0, fmaxf(S[j][0], S[j][1]));
            mx1 = fmaxf(mx1, fmaxf(S[j][2], S[j][3]));
        }
        mx0 = fmaxf(mx0, __shfl_xor_sync(0xFFFFFFFFu, mx0, 1));
        mx0 = fmaxf(mx0, __shfl_xor_sync(0xFFFFFFFFu, mx0, 2));
        mx1 = fmaxf(mx1, __shfl_xor_sync(0xFFFFFFFFu, mx1, 1));
        mx1 = fmaxf(mx1, __shfl_xor_sync(0xFFFFFFFFu, mx1, 2));
        float nm0 = fmaxf(mr0, mx0), nm1 = fmaxf(mr1, mx1);
        float be0 = __expf(mr0 - nm0), be1 = __expf(mr1 - nm1);
        float lt0 = 0.f, lt1 = 0.f;
#pragma unroll
        for (int j = 0; j < 16; j++) {
            S[j][0] = __expf(S[j][0] - nm0); lt0 += S[j][0];
            S[j][1] = __expf(S[j][1] - nm0); lt0 += S[j][1];
            S[j][2] = __expf(S[j][2] - nm1); lt1 += S[j][2];
            S[j][3] = __expf(S[j][3] - nm1); lt1 += S[j][3];
        }
        lt0 += __shfl_xor_sync(0xFFFFFFFFu, lt0, 1);
        lt0 += __shfl_xor_sync(0xFFFFFFFFu, lt0, 2);
        lt1 += __shfl_xor_sync(0xFFFFFFFFu, lt1, 1);
        lt1 += __shfl_xor_sync(0xFFFFFFFFu, lt1, 2);
        lr0 = lr0 * be0 + lt0; lr1 = lr1 * be1 + lt1;
        mr0 = nm0; mr1 = nm1;
#pragma unroll
        for (int dn = 0; dn < 4; dn++) {
            Oacc[dn][0] *= be0; Oacc[dn][1] *= be0;
            Oacc[dn][2] *= be1; Oacc[dn][3] *= be1;
        }

#pragma unroll
        for (int tt = 0; tt < 8; tt++) {
            unsigned ah[4], al[4];
            {
                unsigned short h0 = bf_hi(S[2*tt][0]),   h1 = bf_hi(S[2*tt][1]);
                unsigned short h2 = bf_hi(S[2*tt][2]),   h3 = bf_hi(S[2*tt][3]);
                unsigned short h4 = bf_hi(S[2*tt+1][0]), h5 = bf_hi(S[2*tt+1][1]);
                unsigned short h6 = bf_hi(S[2*tt+1][2]), h7 = bf_hi(S[2*tt+1][3]);
                ah[0] = pk(h0, h1); ah[1] = pk(h2, h3);
                ah[2] = pk(h4, h5); ah[3] = pk(h6, h7);
                al[0] = pk(bf_lo(S[2*tt][0], h0),   bf_lo(S[2*tt][1], h1));
                al[1] = pk(bf_lo(S[2*tt][2], h2),   bf_lo(S[2*tt][3], h3));
                al[2] = pk(bf_lo(S[2*tt+1][0], h4), bf_lo(S[2*tt+1][1], h5));
                al[3] = pk(bf_lo(S[2*tt+1][2], h6), bf_lo(S[2*tt+1][3], h7));
            }
#pragma unroll
            for (int p = 0; p < 2; p++) {
                unsigned drow = (unsigned)p * 16 + ((lane >> 4) & 1) * 8 + (lane & 7);
                unsigned colb = (unsigned)tt * 32 + ((lane >> 3) & 1) * 16;
                unsigned vh0, vh1, vh2, vh3, vl0, vl1, vl2, vl3;
                ldsm_x4(vh0, vh1, vh2, vh3, kb + 17408 + drow * TS + colb);
                ldsm_x4(vl0, vl1, vl2, vl3, kb + 26112 + drow * TS + colb);
                int d0 = p * 2, d1 = p * 2 + 1;
                mma16816(Oacc[d0][0], Oacc[d0][1], Oacc[d0][2], Oacc[d0][3],
                         ah[0], ah[1], ah[2], ah[3], vh0, vh1);
                mma16816(Oacc[d0][0], Oacc[d0][1], Oacc[d0][2], Oacc[d0][3],
                         ah[0], ah[1], ah[2], ah[3], vl0, vl1);
                mma16816(Oacc[d0][0], Oacc[d0][1], Oacc[d0][2], Oacc[d0][3],
                         al[0], al[1], al[2], al[3], vh0, vh1);
                mma16816(Oacc[d1][0], Oacc[d1][1], Oacc[d1][2], Oacc[d1][3],
                         ah[0], ah[1], ah[2], ah[3], vh2, vh3);
                mma16816(Oacc[d1][0], Oacc[d1][1], Oacc[d1][2], Oacc[d1][3],
                         ah[0], ah[1], ah[2], ah[3], vl2, vl3);
                mma16816(Oacc[d1][0], Oacc[d1][1], Oacc[d1][2], Oacc[d1][3],
                         al[0], al[1], al[2], al[3], vh2, vh3);
            }
        }
    }

    // ---- epilogue: normalize, add g_pp, split hi/lo, write g_oph/g_opl -------
    __syncthreads();
    {
        float inv0 = 1.f / lr0, inv1 = 1.f / lr1;
        int r = w * 16 + (lane >> 2);
        int dc = (lane & 3) * 2;
        float* Os = (float*)(smbuf);
#pragma unroll
        for (int dn = 0; dn < 4; dn++) {
            int d = dn * 8 + dc;
            Os[r * 33 + d]           = Oacc[dn][0] * inv0;
            Os[r * 33 + d + 1]       = Oacc[dn][1] * inv0;
            Os[(r + 8) * 33 + d]     = Oacc[dn][2] * inv1;
            Os[(r + 8) * 33 + d + 1] = Oacc[dn][3] * inv1;
        }
    }
    __syncthreads();

    const long ob = (long)(b * 256 + h * 32) * 4096 + area * 1024 + q0;
    const float* Pp = g_pp + ob;
    __nv_bfloat16* OH = g_oph + ob;
    __nv_bfloat16* OL = g_opl + ob;
    const float* Os = (const float*)(smbuf);
    for (int i = t * 4; i < 2048; i += 512) {
        int d = i >> 6, q = i & 63;
        float o[4];
        o[0] = Os[(q + 0) * 33 + d];
        o[1] = Os[(q + 1) * 33 + d];
        o[2] = Os[(q + 2) * 33 + d];
        o[3] = Os[(q + 3) * 33 + d];
        float4 p = *reinterpret_cast<const float4*>(&Pp[d * 4096 + q]);
        o[0] += p.x; o[1] += p.y; o[2] += p.z; o[3] += p.w;
        unsigned short hh[4], ll[4];
#pragma unroll
        for (int j = 0; j < 4; j++) { hh[j] = bf_hi(o[j]); ll[j] = bf_lo(o[j], hh[j]); }
        *reinterpret_cast<uint2*>(&OH[d * 4096 + q]) =
            make_uint2(pk(hh[0], hh[1]), pk(hh[2], hh[3]));
        *reinterpret_cast<uint2*>(&OL[d * 4096 + q]) =
            make_uint2(pk(ll[0], ll[1]), pk(ll[2], ll[3]));
    }
}

// ---------------- helpers to get device-global addresses ----------------------
static void* dev_addr(const void* sym) {
    void* p = nullptr;
    cudaGetSymbolAddress(&p, sym);
    return p;
}

// ---------------- launch ------------------------------------------------------
extern "C" void kernel_launch(void* const* d_in, const int* in_sizes, int n_in,
                              void* d_out, int out_size)
{
    const float *x, *w_qk, *w_v, *w_pe, *w_proj;
    const float *qk_g, *qk_b, *qk_m, *qk_v;
    const float *v_g, *v_b, *v_m, *v_v;
    const float *pe_g, *pe_b, *pe_m, *pe_v;
    const float *pr_g, *pr_b, *pr_m, *pr_v;

    x = (const float*)d_in[0];
    w_qk = (const float*)d_in[1];
    if (in_sizes[2] == 512) {
        qk_g = (const float*)d_in[2];  qk_b = (const float*)d_in[3];
        qk_m = (const float*)d_in[4];  qk_v = (const float*)d_in[5];
        w_v  = (const float*)d_in[6];
        v_g  = (const float*)d_in[7];  v_b  = (const float*)d_in[8];
        v_m  = (const float*)d_in[9];  v_v  = (const float*)d_in[10];
        w_pe = (const float*)d_in[11];
        pe_g = (const float*)d_in[12]; pe_b = (const float*)d_in[13];
        pe_m = (const float*)d_in[14]; pe_v = (const float*)d_in[15];
        w_proj = (const float*)d_in[16];
        pr_g = (const float*)d_in[17]; pr_b = (const float*)d_in[18];
        pr_m = (const float*)d_in[19]; pr_v = (const float*)d_in[20];
    } else {
        w_v    = (const float*)d_in[2];
        w_pe   = (const float*)d_in[3];
        w_proj = (const float*)d_in[4];
        qk_g = (const float*)d_in[5];  qk_b = (const float*)d_in[6];
        qk_m = (const float*)d_in[7];  qk_v = (const float*)d_in[8];
        v_g  = (const float*)d_in[9];  v_b  = (const float*)d_in[10];
        v_m  = (const float*)d_in[11]; v_v  = (const float*)d_in[12];
        pe_g = (const float*)d_in[13]; pe_b = (const float*)d_in[14];
        pe_m = (const float*)d_in[15]; pe_v = (const float*)d_in[16];
        pr_g = (const float*)d_in[17]; pr_b = (const float*)d_in[18];
        pr_m = (const float*)d_in[19]; pr_v = (const float*)d_in[20];
    }
    float* out = (float*)d_out;

    static __nv_bfloat16* p_wqkt_h = (__nv_bfloat16*)dev_addr(g_wqkt_h);
    static __nv_bfloat16* p_wqkt_l = (__nv_bfloat16*)dev_addr(g_wqkt_l);
    static __nv_bfloat16* p_wvt_h  = (__nv_bfloat16*)dev_addr(g_wvt_h);
    static __nv_bfloat16* p_wvt_l  = (__nv_bfloat16*)dev_addr(g_wvt_l);
    static __nv_bfloat16* p_wprt_h = (__nv_bfloat16*)dev_addr(g_wprt_h);
    static __nv_bfloat16* p_wprt_l = (__nv_bfloat16*)dev_addr(g_wprt_l);
    static __nv_bfloat16* p_xh = (__nv_bfloat16*)dev_addr(g_xh);
    static __nv_bfloat16* p_xl = (__nv_bfloat16*)dev_addr(g_xl);
    static __nv_bfloat16* p_oph = (__nv_bfloat16*)dev_addr(g_oph);
    static __nv_bfloat16* p_opl = (__nv_bfloat16*)dev_addr(g_opl);

    cudaFuncSetAttribute(flash_mma, cudaFuncAttributeMaxDynamicSharedMemorySize, FM_SMEM);
    cudaFuncSetAttribute(conv_bf, cudaFuncAttributeMaxDynamicSharedMemorySize, CB_SMEM);

    const int NX = 2 * 256 * 4096;
    prep_wt<<<512, 256>>>(w_qk, p_wqkt_h, p_wqkt_l, 512, 256, 256);
    prep_wt<<<256, 256>>>(w_v, p_wvt_h, p_wvt_l, 256, 256, 0);
    prep_wt<<<256, 256>>>(w_proj, p_wprt_h, p_wprt_l, 256, 256, 0);
    prep_split<<<NX / 1024, 256>>>(x, nullptr, p_xh, p_xl, NX);

    conv_bf<<<dim3(32, 8, 2), 128, CB_SMEM>>>(p_wqkt_h, p_wqkt_l, p_xh, p_xl, nullptr,
                                              qk_g, qk_b, qk_m, qk_v, 512, 0);
    conv_bf<<<dim3(32, 4, 2), 128, CB_SMEM>>>(p_wvt_h, p_wvt_l, p_xh, p_xl, nullptr,
                                              v_g, v_b, v_m, v_v, 256, 1);
    dw5_bn<<<512, 256>>>(w_pe, pe_g, pe_b, pe_m, pe_v);
    flash_mma<<<dim3(16, 64), 128, FM_SMEM>>>();
    conv_bf<<<dim3(32, 4, 2), 128, CB_SMEM>>>(p_wprt_h, p_wprt_l, p_oph, p_opl, out,
                                              pr_g, pr_b, pr_m, pr_v, 256, 2);
}

// round 15
// speedup vs baseline: 2.4606x; 1.0561x over previous
#include <cuda_runtime.h>
#include <cuda_bf16.h>

#define BN_EPS 1e-5f
#define SC 0.17677669529663687f

// ---------------- scratch (device globals; no allocation allowed) -------------
__device__ float g_yv [2 * 256 * 4096];                 // v conv fp32 (for dw)
__device__ float g_pp [2 * 256 * 4096];                 // depthwise+BN
__device__ __nv_bfloat16 g_qk_hi[2 * 512 * 4096];
__device__ __nv_bfloat16 g_qk_lo[2 * 512 * 4096];
__device__ __nv_bfloat16 g_v_hi [2 * 256 * 4096];
__device__ __nv_bfloat16 g_v_lo [2 * 256 * 4096];
__device__ __nv_bfloat16 g_xh  [2 * 256 * 4096];        // x split
__device__ __nv_bfloat16 g_xl  [2 * 256 * 4096];
__device__ __nv_bfloat16 g_oph [2 * 256 * 4096];        // (o+pp) split (flash epi)
__device__ __nv_bfloat16 g_opl [2 * 256 * 4096];
__device__ __nv_bfloat16 g_wqkt_h[256 * 512], g_wqkt_l[256 * 512];   // [k][m]
__device__ __nv_bfloat16 g_wvt_h [256 * 256], g_wvt_l [256 * 256];
__device__ __nv_bfloat16 g_wprt_h[256 * 256], g_wprt_l[256 * 256];

__device__ __forceinline__ unsigned short bf_hi(float x) {
    return __bfloat16_as_ushort(__float2bfloat16(x));
}
__device__ __forceinline__ unsigned short bf_lo(float x, unsigned short h) {
    __nv_bfloat16 hb = __ushort_as_bfloat16(h);
    return __bfloat16_as_ushort(__float2bfloat16(x - __bfloat162float(hb)));
}
__device__ __forceinline__ unsigned pk(unsigned short a, unsigned short b) {
    return ((unsigned)b << 16) | (unsigned)a;
}
__device__ __forceinline__ unsigned smem_u32(const void* p) {
    unsigned a;
    asm("{ .reg .u64 t; cvta.to.shared.u64 t, %1; cvt.u32.u64 %0, t; }" : "=r"(a) : "l"(p));
    return a;
}
__device__ __forceinline__ void ldsm_x4(unsigned& r0, unsigned& r1, unsigned& r2, unsigned& r3,
                                        unsigned addr) {
    asm volatile("ldmatrix.sync.aligned.m8n8.x4.shared.b16 {%0,%1,%2,%3}, [%4];"
                 : "=r"(r0), "=r"(r1), "=r"(r2), "=r"(r3) : "r"(addr));
}
__device__ __forceinline__ void ldsm_x4t(unsigned& r0, unsigned& r1, unsigned& r2, unsigned& r3,
                                         unsigned addr) {
    asm volatile("ldmatrix.sync.aligned.m8n8.x4.trans.shared.b16 {%0,%1,%2,%3}, [%4];"
                 : "=r"(r0), "=r"(r1), "=r"(r2), "=r"(r3) : "r"(addr));
}
__device__ __forceinline__ void mma16816(float& c0, float& c1, float& c2, float& c3,
                                         unsigned a0, unsigned a1, unsigned a2, unsigned a3,
                                         unsigned b0, unsigned b1) {
    asm volatile(
        "mma.sync.aligned.m16n8k16.row.col.f32.bf16.bf16.f32 "
        "{%0,%1,%2,%3}, {%4,%5,%6,%7}, {%8,%9}, {%0,%1,%2,%3};"
        : "+f"(c0), "+f"(c1), "+f"(c2), "+f"(c3)
        : "r"(a0), "r"(a1), "r"(a2), "r"(a3), "r"(b0), "r"(b1));
}
__device__ __forceinline__ void cp_async16(unsigned dst, const void* src) {
    asm volatile("cp.async.cg.shared.global [%0], [%1], 16;" :: "r"(dst), "l"(src) : "memory");
}
__device__ __forceinline__ void cp_commit() {
    asm volatile("cp.async.commit_group;" ::: "memory");
}
__device__ __forceinline__ void cp_wait_all() {
    asm volatile("cp.async.wait_group 0;" ::: "memory");
}

// ---------------- prep kernels -------------------------------------------------
// split fp32 -> bf16 hi/lo; 8 floats (32B) per thread for more MLP
__global__ __launch_bounds__(256) void prep_split(
    const float* __restrict__ a, const float* __restrict__ b,
    __nv_bfloat16* __restrict__ h, __nv_bfloat16* __restrict__ l, int n)
{
    int i = (blockIdx.x * 256 + threadIdx.x) * 8;
    if (i >= n) return;
    float4 v0 = *reinterpret_cast<const float4*>(&a[i]);
    float4 v1 = *reinterpret_cast<const float4*>(&a[i + 4]);
    if (b) {
        float4 u0 = *reinterpret_cast<const float4*>(&b[i]);
        float4 u1 = *reinterpret_cast<const float4*>(&b[i + 4]);
        v0.x += u0.x; v0.y += u0.y; v0.z += u0.z; v0.w += u0.w;
        v1.x += u1.x; v1.y += u1.y; v1.z += u1.z; v1.w += u1.w;
    }
    float va[8] = {v0.x, v0.y, v0.z, v0.w, v1.x, v1.y, v1.z, v1.w};
    unsigned short hh[8], ll[8];
#pragma unroll
    for (int j = 0; j < 8; j++) { hh[j] = bf_hi(va[j]); ll[j] = bf_lo(va[j], hh[j]); }
    *reinterpret_cast<uint4*>(&h[i]) =
        make_uint4(pk(hh[0], hh[1]), pk(hh[2], hh[3]), pk(hh[4], hh[5]), pk(hh[6], hh[7]));
    *reinterpret_cast<uint4*>(&l[i]) =
        make_uint4(pk(ll[0], ll[1]), pk(ll[2], ll[3]), pk(ll[4], ll[5]), pk(ll[6], ll[7]));
}

// all three weights transposed+split in ONE launch.
// segments: [0, 131072) qk (M=512, SC on m<256); [131072, 196608) v; [196608, 262144) proj
__global__ __launch_bounds__(256) void prep_wt_all(
    const float* __restrict__ Wqk, const float* __restrict__ Wv,
    const float* __restrict__ Wpr)
{
    int idx = blockIdx.x * 256 + threadIdx.x;
    const float* W; __nv_bfloat16 *th, *tl; int M, sc_rows, off;
    if (idx < 131072)      { W = Wqk; th = g_wqkt_h; tl = g_wqkt_l; M = 512; sc_rows = 256; off = idx; }
    else if (idx < 196608) { W = Wv;  th = g_wvt_h;  tl = g_wvt_l;  M = 256; sc_rows = 0;   off = idx - 131072; }
    else                   { W = Wpr; th = g_wprt_h; tl = g_wprt_l; M = 256; sc_rows = 0;   off = idx - 196608; }
    int k = off / M, m = off - k * M;
    float v = W[m * 256 + k];
    if (m < sc_rows) v *= SC;
    unsigned short h = bf_hi(v);
    th[off] = __ushort_as_bfloat16(h);
    tl[off] = __ushort_as_bfloat16(bf_lo(v, h));
}

// =============== all-bf16 conv1x1 + BN core (cp.async pipelined) ==============
#define BW_L 4608
#define BX_H 9216
#define BX_L 17920
#define BUFB 26624
#define CB_SMEM (2 * BUFB)

__device__ __forceinline__ void conv_core(
    char* csm,
    const __nv_bfloat16* __restrict__ Wth, const __nv_bfloat16* __restrict__ Wtl,
    const __nv_bfloat16* __restrict__ Xh, const __nv_bfloat16* __restrict__ Xl,
    float* __restrict__ dout,
    const float* __restrict__ gg, const float* __restrict__ bb,
    const float* __restrict__ mm, const float* __restrict__ vv,
    int M, int out_mode, int b, int m0, int n0)
{
    const unsigned sbc = smem_u32(csm);
    const int N = 4096;
    const int t = threadIdx.x, lane = t & 31, w = t >> 5;

    auto chunk_copy = [&](unsigned base, int k0) {
#pragma unroll
        for (int c = t; c < 1536; c += 128) {
            if (c < 512) {
                int arr = c >> 8, rem = c & 255, r = rem >> 3, c16 = rem & 7;
                const __nv_bfloat16* s = (arr ? Wtl : Wth) + (k0 + r) * M + m0 + c16 * 8;
                cp_async16(base + arr * BW_L + r * 144 + c16 * 16, s);
            } else {
                int c2 = c - 512;
                int arr = c2 >> 9, rem = c2 & 511, r = rem >> 4, c16 = rem & 15;
                const __nv_bfloat16* s = (arr ? Xl : Xh) + (k0 + r) * N + n0 + c16 * 8;
                cp_async16(base + BX_H + arr * (BX_L - BX_H) + r * 272 + c16 * 16, s);
            }
        }
        cp_commit();
    };

    chunk_copy(sbc, 0);

    float S[16][4];
#pragma unroll
    for (int j = 0; j < 16; j++)
#pragma unroll
        for (int c = 0; c < 4; c++) S[j][c] = 0.f;

    for (int c0 = 0; c0 < 8; c0++) {
        cp_wait_all();
        __syncthreads();
        if (c0 < 7) chunk_copy(sbc + ((c0 + 1) & 1) * BUFB, (c0 + 1) * 32);
        const unsigned bbuf = sbc + (c0 & 1) * BUFB;

        unsigned wa_[2][2][4];
#pragma unroll
        for (int sp = 0; sp < 2; sp++)
#pragma unroll
            for (int s = 0; s < 2; s++) {
                unsigned drow = s * 16 + ((lane >> 4) & 1) * 8 + (lane & 7);
                unsigned col  = (unsigned)w * 32 + ((lane >> 3) & 1) * 16;
                ldsm_x4t(wa_[sp][s][0], wa_[sp][s][1], wa_[sp][s][2], wa_[sp][s][3],
                         bbuf + sp * BW_L + drow * 144 + col);
            }
#pragma unroll
        for (int j = 0; j < 16; j++) {
            unsigned xh0, xh1, xh2, xh3, xl0, xl1, xl2, xl3;
            ldsm_x4t(xh0, xh1, xh2, xh3, bbuf + BX_H + lane * 272 + j * 16);
            ldsm_x4t(xl0, xl1, xl2, xl3, bbuf + BX_L + lane * 272 + j * 16);
            mma16816(S[j][0], S[j][1], S[j][2], S[j][3],
                     wa_[0][0][0], wa_[0][0][1], wa_[0][0][2], wa_[0][0][3], xh0, xh1);
            mma16816(S[j][0], S[j][1], S[j][2], S[j][3],
                     wa_[0][1][0], wa_[0][1][1], wa_[0][1][2], wa_[0][1][3], xh2, xh3);
            mma16816(S[j][0], S[j][1], S[j][2], S[j][3],
                     wa_[0][0][0], wa_[0][0][1], wa_[0][0][2], wa_[0][0][3], xl0, xl1);
            mma16816(S[j][0], S[j][1], S[j][2], S[j][3],
                     wa_[0][1][0], wa_[0][1][1], wa_[0][1][2], wa_[0][1][3], xl2, xl3);
            mma16816(S[j][0], S[j][1], S[j][2], S[j][3],
                     wa_[1][0][0], wa_[1][0][1], wa_[1][0][2], wa_[1][0][3], xh0, xh1);
            mma16816(S[j][0], S[j][1], S[j][2], S[j][3],
                     wa_[1][1][0], wa_[1][1][1], wa_[1][1][2], wa_[1][1][3], xh2, xh3);
        }
    }

    const int r0 = m0 + w * 16 + (lane >> 2);
    const int r1 = r0 + 8;
    float s0 = gg[r0] * rsqrtf(vv[r0] + BN_EPS);
    float bi0 = bb[r0] - mm[r0] * s0;
    float s1 = gg[r1] * rsqrtf(vv[r1] + BN_EPS);
    float bi1 = bb[r1] - mm[r1] * s1;
    if (out_mode == 0 && r0 < 256) { bi0 *= SC; }
    if (out_mode == 0 && r1 < 256) { bi1 *= SC; }

#pragma unroll
    for (int j = 0; j < 16; j++) {
        int n = n0 + j * 8 + (lane & 3) * 2;
        float o0 = S[j][0] * s0 + bi0, o1 = S[j][1] * s0 + bi0;
        float o2 = S[j][2] * s1 + bi1, o3 = S[j][3] * s1 + bi1;
        long i0 = (long)b * M * 4096 + (long)r0 * 4096 + n;
        long i1 = (long)b * M * 4096 + (long)r1 * 4096 + n;
        if (out_mode == 2) {
            *reinterpret_cast<float2*>(&dout[i0]) = make_float2(o0, o1);
            *reinterpret_cast<float2*>(&dout[i1]) = make_float2(o2, o3);
        } else {
            if (out_mode == 1) {
                *reinterpret_cast<float2*>(&g_yv[i0]) = make_float2(o0, o1);
                *reinterpret_cast<float2*>(&g_yv[i1]) = make_float2(o2, o3);
            }
            __nv_bfloat16* H = (out_mode == 0 ? g_qk_hi : g_v_hi);
            __nv_bfloat16* L = (out_mode == 0 ? g_qk_lo : g_v_lo);
            unsigned short h0 = bf_hi(o0), h1 = bf_hi(o1);
            unsigned short h2 = bf_hi(o2), h3 = bf_hi(o3);
            *reinterpret_cast<unsigned*>(&H[i0]) = pk(h0, h1);
            *reinterpret_cast<unsigned*>(&H[i1]) = pk(h2, h3);
            *reinterpret_cast<unsigned*>(&L[i0]) = pk(bf_lo(o0, h0), bf_lo(o1, h1));
            *reinterpret_cast<unsigned*>(&L[i1]) = pk(bf_lo(o2, h2), bf_lo(o3, h3));
        }
    }
}

// fused qk + v conv: blockIdx.y in [0,8) -> qk rows, [8,12) -> v rows
__global__ __launch_bounds__(128) void conv_qkv()
{
    extern __shared__ char csm[];
    const int b = blockIdx.z, n0 = blockIdx.x * 128;
    const __nv_bfloat16* Xh = g_xh + b * 256 * 4096;
    const __nv_bfloat16* Xl = g_xl + b * 256 * 4096;
    if (blockIdx.y < 8)
        conv_core(csm, g_wqkt_h, g_wqkt_l, Xh, Xl, nullptr,
                  nullptr, nullptr, nullptr, nullptr, 512, 0, b, blockIdx.y * 64, n0);
    else
        conv_core(csm, g_wvt_h, g_wvt_l, Xh, Xl, nullptr,
                  nullptr, nullptr, nullptr, nullptr, 256, 1, b, (blockIdx.y - 8) * 64, n0);
}
// BN params must come from kernel args (can't read host ptrs in conv_qkv) -> keep
// a param-carrying variant for all jobs:
__global__ __launch_bounds__(128) void conv_qkv_p(
    const float* __restrict__ qk_g, const float* __restrict__ qk_b,
    const float* __restrict__ qk_m, const float* __restrict__ qk_v,
    const float* __restrict__ v_g, const float* __restrict__ v_b,
    const float* __restrict__ v_m, const float* __restrict__ v_v)
{
    extern __shared__ char csm[];
    const int b = blockIdx.z, n0 = blockIdx.x * 128;
    const __nv_bfloat16* Xh = g_xh + b * 256 * 4096;
    const __nv_bfloat16* Xl = g_xl + b * 256 * 4096;
    if (blockIdx.y < 8)
        conv_core(csm, g_wqkt_h, g_wqkt_l, Xh, Xl, nullptr,
                  qk_g, qk_b, qk_m, qk_v, 512, 0, b, blockIdx.y * 64, n0);
    else
        conv_core(csm, g_wvt_h, g_wvt_l, Xh, Xl, nullptr,
                  v_g, v_b, v_m, v_v, 256, 1, b, (blockIdx.y - 8) * 64, n0);
}

__global__ __launch_bounds__(128) void conv_proj(
    float* __restrict__ dout,
    const float* __restrict__ pr_g, const float* __restrict__ pr_b,
    const float* __restrict__ pr_m, const float* __restrict__ pr_v)
{
    extern __shared__ char csm[];
    const int b = blockIdx.z, n0 = blockIdx.x * 128;
    conv_core(csm, g_wprt_h, g_wprt_l,
              g_oph + b * 256 * 4096, g_opl + b * 256 * 4096, dout,
              pr_g, pr_b, pr_m, pr_v, 256, 2, b, blockIdx.y * 64, n0);
}

// ---------------- depthwise 5x5 (pad 2) + BN, vectorized (unchanged) ----------
__global__ __launch_bounds__(256) void dw5_bn(
    const float* __restrict__ w_pe,
    const float* __restrict__ gg, const float* __restrict__ bb,
    const float* __restrict__ mm, const float* __restrict__ vv)
{
    const int bc = blockIdx.x;
    const int c  = bc & 255;
    const float* src = g_yv + bc * 4096;
    float* dst = g_pp + bc * 4096;

    __shared__ float tile[68][68];
    __shared__ float wk[25];
    const int t = threadIdx.x;

    for (int i = t * 4; i < 68 * 68; i += 1024)
        *reinterpret_cast<float4*>(&((float*)tile)[i]) = make_float4(0.f, 0.f, 0.f, 0.f);
    if (t < 25) wk[t] = w_pe[c * 25 + t];
    __syncthreads();
    for (int i = t * 4; i < 4096; i += 1024) {
        float4 v = *reinterpret_cast<const float4*>(&src[i]);
        int y = (i >> 6) + 2, x = (i & 63) + 2;
        tile[y][x] = v.x; tile[y][x + 1] = v.y; tile[y][x + 2] = v.z; tile[y][x + 3] = v.w;
    }
    __syncthreads();

    float s  = gg[c] * rsqrtf(vv[c] + BN_EPS);
    float bi = bb[c] - mm[c] * s;

    for (int i = t * 4; i < 4096; i += 1024) {
        int y = i >> 6, x = i & 63;
        float a0 = 0.f, a1 = 0.f, a2 = 0.f, a3 = 0.f;
#pragma unroll
        for (int ky = 0; ky < 5; ky++)
#pragma unroll
            for (int kx = 0; kx < 5; kx++) {
                float wv = wk[ky * 5 + kx];
                a0 = fmaf(tile[y + ky][x + kx],     wv, a0);
                a1 = fmaf(tile[y + ky][x + kx + 1], wv, a1);
                a2 = fmaf(tile[y + ky][x + kx + 2], wv, a2);
                a3 = fmaf(tile[y + ky][x + kx + 3], wv, a3);
            }
        *reinterpret_cast<float4*>(&dst[i]) =
            make_float4(a0 * s + bi, a1 * s + bi, a2 * s + bi, a3 * s + bi);
    }
}

// ================= flash attention (unchanged from R14 WIN) ===================
#define TS 272
#define BUFSZ  34816
#define FM_SMEM (2 * BUFSZ)

__device__ __forceinline__ void kv_copy(unsigned base, int t,
    const __nv_bfloat16* Kh, const __nv_bfloat16* Kl,
    const __nv_bfloat16* Vh, const __nv_bfloat16* Vl, int m0)
{
#pragma unroll
    for (int c = t; c < 2048; c += 128) {
        int arr = c >> 9, d = (c >> 4) & 31, mb = c & 15;
        const __nv_bfloat16* s =
            (arr == 0 ? Kh : (arr == 1 ? Kl : (arr == 2 ? Vh : Vl))) + d * 4096 + m0 + mb * 8;
        cp_async16(base + arr * 8704 + d * TS + mb * 16, s);
    }
    cp_commit();
}

__global__ __launch_bounds__(128, 3) void flash_mma()
{
    extern __shared__ char smbuf[];
    const unsigned sb = smem_u32(smbuf);
    const int t = threadIdx.x, lane = t & 31, w = t >> 5;

    const int bh = blockIdx.y;
    const int b = bh >> 5, area = (bh >> 3) & 3, h = bh & 7;
    const int q0 = blockIdx.x * 64;

    const int qch = (b * 512 + h * 32) * 4096 + area * 1024;
    const int kch = (b * 512 + 256 + h * 32) * 4096 + area * 1024;
    const int vch = (b * 256 + h * 32) * 4096 + area * 1024;
    const __nv_bfloat16* Qh = g_qk_hi + qch + q0;
    const __nv_bfloat16* Ql = g_qk_lo + qch + q0;
    const __nv_bfloat16* Kh = g_qk_hi + kch;
    const __nv_bfloat16* Kl = g_qk_lo + kch;
    const __nv_bfloat16* Vh = g_v_hi + vch;
    const __nv_bfloat16* Vl = g_v_lo + vch;

#pragma unroll
    for (int c = t; c < 512; c += 128) {
        int arr = c >> 8, d = (c >> 3) & 31, qb = c & 7;
        const __nv_bfloat16* s = (arr ? Ql : Qh) + d * 4096 + qb * 8;
        *reinterpret_cast<uint4*>(smbuf + arr * 8704 + d * TS + qb * 16) =
            *reinterpret_cast<const uint4*>(s);
    }
    __syncthreads();

    unsigned qa[2][2][4];
#pragma unroll
    for (int sp = 0; sp < 2; sp++)
#pragma unroll
        for (int s = 0; s < 2; s++) {
            unsigned drow = s * 16 + ((lane >> 4) & 1) * 8 + (lane & 7);
            unsigned col  = (unsigned)w * 32 + ((lane >> 3) & 1) * 16;
            ldsm_x4t(qa[sp][s][0], qa[sp][s][1], qa[sp][s][2], qa[sp][s][3],
                     sb + sp * 8704 + drow * TS + col);
        }
    __syncthreads();

    kv_copy(sb, t, Kh, Kl, Vh, Vl, 0);

    float Oacc[4][4];
#pragma unroll
    for (int dn = 0; dn < 4; dn++)
#pragma unroll
        for (int c = 0; c < 4; c++) Oacc[dn][c] = 0.f;
    float mr0 = -1e30f, mr1 = -1e30f, lr0 = 0.f, lr1 = 0.f;

    for (int kt = 0; kt < 8; kt++) {
        cp_wait_all();
        __syncthreads();
        if (kt < 7)
            kv_copy(sb + ((kt + 1) & 1) * BUFSZ, t, Kh, Kl, Vh, Vl, (kt + 1) * 128);
        const unsigned kb = sb + (kt & 1) * BUFSZ;

        float S[16][4];
#pragma unroll
        for (int j = 0; j < 16; j++) {
            unsigned kh0, kh1, kh2, kh3, kl0, kl1, kl2, kl3;
            ldsm_x4t(kh0, kh1, kh2, kh3, kb + lane * TS + j * 16);
            ldsm_x4t(kl0, kl1, kl2, kl3, kb + 8704 + lane * TS + j * 16);
            float a0 = 0.f, a1 = 0.f, a2 = 0.f, a3 = 0.f;
            float b0 = 0.f, b1 = 0.f, b2 = 0.f, b3 = 0.f;
            mma16816(a0, a1, a2, a3, qa[0][0][0], qa[0][0][1], qa[0][0][2], qa[0][0][3], kh0, kh1);
            mma16816(a0, a1, a2, a3, qa[0][1][0], qa[0][1][1], qa[0][1][2], qa[0][1][3], kh2, kh3);
            mma16816(b0, b1, b2, b3, qa[0][0][0], qa[0][0][1], qa[0][0][2], qa[0][0][3], kl0, kl1);
            mma16816(b0, b1, b2, b3, qa[0][1][0], qa[0][1][1], qa[0][1][2], qa[0][1][3], kl2, kl3);
            mma16816(b0, b1, b2, b3, qa[1][0][0], qa[1][0][1], qa[1][0][2], qa[1][0][3], kh0, kh1);
            mma16816(b0, b1, b2, b3, qa[1][1][0], qa[1][1][1], qa[1][1][2], qa[1][1][3], kh2, kh3);
            S[j][0] = a0 + b0; S[j][1] = a1 + b1; S[j][2] = a2 + b2; S[j][3] = a3 + b3;
        }

        float mx0 = -1e30f, mx1 = -1e30f;
#pragma unroll
        for (int j = 0; j < 16; j++) {
            mx0 = fmaxf(mx0, fmaxf(S[j][0], S[j][1]));
            mx1 = fmaxf(mx1, fmaxf(S[j][2], S[j][3]));
        }
        mx0 = fmaxf(mx0, __shfl_xor_sync(0xFFFFFFFFu, mx0, 1));
        mx0 = fmaxf(mx0, __shfl_xor_sync(0xFFFFFFFFu, mx0, 2));
        mx1 = fmaxf(mx1, __shfl_xor_sync(0xFFFFFFFFu, mx1, 1));
        mx1 = fmaxf(mx1, __shfl_xor_sync(0xFFFFFFFFu, mx1, 2));
        float nm0 = fmaxf(mr0, mx0), nm1 = fmaxf(mr1, mx1);
        float be0 = __expf(mr0 - nm0), be1 = __expf(mr1 - nm1);
        float lt0 = 0.f, lt1 = 0.f;
#pragma unroll
        for (int j = 0; j < 16; j++) {
            S[j][0] = __expf(S[j][0] - nm0); lt0 += S[j][0];
            S[j][1] = __expf(S[j][1] - nm0); lt0 += S[j][1];
            S[j][2] = __expf(S[j][2] - nm1); lt1 += S[j][2];
            S[j][3] = __expf(S[j][3] - nm1); lt1 += S[j][3];
        }
        lt0 += __shfl_xor_sync(0xFFFFFFFFu, lt0, 1);
        lt0 += __shfl_xor_sync(0xFFFFFFFFu, lt0, 2);
        lt1 += __shfl_xor_sync(0xFFFFFFFFu, lt1, 1);
        lt1 += __shfl_xor_sync(0xFFFFFFFFu, lt1, 2);
        lr0 = lr0 * be0 + lt0; lr1 = lr1 * be1 + lt1;
        mr0 = nm0; mr1 = nm1;
#pragma unroll
        for (int dn = 0; dn < 4; dn++) {
            Oacc[dn][0] *= be0; Oacc[dn][1] *= be0;
            Oacc[dn][2] *= be1; Oacc[dn][3] *= be1;
        }

#pragma unroll
        for (int tt = 0; tt < 8; tt++) {
            unsigned ah[4], al[4];
            {
                unsigned short h0 = bf_hi(S[2*tt][0]),   h1 = bf_hi(S[2*tt][1]);
                unsigned short h2 = bf_hi(S[2*tt][2]),   h3 = bf_hi(S[2*tt][3]);
                unsigned short h4 = bf_hi(S[2*tt+1][0]), h5 = bf_hi(S[2*tt+1][1]);
                unsigned short h6 = bf_hi(S[2*tt+1][2]), h7 = bf_hi(S[2*tt+1][3]);
                ah[0] = pk(h0, h1); ah[1] = pk(h2, h3);
                ah[2] = pk(h4, h5); ah[3] = pk(h6, h7);
                al[0] = pk(bf_lo(S[2*tt][0], h0),   bf_lo(S[2*tt][1], h1));
                al[1] = pk(bf_lo(S[2*tt][2], h2),   bf_lo(S[2*tt][3], h3));
                al[2] = pk(bf_lo(S[2*tt+1][0], h4), bf_lo(S[2*tt+1][1], h5));
                al[3] = pk(bf_lo(S[2*tt+1][2], h6), bf_lo(S[2*tt+1][3], h7));
            }
#pragma unroll
            for (int p = 0; p < 2; p++) {
                unsigned drow = (unsigned)p * 16 + ((lane >> 4) & 1) * 8 + (lane & 7);
                unsigned colb = (unsigned)tt * 32 + ((lane >> 3) & 1) * 16;
                unsigned vh0, vh1, vh2, vh3, vl0, vl1, vl2, vl3;
                ldsm_x4(vh0, vh1, vh2, vh3, kb + 17408 + drow * TS + colb);
                ldsm_x4(vl0, vl1, vl2, vl3, kb + 26112 + drow * TS + colb);
                int d0 = p * 2, d1 = p * 2 + 1;
                mma16816(Oacc[d0][0], Oacc[d0][1], Oacc[d0][2], Oacc[d0][3],
                         ah[0], ah[1], ah[2], ah[3], vh0, vh1);
                mma16816(Oacc[d0][0], Oacc[d0][1], Oacc[d0][2], Oacc[d0][3],
                         ah[0], ah[1], ah[2], ah[3], vl0, vl1);
                mma16816(Oacc[d0][0], Oacc[d0][1], Oacc[d0][2], Oacc[d0][3],
                         al[0], al[1], al[2], al[3], vh0, vh1);
                mma16816(Oacc[d1][0], Oacc[d1][1], Oacc[d1][2], Oacc[d1][3],
                         ah[0], ah[1], ah[2], ah[3], vh2, vh3);
                mma16816(Oacc[d1][0], Oacc[d1][1], Oacc[d1][2], Oacc[d1][3],
                         ah[0], ah[1], ah[2], ah[3], vl2, vl3);
                mma16816(Oacc[d1][0], Oacc[d1][1], Oacc[d1][2], Oacc[d1][3],
                         al[0], al[1], al[2], al[3], vh2, vh3);
            }
        }
    }

    __syncthreads();
    {
        float inv0 = 1.f / lr0, inv1 = 1.f / lr1;
        int r = w * 16 + (lane >> 2);
        int dc = (lane & 3) * 2;
        float* Os = (float*)(smbuf);
#pragma unroll
        for (int dn = 0; dn < 4; dn++) {
            int d = dn * 8 + dc;
            Os[r * 33 + d]           = Oacc[dn][0] * inv0;
            Os[r * 33 + d + 1]       = Oacc[dn][1] * inv0;
            Os[(r + 8) * 33 + d]     = Oacc[dn][2] * inv1;
            Os[(r + 8) * 33 + d + 1] = Oacc[dn][3] * inv1;
        }
    }
    __syncthreads();

    const long ob = (long)(b * 256 + h * 32) * 4096 + area * 1024 + q0;
    const float* Pp = g_pp + ob;
    __nv_bfloat16* OH = g_oph + ob;
    __nv_bfloat16* OL = g_opl + ob;
    const float* Os = (const float*)(smbuf);
    for (int i = t * 4; i < 2048; i += 512) {
        int d = i >> 6, q = i & 63;
        float o[4];
        o[0] = Os[(q + 0) * 33 + d];
        o[1] = Os[(q + 1) * 33 + d];
        o[2] = Os[(q + 2) * 33 + d];
        o[3] = Os[(q + 3) * 33 + d];
        float4 p = *reinterpret_cast<const float4*>(&Pp[d * 4096 + q]);
        o[0] += p.x; o[1] += p.y; o[2] += p.z; o[3] += p.w;
        unsigned short hh[4], ll[4];
#pragma unroll
        for (int j = 0; j < 4; j++) { hh[j] = bf_hi(o[j]); ll[j] = bf_lo(o[j], hh[j]); }
        *reinterpret_cast<uint2*>(&OH[d * 4096 + q]) =
            make_uint2(pk(hh[0], hh[1]), pk(hh[2], hh[3]));
        *reinterpret_cast<uint2*>(&OL[d * 4096 + q]) =
            make_uint2(pk(ll[0], ll[1]), pk(ll[2], ll[3]));
    }
}

// ---------------- launch ------------------------------------------------------
extern "C" void kernel_launch(void* const* d_in, const int* in_sizes, int n_in,
                              void* d_out, int out_size)
{
    const float *x, *w_qk, *w_v, *w_pe, *w_proj;
    const float *qk_g, *qk_b, *qk_m, *qk_v;
    const float *v_g, *v_b, *v_m, *v_v;
    const float *pe_g, *pe_b, *pe_m, *pe_v;
    const float *pr_g, *pr_b, *pr_m, *pr_v;

    x = (const float*)d_in[0];
    w_qk = (const float*)d_in[1];
    if (in_sizes[2] == 512) {
        qk_g = (const float*)d_in[2];  qk_b = (const float*)d_in[3];
        qk_m = (const float*)d_in[4];  qk_v = (const float*)d_in[5];
        w_v  = (const float*)d_in[6];
        v_g  = (const float*)d_in[7];  v_b  = (const float*)d_in[8];
        v_m  = (const float*)d_in[9];  v_v  = (const float*)d_in[10];
        w_pe = (const float*)d_in[11];
        pe_g = (const float*)d_in[12]; pe_b = (const float*)d_in[13];
        pe_m = (const float*)d_in[14]; pe_v = (const float*)d_in[15];
        w_proj = (const float*)d_in[16];
        pr_g = (const float*)d_in[17]; pr_b = (const float*)d_in[18];
        pr_m = (const float*)d_in[19]; pr_v = (const float*)d_in[20];
    } else {
        w_v    = (const float*)d_in[2];
        w_pe   = (const float*)d_in[3];
        w_proj = (const float*)d_in[4];
        qk_g = (const float*)d_in[5];  qk_b = (const float*)d_in[6];
        qk_m = (const float*)d_in[7];  qk_v = (const float*)d_in[8];
        v_g  = (const float*)d_in[9];  v_b  = (const float*)d_in[10];
        v_m  = (const float*)d_in[11]; v_v  = (const float*)d_in[12];
        pe_g = (const float*)d_in[13]; pe_b = (const float*)d_in[14];
        pe_m = (const float*)d_in[15]; pe_v = (const float*)d_in[16];
        pr_g = (const float*)d_in[17]; pr_b = (const float*)d_in[18];
        pr_m = (const float*)d_in[19]; pr_v = (const float*)d_in[20];
    }
    float* out = (float*)d_out;

    static __nv_bfloat16* p_xh = nullptr;
    static __nv_bfloat16* p_xl = nullptr;
    if (!p_xh) {
        void* p;
        cudaGetSymbolAddress(&p, g_xh); p_xh = (__nv_bfloat16*)p;
        cudaGetSymbolAddress(&p, g_xl); p_xl = (__nv_bfloat16*)p;
    }

    cudaFuncSetAttribute(flash_mma, cudaFuncAttributeMaxDynamicSharedMemorySize, FM_SMEM);
    cudaFuncSetAttribute(conv_qkv_p, cudaFuncAttributeMaxDynamicSharedMemorySize, CB_SMEM);
    cudaFuncSetAttribute(conv_proj, cudaFuncAttributeMaxDynamicSharedMemorySize, CB_SMEM);

    const int NX = 2 * 256 * 4096;
    prep_wt_all<<<1024, 256>>>(w_qk, w_v, w_proj);
    prep_split<<<NX / 2048, 256>>>(x, nullptr, p_xh, p_xl, NX);

    // fused qk + v conv (12 m-jobs)
    conv_qkv_p<<<dim3(32, 12, 2), 128, CB_SMEM>>>(qk_g, qk_b, qk_m, qk_v,
                                                  v_g, v_b, v_m, v_v);
    dw5_bn<<<512, 256>>>(w_pe, pe_g, pe_b, pe_m, pe_v);
    flash_mma<<<dim3(16, 64), 128, FM_SMEM>>>();
    conv_proj<<<dim3(32, 4, 2), 128, CB_SMEM>>>(out, pr_g, pr_b, pr_m, pr_v);
}